// round 6
// baseline (speedup 1.0000x reference)
#include <cuda_runtime.h>
#include <math.h>

#define B_      2
#define S_      2048
#define HID_    2048
#define H_      16
#define DQ_     192
#define DNOPE_  128
#define DROPE_  64
#define DV_     128
#define RANK_   512
#define INTER_  10944
#define TOK_    (B_*S_)
#define NEG_INF (-3.4028235e38f)

__device__ __forceinline__ float tf32r(float x) {
    float r;
    asm("cvt.rna.tf32.f32 %0, %1;" : "=f"(r) : "f"(x));
    return r;
}

__device__ float g_invfreq[32];
__device__ float g_xln    [TOK_*HID_];
__device__ float g_q      [TOK_*H_*DQ_];
__device__ float g_ckv    [TOK_*(RANK_+DROPE_)];
__device__ float g_cln    [TOK_*RANK_];
__device__ float g_kv     [TOK_*H_*(DNOPE_+DV_)];
__device__ float g_qrope  [TOK_*H_*DROPE_];
__device__ float g_krope  [TOK_*DROPE_];
__device__ float g_attnfl [TOK_*H_*DV_];
__device__ float g_x2     [TOK_*HID_];
__device__ float g_y      [TOK_*HID_];
__device__ float g_gate   [TOK_*INTER_];
__device__ float g_up     [TOK_*INTER_];

// ---- yarn inv_freq computed on device from the reference formulas ----
__global__ void init_invfreq2_kernel() {
    int j = threadIdx.x;
    if (j >= 32) return;
    const double dim = 64.0, base = 10000.0, orig_max = 4096.0;
    const double two_pi = 6.283185307179586476925286766559;
    double cd_fast = dim * log(orig_max / (32.0 * two_pi)) / (2.0 * log(base));
    double cd_slow = dim * log(orig_max / ( 1.0 * two_pi)) / (2.0 * log(base));
    double lowd  = floor(cd_fast); if (lowd < 0.0) lowd = 0.0;
    double highd = ceil(cd_slow);  if (highd > dim - 1.0) highd = dim - 1.0;
    double hid = (lowd == highd) ? highd + 0.001 : highd;
    double ar = (2.0 * (double)j) / dim;
    double freq_extra = 1.0 / pow(base, ar);
    double freq_inter = 1.0 / (40.0 * pow(base, ar));
    double ramp = ((double)j - lowd) / (hid - lowd);
    if (ramp < 0.0) ramp = 0.0;
    if (ramp > 1.0) ramp = 1.0;
    double mask = 1.0 - ramp;
    g_invfreq[j] = (float)(freq_inter * (1.0 - mask) + freq_extra * mask);
}

// ---- RMSNorm (exact fp32, elementwise path is exact in the reference too) ----
__global__ void rmsnorm2_kernel(const float* __restrict__ x, const float* __restrict__ w,
                                float* __restrict__ out, int dim, int in_stride)
{
    const long long row = blockIdx.x;
    const float* xr = x + row * (long long)in_stride;
    __shared__ float buf[256];
    float partial = 0.f;
    for (int i = threadIdx.x; i < dim; i += 256) { float v = xr[i]; partial += v * v; }
    buf[threadIdx.x] = partial;
    __syncthreads();
    for (int stride = 128; stride > 0; stride >>= 1) {
        if (threadIdx.x < stride) buf[threadIdx.x] += buf[threadIdx.x + stride];
        __syncthreads();
    }
    float scale = rsqrtf(buf[0] / (float)dim + 1e-6f);
    for (int i = threadIdx.x; i < dim; i += 256)
        out[row * (long long)dim + i] = xr[i] * scale * w[i];
}

// ---- GEMM with TF32-truncated operands, fp32 accumulate (emulates JAX GPU default) ----
template<int MODE>
__global__ void __launch_bounds__(256) gemm2_kernel(
    const float* __restrict__ A, const float* __restrict__ Bw,
    float* __restrict__ C, const float* __restrict__ R,
    int M, int N, int K)
{
    __shared__ float As[32][65];
    __shared__ float Bs[32][65];
    const int m0 = blockIdx.y * 64;
    const int n0 = blockIdx.x * 64;
    const int tid = threadIdx.x;
    const int tm = (tid >> 4) * 4;
    const int tn = (tid & 15) * 4;
    float acc[4][4];
    #pragma unroll
    for (int i = 0; i < 4; i++)
        #pragma unroll
        for (int j = 0; j < 4; j++) acc[i][j] = 0.f;

    for (int k0 = 0; k0 < K; k0 += 32) {
        #pragma unroll
        for (int u = 0; u < 8; u++) {
            int idx = tid * 8 + u;
            int r  = idx >> 5;
            int kk = idx & 31;
            int gm = m0 + r;
            int gn = n0 + r;
            As[kk][r] = (gm < M) ? tf32r(A [(long long)gm * K + k0 + kk]) : 0.f;
            Bs[kk][r] = (gn < N) ? tf32r(Bw[(long long)gn * K + k0 + kk]) : 0.f;
        }
        __syncthreads();
        #pragma unroll 8
        for (int kk = 0; kk < 32; kk++) {
            float a[4], b[4];
            #pragma unroll
            for (int i = 0; i < 4; i++) a[i] = As[kk][tm + i];
            #pragma unroll
            for (int j = 0; j < 4; j++) b[j] = Bs[kk][tn + j];
            #pragma unroll
            for (int i = 0; i < 4; i++)
                #pragma unroll
                for (int j = 0; j < 4; j++)
                    acc[i][j] = fmaf(a[i], b[j], acc[i][j]);
        }
        __syncthreads();
    }

    #pragma unroll
    for (int i = 0; i < 4; i++) {
        int mm = m0 + tm + i;
        if (mm >= M) continue;
        #pragma unroll
        for (int j = 0; j < 4; j++) {
            int nn = n0 + tn + j;
            if (nn >= N) continue;
            float v = acc[i][j];
            if (MODE == 1) v += R[(long long)mm * N + nn];
            C[(long long)mm * N + nn] = v;
        }
    }
}

// ---- RoPE (exact fp32 elementwise, mirrors reference) ----
__global__ void rope_q_kernel(const int* __restrict__ pos_ids) {
    int idx = blockIdx.x * 256 + threadIdx.x;
    if (idx >= TOK_ * H_) return;
    int tok = idx / H_;
    const float* x = g_q + (long long)idx * DQ_ + DNOPE_;
    float* o = g_qrope + (long long)idx * DROPE_;
    float pos = (float)pos_ids[tok];
    for (int j = 0; j < 32; j++) {
        float th = pos * g_invfreq[j];
        float c = cosf(th), sn = sinf(th);
        float x1 = x[2*j], x2 = x[2*j+1];
        o[j]      = x1 * c - x2 * sn;
        o[j + 32] = x2 * c + x1 * sn;
    }
}

__global__ void rope_k_kernel(const int* __restrict__ pos_ids) {
    int tok = blockIdx.x * 256 + threadIdx.x;
    if (tok >= TOK_) return;
    const float* x = g_ckv + (long long)tok * (RANK_ + DROPE_) + RANK_;
    float* o = g_krope + (long long)tok * DROPE_;
    float pos = (float)pos_ids[tok];
    for (int j = 0; j < 32; j++) {
        float th = pos * g_invfreq[j];
        float c = cosf(th), sn = sinf(th);
        float x1 = x[2*j], x2 = x[2*j+1];
        o[j]      = x1 * c - x2 * sn;
        o[j + 32] = x2 * c + x1 * sn;
    }
}

// ---- brute-force causal attention with TF32-truncated einsum operands ----
__global__ void __launch_bounds__(256) brute_attn_kernel(float* __restrict__ outfl) {
    const int q = blockIdx.x;
    const int z = blockIdx.y;
    const int b = z / H_, h = z % H_;
    const int tid = threadIdx.x;
    const long long tok_q = (long long)b * S_ + q;
    const int nk = q + 1;
    const float scale = 0.07216878364870323f;  // 192^-0.5

    __shared__ float qv[DQ_];
    __shared__ float p[S_];
    __shared__ float red[256];

    // q operand, TF32-truncated (reference: qf operand of TF32 einsum)
    if (tid < DNOPE_) qv[tid] = tf32r(g_q[(tok_q * H_ + h) * DQ_ + tid]);
    else if (tid < DQ_) qv[tid] = tf32r(g_qrope[(tok_q * H_ + h) * DROPE_ + (tid - DNOPE_)]);
    __syncthreads();

    // scores
    float lmax = NEG_INF;
    for (int k = tid; k < nk; k += 256) {
        long long tok_k = (long long)b * S_ + k;
        const float* kn = g_kv + (tok_k * H_ + h) * (DNOPE_ + DV_);
        const float* kr = g_krope + tok_k * DROPE_;
        float s = 0.f;
        #pragma unroll 16
        for (int d = 0; d < DNOPE_; d++)
            s = fmaf(qv[d], tf32r(kn[d]), s);
        #pragma unroll 16
        for (int j = 0; j < DROPE_; j++)
            s = fmaf(qv[DNOPE_ + j], tf32r(kr[j]), s);
        s *= scale;
        p[k] = s;
        lmax = fmaxf(lmax, s);
    }
    red[tid] = lmax; __syncthreads();
    for (int o = 128; o; o >>= 1) { if (tid < o) red[tid] = fmaxf(red[tid], red[tid+o]); __syncthreads(); }
    float m = red[0]; __syncthreads();
    float lsum = 0.f;
    for (int k = tid; k < nk; k += 256) { float e = expf(p[k] - m); p[k] = e; lsum += e; }
    red[tid] = lsum; __syncthreads();
    for (int o = 128; o; o >>= 1) { if (tid < o) red[tid] += red[tid+o]; __syncthreads(); }
    float inv_l = 1.f / red[0];
    __syncthreads();

    // normalize probs, THEN truncate (reference truncates the softmax output as einsum operand)
    for (int k = tid; k < nk; k += 256) p[k] = tf32r(p[k] * inv_l);
    __syncthreads();

    // O[d] = sum_k p[k] * v[k][d], v TF32-truncated
    const int d = tid & 127, half = tid >> 7;
    float acc = 0.f;
    for (int k = half; k < nk; k += 2)
        acc = fmaf(p[k], tf32r(g_kv[(((long long)b * S_ + k) * H_ + h) * (DNOPE_ + DV_) + DNOPE_ + d]), acc);
    red[tid] = acc; __syncthreads();
    if (tid < 128)
        outfl[tok_q * (H_*DV_) + h * DV_ + d] = red[tid] + red[tid + 128];
}

// ---- silu (exact fp32) ----
__global__ void silu_mul2_kernel() {
    long long idx = (long long)blockIdx.x * 256 + threadIdx.x;
    if (idx >= (long long)TOK_ * INTER_) return;
    float g = g_gate[idx];
    float sig = 1.f / (1.f + expf(-g));
    g_gate[idx] = g * sig * g_up[idx];
}

static inline dim3 g2(int M, int N) { return dim3((N + 63) / 64, (M + 63) / 64, 1); }

extern "C" void kernel_launch(void* const* d_in, const int* in_sizes, int n_in,
                              void* d_out, int out_size)
{
    const float* hidden = (const float*)d_in[0];
    const int*   pos    = (const int*)  d_in[1];
    const float* Wq     = (const float*)d_in[2];
    const float* Wkva   = (const float*)d_in[3];
    const float* w_kvln = (const float*)d_in[4];
    const float* Wkvb   = (const float*)d_in[5];
    const float* Wo     = (const float*)d_in[6];
    const float* Wg     = (const float*)d_in[7];
    const float* Wu     = (const float*)d_in[8];
    const float* Wd     = (const float*)d_in[9];
    const float* w_ln1  = (const float*)d_in[10];
    const float* w_ln2  = (const float*)d_in[11];
    float* out = (float*)d_out;

    float *p_xln, *p_q, *p_ckv, *p_cln, *p_kv, *p_afl, *p_x2, *p_y, *p_g, *p_u;
    cudaGetSymbolAddress((void**)&p_xln, g_xln);
    cudaGetSymbolAddress((void**)&p_q,   g_q);
    cudaGetSymbolAddress((void**)&p_ckv, g_ckv);
    cudaGetSymbolAddress((void**)&p_cln, g_cln);
    cudaGetSymbolAddress((void**)&p_kv,  g_kv);
    cudaGetSymbolAddress((void**)&p_afl, g_attnfl);
    cudaGetSymbolAddress((void**)&p_x2,  g_x2);
    cudaGetSymbolAddress((void**)&p_y,   g_y);
    cudaGetSymbolAddress((void**)&p_g,   g_gate);
    cudaGetSymbolAddress((void**)&p_u,   g_up);

    init_invfreq2_kernel<<<1, 32>>>();

    rmsnorm2_kernel<<<TOK_, 256>>>(hidden, w_ln1, p_xln, HID_, HID_);

    gemm2_kernel<0><<<g2(TOK_, H_*DQ_), 256>>>(p_xln, Wq, p_q, nullptr, TOK_, H_*DQ_, HID_);
    gemm2_kernel<0><<<g2(TOK_, RANK_+DROPE_), 256>>>(p_xln, Wkva, p_ckv, nullptr, TOK_, RANK_+DROPE_, HID_);

    rmsnorm2_kernel<<<TOK_, 256>>>(p_ckv, w_kvln, p_cln, RANK_, RANK_+DROPE_);

    gemm2_kernel<0><<<g2(TOK_, H_*(DNOPE_+DV_)), 256>>>(p_cln, Wkvb, p_kv, nullptr, TOK_, H_*(DNOPE_+DV_), RANK_);

    rope_q_kernel<<<(TOK_*H_ + 255)/256, 256>>>(pos);
    rope_k_kernel<<<(TOK_ + 255)/256, 256>>>(pos);

    brute_attn_kernel<<<dim3(S_, B_*H_), 256>>>(p_afl);

    gemm2_kernel<1><<<g2(TOK_, HID_), 256>>>(p_afl, Wo, p_x2, hidden, TOK_, HID_, H_*DV_);

    rmsnorm2_kernel<<<TOK_, 256>>>(p_x2, w_ln2, p_y, HID_, HID_);

    gemm2_kernel<0><<<g2(TOK_, INTER_), 256>>>(p_y, Wg, p_g, nullptr, TOK_, INTER_, HID_);
    gemm2_kernel<0><<<g2(TOK_, INTER_), 256>>>(p_y, Wu, p_u, nullptr, TOK_, INTER_, HID_);

    silu_mul2_kernel<<<(unsigned)(((long long)TOK_*INTER_ + 255) / 256), 256>>>();

    gemm2_kernel<1><<<g2(TOK_, HID_), 256>>>(p_g, Wd, out, p_x2, TOK_, HID_, INTER_);
}

// round 7
// speedup vs baseline: 3.5176x; 3.5176x over previous
#include <cuda_runtime.h>
#include <math.h>

#define B_      2
#define S_      2048
#define HID_    2048
#define H_      16
#define DQ_     192
#define DNOPE_  128
#define DROPE_  64
#define DV_     128
#define RANK_   512
#define INTER_  10944
#define TOK_    (B_*S_)
#define NEG_INF (-3.4028235e38f)

__device__ __forceinline__ float tf32r(float x) {
    float r;
    asm("cvt.rna.tf32.f32 %0, %1;" : "=f"(r) : "f"(x));
    return r;
}

__device__ float g_invfreq[32];
__device__ float g_xln    [TOK_*HID_];
__device__ float g_q      [TOK_*H_*DQ_];
__device__ float g_ckv    [TOK_*(RANK_+DROPE_)];
__device__ float g_cln    [TOK_*RANK_];
__device__ float g_kv     [TOK_*H_*(DNOPE_+DV_)];
__device__ float g_qrope  [TOK_*H_*DROPE_];
__device__ float g_krope  [TOK_*DROPE_];
__device__ float g_Qp     [(size_t)B_*H_*S_*DQ_];
__device__ float g_Kp     [(size_t)B_*H_*S_*DQ_];
__device__ float g_Vp     [(size_t)B_*H_*S_*DV_];
__device__ float g_attnfl [TOK_*H_*DV_];
__device__ float g_x2     [TOK_*HID_];
__device__ float g_y      [TOK_*HID_];
__device__ float g_gate   [TOK_*INTER_];
__device__ float g_up     [TOK_*INTER_];

// ---- yarn inv_freq computed on device from the reference formulas ----
__global__ void init_invfreq2_kernel() {
    int j = threadIdx.x;
    if (j >= 32) return;
    const double dim = 64.0, base = 10000.0, orig_max = 4096.0;
    const double two_pi = 6.283185307179586476925286766559;
    double cd_fast = dim * log(orig_max / (32.0 * two_pi)) / (2.0 * log(base));
    double cd_slow = dim * log(orig_max / ( 1.0 * two_pi)) / (2.0 * log(base));
    double lowd  = floor(cd_fast); if (lowd < 0.0) lowd = 0.0;
    double highd = ceil(cd_slow);  if (highd > dim - 1.0) highd = dim - 1.0;
    double hid = (lowd == highd) ? highd + 0.001 : highd;
    double ar = (2.0 * (double)j) / dim;
    double freq_extra = 1.0 / pow(base, ar);
    double freq_inter = 1.0 / (40.0 * pow(base, ar));
    double ramp = ((double)j - lowd) / (hid - lowd);
    if (ramp < 0.0) ramp = 0.0;
    if (ramp > 1.0) ramp = 1.0;
    double mask = 1.0 - ramp;
    g_invfreq[j] = (float)(freq_inter * (1.0 - mask) + freq_extra * mask);
}

// ---- RMSNorm ----
__global__ void rmsnorm2_kernel(const float* __restrict__ x, const float* __restrict__ w,
                                float* __restrict__ out, int dim, int in_stride)
{
    const long long row = blockIdx.x;
    const float* xr = x + row * (long long)in_stride;
    __shared__ float buf[256];
    float partial = 0.f;
    for (int i = threadIdx.x; i < dim; i += 256) { float v = xr[i]; partial += v * v; }
    buf[threadIdx.x] = partial;
    __syncthreads();
    for (int stride = 128; stride > 0; stride >>= 1) {
        if (threadIdx.x < stride) buf[threadIdx.x] += buf[threadIdx.x + stride];
        __syncthreads();
    }
    float scale = rsqrtf(buf[0] / (float)dim + 1e-6f);
    for (int i = threadIdx.x; i < dim; i += 256)
        out[row * (long long)dim + i] = xr[i] * scale * w[i];
}

// ---- GEMM v1 (128x128 tile, 8x8/thread) with TF32-truncated operands ----
// MODE 0: plain   MODE 1: += R
template<int MODE>
__global__ void __launch_bounds__(256) gemm_kernel(
    const float* __restrict__ A, const float* __restrict__ Bw,
    float* __restrict__ C, const float* __restrict__ R,
    int M, int N, int K)
{
    const int m0 = blockIdx.y * 128, n0 = blockIdx.x * 128;
    const int tid = threadIdx.x;

    __shared__ float As[16][129];
    __shared__ float Bs[16][129];
    float acc[8][8] = {};
    const int tx = tid & 15, ty = tid >> 4;

    for (int k0 = 0; k0 < K; k0 += 16) {
        #pragma unroll
        for (int i = 0; i < 2; i++) {
            int v = tid + i * 256;
            int row = v >> 2, kc = (v & 3) * 4;
            int gm = m0 + row;
            float4 val = make_float4(0.f, 0.f, 0.f, 0.f);
            if (gm < M) val = *(const float4*)(A + (long long)gm * K + k0 + kc);
            As[kc + 0][row] = tf32r(val.x); As[kc + 1][row] = tf32r(val.y);
            As[kc + 2][row] = tf32r(val.z); As[kc + 3][row] = tf32r(val.w);
        }
        #pragma unroll
        for (int i = 0; i < 2; i++) {
            int v = tid + i * 256;
            int row = v >> 2, kc = (v & 3) * 4;
            int gn = n0 + row;
            float4 val = make_float4(0.f, 0.f, 0.f, 0.f);
            if (gn < N) val = *(const float4*)(Bw + (long long)gn * K + k0 + kc);
            Bs[kc + 0][row] = tf32r(val.x); Bs[kc + 1][row] = tf32r(val.y);
            Bs[kc + 2][row] = tf32r(val.z); Bs[kc + 3][row] = tf32r(val.w);
        }
        __syncthreads();
        #pragma unroll
        for (int kk = 0; kk < 16; kk++) {
            float a[8], b[8];
            #pragma unroll
            for (int i = 0; i < 8; i++) a[i] = As[kk][ty * 8 + i];
            #pragma unroll
            for (int j = 0; j < 8; j++) b[j] = Bs[kk][tx * 8 + j];
            #pragma unroll
            for (int i = 0; i < 8; i++)
                #pragma unroll
                for (int j = 0; j < 8; j++)
                    acc[i][j] = fmaf(a[i], b[j], acc[i][j]);
        }
        __syncthreads();
    }

    #pragma unroll
    for (int i = 0; i < 8; i++) {
        int mm = m0 + ty * 8 + i;
        if (mm >= M) continue;
        #pragma unroll
        for (int j = 0; j < 8; j++) {
            int nn = n0 + tx * 8 + j;
            if (nn >= N) continue;
            float v = acc[i][j];
            if (MODE == 1) v += R[(long long)mm * N + nn];
            C[(long long)mm * N + nn] = v;
        }
    }
}

// ---- RoPE ----
__global__ void rope_q_kernel(const int* __restrict__ pos_ids) {
    int idx = blockIdx.x * 256 + threadIdx.x;
    if (idx >= TOK_ * H_) return;
    int tok = idx / H_;
    const float* x = g_q + (long long)idx * DQ_ + DNOPE_;
    float* o = g_qrope + (long long)idx * DROPE_;
    float pos = (float)pos_ids[tok];
    for (int j = 0; j < 32; j++) {
        float th = pos * g_invfreq[j];
        float c = cosf(th), sn = sinf(th);
        float x1 = x[2*j], x2 = x[2*j+1];
        o[j]      = x1 * c - x2 * sn;
        o[j + 32] = x2 * c + x1 * sn;
    }
}

__global__ void rope_k_kernel(const int* __restrict__ pos_ids) {
    int tok = blockIdx.x * 256 + threadIdx.x;
    if (tok >= TOK_) return;
    const float* x = g_ckv + (long long)tok * (RANK_ + DROPE_) + RANK_;
    float* o = g_krope + (long long)tok * DROPE_;
    float pos = (float)pos_ids[tok];
    for (int j = 0; j < 32; j++) {
        float th = pos * g_invfreq[j];
        float c = cosf(th), sn = sinf(th);
        float x1 = x[2*j], x2 = x[2*j+1];
        o[j]      = x1 * c - x2 * sn;
        o[j + 32] = x2 * c + x1 * sn;
    }
}

// ---- pack kernels (pure layout transforms + TF32 truncation at source) ----
__global__ void pack_q_kernel() {
    long long idx = (long long)blockIdx.x * 256 + threadIdx.x;
    const long long total = (long long)TOK_ * H_ * DQ_;
    if (idx >= total) return;
    int d = (int)(idx % DQ_);
    int h = (int)((idx / DQ_) % H_);
    long long tok = idx / ((long long)DQ_ * H_);
    int b = (int)(tok / S_), s = (int)(tok % S_);
    float val = (d < DNOPE_)
        ? g_q[(tok * H_ + h) * DQ_ + d]
        : g_qrope[(tok * H_ + h) * DROPE_ + (d - DNOPE_)];
    g_Qp[(((long long)(b * H_ + h)) * S_ + s) * DQ_ + d] = tf32r(val);
}

__global__ void pack_k_kernel() {
    long long idx = (long long)blockIdx.x * 256 + threadIdx.x;
    const long long total = (long long)TOK_ * H_ * DQ_;
    if (idx >= total) return;
    int d = (int)(idx % DQ_);
    int h = (int)((idx / DQ_) % H_);
    long long tok = idx / ((long long)DQ_ * H_);
    int b = (int)(tok / S_), s = (int)(tok % S_);
    float val = (d < DNOPE_)
        ? g_kv[(tok * H_ + h) * (DNOPE_ + DV_) + d]
        : g_krope[tok * DROPE_ + (d - DNOPE_)];
    g_Kp[(((long long)(b * H_ + h)) * S_ + s) * DQ_ + d] = tf32r(val);
}

__global__ void pack_v_kernel() {
    long long idx = (long long)blockIdx.x * 256 + threadIdx.x;
    const long long total = (long long)TOK_ * H_ * DV_;
    if (idx >= total) return;
    int d = (int)(idx % DV_);
    int h = (int)((idx / DV_) % H_);
    long long tok = idx / ((long long)DV_ * H_);
    int b = (int)(tok / S_), s = (int)(tok % S_);
    g_Vp[(((long long)(b * H_ + h)) * S_ + s) * DV_ + d] =
        tf32r(g_kv[(tok * H_ + h) * (DNOPE_ + DV_) + DNOPE_ + d]);
}

// ---- fused flash attention (fp32 math, TF32-truncated operands, causal) ----
#define FBR 64
#define FBC 64
#define QK_STR 193
#define V_STR  132
#define P_STR  68

__global__ void __launch_bounds__(256) flash_kernel(
    const float* __restrict__ Qp, const float* __restrict__ Kp,
    const float* __restrict__ Vp, float* __restrict__ outfl)
{
    extern __shared__ float sm[];
    float* Qs = sm;
    float* Ks = sm + FBR * QK_STR;
    float* Vs = Ks + FBC * QK_STR;
    float* Ps = Vs + FBC * V_STR;

    const int z  = blockIdx.y;
    const int q0 = blockIdx.x * FBR;
    const int tid = threadIdx.x;
    const int tx = tid & 15, ty = tid >> 4;

    const float scale = 0.07216878364870323f; // 192^-0.5
    const float* Qg = Qp + ((long long)z * S_ + q0) * DQ_;
    const float* Kg = Kp + (long long)z * S_ * DQ_;
    const float* Vg = Vp + (long long)z * S_ * DV_;

    for (int i = tid; i < FBR * 48; i += 256) {
        int r = i / 48, c4 = (i % 48) * 4;
        float4 v = *(const float4*)(Qg + (long long)r * DQ_ + c4);
        Qs[r*QK_STR + c4 + 0] = v.x; Qs[r*QK_STR + c4 + 1] = v.y;
        Qs[r*QK_STR + c4 + 2] = v.z; Qs[r*QK_STR + c4 + 3] = v.w;
    }

    float m_run[4], l_run[4], o[4][8];
    #pragma unroll
    for (int i = 0; i < 4; i++) {
        m_run[i] = -INFINITY; l_run[i] = 0.f;
        #pragma unroll
        for (int j = 0; j < 8; j++) o[i][j] = 0.f;
    }

    const int ntiles = blockIdx.x + 1;
    for (int t = 0; t < ntiles; t++) {
        const int k0 = t * FBC;
        __syncthreads();
        for (int i = tid; i < FBC * 48; i += 256) {
            int r = i / 48, c4 = (i % 48) * 4;
            float4 v = *(const float4*)(Kg + (long long)(k0 + r) * DQ_ + c4);
            Ks[r*QK_STR + c4 + 0] = v.x; Ks[r*QK_STR + c4 + 1] = v.y;
            Ks[r*QK_STR + c4 + 2] = v.z; Ks[r*QK_STR + c4 + 3] = v.w;
        }
        for (int i = tid; i < FBC * 32; i += 256) {
            int r = i / 32, c4 = (i % 32) * 4;
            float4 v = *(const float4*)(Vg + (long long)(k0 + r) * DV_ + c4);
            *(float4*)(Vs + r*V_STR + c4) = v;
        }
        __syncthreads();

        float s[4][4];
        #pragma unroll
        for (int i = 0; i < 4; i++)
            #pragma unroll
            for (int j = 0; j < 4; j++) s[i][j] = 0.f;
        for (int d = 0; d < DQ_; d++) {
            float a[4], b4[4];
            #pragma unroll
            for (int i = 0; i < 4; i++) a[i] = Qs[(ty*4+i)*QK_STR + d];
            #pragma unroll
            for (int j = 0; j < 4; j++) b4[j] = Ks[(tx*4+j)*QK_STR + d];
            #pragma unroll
            for (int i = 0; i < 4; i++)
                #pragma unroll
                for (int j = 0; j < 4; j++)
                    s[i][j] = fmaf(a[i], b4[j], s[i][j]);
        }
        #pragma unroll
        for (int i = 0; i < 4; i++) {
            int qrow = q0 + ty*4 + i;
            #pragma unroll
            for (int j = 0; j < 4; j++) {
                int kcol = k0 + tx*4 + j;
                s[i][j] = (kcol <= qrow) ? s[i][j] * scale : -INFINITY;
            }
        }
        #pragma unroll
        for (int i = 0; i < 4; i++) {
            float mt = fmaxf(fmaxf(s[i][0], s[i][1]), fmaxf(s[i][2], s[i][3]));
            #pragma unroll
            for (int off = 8; off; off >>= 1)
                mt = fmaxf(mt, __shfl_xor_sync(0xffffffffu, mt, off));
            float m_new = fmaxf(m_run[i], mt);
            float alpha = expf(m_run[i] - m_new);
            float ps = 0.f;
            #pragma unroll
            for (int j = 0; j < 4; j++) { s[i][j] = expf(s[i][j] - m_new); ps += s[i][j]; }
            #pragma unroll
            for (int off = 8; off; off >>= 1)
                ps += __shfl_xor_sync(0xffffffffu, ps, off);
            l_run[i] = l_run[i] * alpha + ps;
            m_run[i] = m_new;
            #pragma unroll
            for (int j = 0; j < 8; j++) o[i][j] *= alpha;
            *(float4*)(Ps + (ty*4+i)*P_STR + tx*4) =
                make_float4(tf32r(s[i][0]), tf32r(s[i][1]), tf32r(s[i][2]), tf32r(s[i][3]));
        }
        __syncthreads();
        for (int kk = 0; kk < FBC; kk++) {
            float p4[4];
            #pragma unroll
            for (int i = 0; i < 4; i++) p4[i] = Ps[(ty*4+i)*P_STR + kk];
            float4 v0 = *(const float4*)(Vs + kk*V_STR + tx*8);
            float4 v1 = *(const float4*)(Vs + kk*V_STR + tx*8 + 4);
            #pragma unroll
            for (int i = 0; i < 4; i++) {
                o[i][0] = fmaf(p4[i], v0.x, o[i][0]);
                o[i][1] = fmaf(p4[i], v0.y, o[i][1]);
                o[i][2] = fmaf(p4[i], v0.z, o[i][2]);
                o[i][3] = fmaf(p4[i], v0.w, o[i][3]);
                o[i][4] = fmaf(p4[i], v1.x, o[i][4]);
                o[i][5] = fmaf(p4[i], v1.y, o[i][5]);
                o[i][6] = fmaf(p4[i], v1.z, o[i][6]);
                o[i][7] = fmaf(p4[i], v1.w, o[i][7]);
            }
        }
    }

    const int b = z >> 4, h = z & 15;
    #pragma unroll
    for (int i = 0; i < 4; i++) {
        float inv = 1.f / l_run[i];
        long long tok = (long long)b * S_ + q0 + ty*4 + i;
        float* dst = outfl + tok * (H_*DV_) + h * DV_ + tx*8;
        #pragma unroll
        for (int j = 0; j < 8; j++) dst[j] = o[i][j] * inv;
    }
}

// ---- silu ----
__global__ void silu_mul2_kernel() {
    long long idx = (long long)blockIdx.x * 256 + threadIdx.x;
    if (idx >= (long long)TOK_ * INTER_) return;
    float g = g_gate[idx];
    float sig = 1.f / (1.f + expf(-g));
    g_gate[idx] = g * sig * g_up[idx];
}

static inline dim3 g1(int M, int N) { return dim3((N + 127) / 128, (M + 127) / 128, 1); }

extern "C" void kernel_launch(void* const* d_in, const int* in_sizes, int n_in,
                              void* d_out, int out_size)
{
    const float* hidden = (const float*)d_in[0];
    const int*   pos    = (const int*)  d_in[1];
    const float* Wq     = (const float*)d_in[2];
    const float* Wkva   = (const float*)d_in[3];
    const float* w_kvln = (const float*)d_in[4];
    const float* Wkvb   = (const float*)d_in[5];
    const float* Wo     = (const float*)d_in[6];
    const float* Wg     = (const float*)d_in[7];
    const float* Wu     = (const float*)d_in[8];
    const float* Wd     = (const float*)d_in[9];
    const float* w_ln1  = (const float*)d_in[10];
    const float* w_ln2  = (const float*)d_in[11];
    float* out = (float*)d_out;

    float *p_xln, *p_q, *p_ckv, *p_cln, *p_kv, *p_Q, *p_K, *p_V, *p_afl, *p_x2, *p_y, *p_g, *p_u;
    cudaGetSymbolAddress((void**)&p_xln, g_xln);
    cudaGetSymbolAddress((void**)&p_q,   g_q);
    cudaGetSymbolAddress((void**)&p_ckv, g_ckv);
    cudaGetSymbolAddress((void**)&p_cln, g_cln);
    cudaGetSymbolAddress((void**)&p_kv,  g_kv);
    cudaGetSymbolAddress((void**)&p_Q,   g_Qp);
    cudaGetSymbolAddress((void**)&p_K,   g_Kp);
    cudaGetSymbolAddress((void**)&p_V,   g_Vp);
    cudaGetSymbolAddress((void**)&p_afl, g_attnfl);
    cudaGetSymbolAddress((void**)&p_x2,  g_x2);
    cudaGetSymbolAddress((void**)&p_y,   g_y);
    cudaGetSymbolAddress((void**)&p_g,   g_gate);
    cudaGetSymbolAddress((void**)&p_u,   g_up);

    const int flash_smem = (FBR*QK_STR + FBC*QK_STR + FBC*V_STR + FBR*P_STR) * 4;
    cudaFuncSetAttribute(flash_kernel, cudaFuncAttributeMaxDynamicSharedMemorySize, flash_smem);

    init_invfreq2_kernel<<<1, 32>>>();

    rmsnorm2_kernel<<<TOK_, 256>>>(hidden, w_ln1, p_xln, HID_, HID_);

    gemm_kernel<0><<<g1(TOK_, H_*DQ_), 256>>>(p_xln, Wq, p_q, nullptr, TOK_, H_*DQ_, HID_);
    gemm_kernel<0><<<g1(TOK_, RANK_+DROPE_), 256>>>(p_xln, Wkva, p_ckv, nullptr, TOK_, RANK_+DROPE_, HID_);

    rmsnorm2_kernel<<<TOK_, 256>>>(p_ckv, w_kvln, p_cln, RANK_, RANK_+DROPE_);

    gemm_kernel<0><<<g1(TOK_, H_*(DNOPE_+DV_)), 256>>>(p_cln, Wkvb, p_kv, nullptr, TOK_, H_*(DNOPE_+DV_), RANK_);

    rope_q_kernel<<<(TOK_*H_ + 255)/256, 256>>>(pos);
    rope_k_kernel<<<(TOK_ + 255)/256, 256>>>(pos);

    {
        long long tq = (long long)TOK_*H_*DQ_;
        pack_q_kernel<<<(unsigned)((tq + 255)/256), 256>>>();
        pack_k_kernel<<<(unsigned)((tq + 255)/256), 256>>>();
        long long tv = (long long)TOK_*H_*DV_;
        pack_v_kernel<<<(unsigned)((tv + 255)/256), 256>>>();
    }

    flash_kernel<<<dim3(S_/FBR, B_*H_), 256, flash_smem>>>(p_Q, p_K, p_V, p_afl);

    gemm_kernel<1><<<g1(TOK_, HID_), 256>>>(p_afl, Wo, p_x2, hidden, TOK_, HID_, H_*DV_);

    rmsnorm2_kernel<<<TOK_, 256>>>(p_x2, w_ln2, p_y, HID_, HID_);

    gemm_kernel<0><<<g1(TOK_, INTER_), 256>>>(p_y, Wg, p_g, nullptr, TOK_, INTER_, HID_);
    gemm_kernel<0><<<g1(TOK_, INTER_), 256>>>(p_y, Wu, p_u, nullptr, TOK_, INTER_, HID_);

    silu_mul2_kernel<<<(unsigned)(((long long)TOK_*INTER_ + 255) / 256), 256>>>();

    gemm_kernel<1><<<g1(TOK_, HID_), 256>>>(p_g, Wd, out, p_x2, TOK_, HID_, INTER_);
}

// round 8
// speedup vs baseline: 9.2472x; 2.6288x over previous
#include <cuda_runtime.h>
#include <math.h>
#include <stdint.h>

#define B_      2
#define S_      2048
#define HID_    2048
#define H_      16
#define DQ_     192
#define DNOPE_  128
#define DROPE_  64
#define DV_     128
#define RANK_   512
#define INTER_  10944
#define TOK_    (B_*S_)
#define NEG_INF (-3.4028235e38f)

__device__ __forceinline__ float tf32r(float x) {
    float r;
    asm("cvt.rna.tf32.f32 %0, %1;" : "=f"(r) : "f"(x));
    return r;
}

__device__ __forceinline__ void mma_tf32(float* c, const uint32_t* a, const uint32_t* b) {
    asm volatile(
        "mma.sync.aligned.m16n8k8.row.col.f32.tf32.tf32.f32 "
        "{%0,%1,%2,%3}, {%4,%5,%6,%7}, {%8,%9}, {%0,%1,%2,%3};\n"
        : "+f"(c[0]), "+f"(c[1]), "+f"(c[2]), "+f"(c[3])
        : "r"(a[0]), "r"(a[1]), "r"(a[2]), "r"(a[3]), "r"(b[0]), "r"(b[1]));
}

__device__ float g_invfreq[32];
__device__ float g_xln    [TOK_*HID_];
__device__ float g_q      [TOK_*H_*DQ_];
__device__ float g_ckv    [TOK_*(RANK_+DROPE_)];
__device__ float g_cln    [TOK_*RANK_];
__device__ float g_kv     [TOK_*H_*(DNOPE_+DV_)];
__device__ float g_qrope  [TOK_*H_*DROPE_];
__device__ float g_krope  [TOK_*DROPE_];
__device__ float g_Qp     [(size_t)B_*H_*S_*DQ_];
__device__ float g_Kp     [(size_t)B_*H_*S_*DQ_];
__device__ float g_Vp     [(size_t)B_*H_*S_*DV_];
__device__ float g_attnfl [TOK_*H_*DV_];
__device__ float g_x2     [TOK_*HID_];
__device__ float g_y      [TOK_*HID_];
__device__ float g_gate   [TOK_*INTER_];
__device__ float g_up     [TOK_*INTER_];

// ---- yarn inv_freq ----
__global__ void init_invfreq2_kernel() {
    int j = threadIdx.x;
    if (j >= 32) return;
    const double dim = 64.0, base = 10000.0, orig_max = 4096.0;
    const double two_pi = 6.283185307179586476925286766559;
    double cd_fast = dim * log(orig_max / (32.0 * two_pi)) / (2.0 * log(base));
    double cd_slow = dim * log(orig_max / ( 1.0 * two_pi)) / (2.0 * log(base));
    double lowd  = floor(cd_fast); if (lowd < 0.0) lowd = 0.0;
    double highd = ceil(cd_slow);  if (highd > dim - 1.0) highd = dim - 1.0;
    double hid = (lowd == highd) ? highd + 0.001 : highd;
    double ar = (2.0 * (double)j) / dim;
    double freq_extra = 1.0 / pow(base, ar);
    double freq_inter = 1.0 / (40.0 * pow(base, ar));
    double ramp = ((double)j - lowd) / (hid - lowd);
    if (ramp < 0.0) ramp = 0.0;
    if (ramp > 1.0) ramp = 1.0;
    double mask = 1.0 - ramp;
    g_invfreq[j] = (float)(freq_inter * (1.0 - mask) + freq_extra * mask);
}

// ---- RMSNorm ----
__global__ void rmsnorm2_kernel(const float* __restrict__ x, const float* __restrict__ w,
                                float* __restrict__ out, int dim, int in_stride)
{
    const long long row = blockIdx.x;
    const float* xr = x + row * (long long)in_stride;
    __shared__ float buf[256];
    float partial = 0.f;
    for (int i = threadIdx.x; i < dim; i += 256) { float v = xr[i]; partial += v * v; }
    buf[threadIdx.x] = partial;
    __syncthreads();
    for (int stride = 128; stride > 0; stride >>= 1) {
        if (threadIdx.x < stride) buf[threadIdx.x] += buf[threadIdx.x + stride];
        __syncthreads();
    }
    float scale = rsqrtf(buf[0] / (float)dim + 1e-6f);
    for (int i = threadIdx.x; i < dim; i += 256)
        out[row * (long long)dim + i] = xr[i] * scale * w[i];
}

// ---- tensor-core TF32 GEMM: C = A[M,K] @ Bw[N,K]^T (+R) ----
// 128x128 block tile, 8 warps (2x4), each warp 64x32 via m16n8k8.
// Requires K % 32 == 0, M % 128 == 0. N arbitrary (guarded).
template<int MODE>
__global__ void __launch_bounds__(256) gemm_tc_kernel(
    const float* __restrict__ A, const float* __restrict__ Bw,
    float* __restrict__ C, const float* __restrict__ R,
    int M, int N, int K)
{
    __shared__ float As[128][36];
    __shared__ float Bs[128][36];
    const int m0 = blockIdx.y * 128, n0 = blockIdx.x * 128;
    const int tid = threadIdx.x;
    const int warp = tid >> 5, lane = tid & 31;
    const int wm = (warp >> 2) * 64;
    const int wn = (warp & 3) * 32;
    const int lr = lane >> 2;      // 0..7
    const int lc = lane & 3;       // 0..3

    float acc[4][4][4];
    #pragma unroll
    for (int mt = 0; mt < 4; mt++)
        #pragma unroll
        for (int nt = 0; nt < 4; nt++)
            #pragma unroll
            for (int i = 0; i < 4; i++) acc[mt][nt][i] = 0.f;

    for (int k0 = 0; k0 < K; k0 += 32) {
        #pragma unroll
        for (int i = 0; i < 4; i++) {
            int idx = tid + i * 256;            // 0..1023
            int r = idx >> 3, c4 = (idx & 7) * 4;
            float4 va = make_float4(0.f,0.f,0.f,0.f);
            int gm = m0 + r;
            if (gm < M) va = *(const float4*)(A + (long long)gm * K + k0 + c4);
            As[r][c4+0] = tf32r(va.x); As[r][c4+1] = tf32r(va.y);
            As[r][c4+2] = tf32r(va.z); As[r][c4+3] = tf32r(va.w);
            float4 vb = make_float4(0.f,0.f,0.f,0.f);
            int gn = n0 + r;
            if (gn < N) vb = *(const float4*)(Bw + (long long)gn * K + k0 + c4);
            Bs[r][c4+0] = tf32r(vb.x); Bs[r][c4+1] = tf32r(vb.y);
            Bs[r][c4+2] = tf32r(vb.z); Bs[r][c4+3] = tf32r(vb.w);
        }
        __syncthreads();
        #pragma unroll
        for (int ks = 0; ks < 32; ks += 8) {
            uint32_t af[4][4], bf[4][2];
            #pragma unroll
            for (int mt = 0; mt < 4; mt++) {
                int row = wm + mt * 16 + lr;
                af[mt][0] = __float_as_uint(As[row    ][ks + lc    ]);
                af[mt][1] = __float_as_uint(As[row + 8][ks + lc    ]);
                af[mt][2] = __float_as_uint(As[row    ][ks + lc + 4]);
                af[mt][3] = __float_as_uint(As[row + 8][ks + lc + 4]);
            }
            #pragma unroll
            for (int nt = 0; nt < 4; nt++) {
                int col = wn + nt * 8 + lr;
                bf[nt][0] = __float_as_uint(Bs[col][ks + lc    ]);
                bf[nt][1] = __float_as_uint(Bs[col][ks + lc + 4]);
            }
            #pragma unroll
            for (int mt = 0; mt < 4; mt++)
                #pragma unroll
                for (int nt = 0; nt < 4; nt++)
                    mma_tf32(acc[mt][nt], af[mt], bf[nt]);
        }
        __syncthreads();
    }

    #pragma unroll
    for (int mt = 0; mt < 4; mt++) {
        #pragma unroll
        for (int nt = 0; nt < 4; nt++) {
            int mm = m0 + wm + mt * 16 + lr;
            int nn = n0 + wn + nt * 8 + lc * 2;
            #pragma unroll
            for (int half = 0; half < 2; half++) {
                int mrow = mm + half * 8;
                if (mrow >= M) continue;
                float v0 = acc[mt][nt][half * 2 + 0];
                float v1 = acc[mt][nt][half * 2 + 1];
                if (nn < N) {
                    float o = v0;
                    if (MODE == 1) o += R[(long long)mrow * N + nn];
                    C[(long long)mrow * N + nn] = o;
                }
                if (nn + 1 < N) {
                    float o = v1;
                    if (MODE == 1) o += R[(long long)mrow * N + nn + 1];
                    C[(long long)mrow * N + nn + 1] = o;
                }
            }
        }
    }
}

// ---- RoPE ----
__global__ void rope_q_kernel(const int* __restrict__ pos_ids) {
    int idx = blockIdx.x * 256 + threadIdx.x;
    if (idx >= TOK_ * H_) return;
    int tok = idx / H_;
    const float* x = g_q + (long long)idx * DQ_ + DNOPE_;
    float* o = g_qrope + (long long)idx * DROPE_;
    float pos = (float)pos_ids[tok];
    for (int j = 0; j < 32; j++) {
        float th = pos * g_invfreq[j];
        float c = cosf(th), sn = sinf(th);
        float x1 = x[2*j], x2 = x[2*j+1];
        o[j]      = x1 * c - x2 * sn;
        o[j + 32] = x2 * c + x1 * sn;
    }
}

__global__ void rope_k_kernel(const int* __restrict__ pos_ids) {
    int tok = blockIdx.x * 256 + threadIdx.x;
    if (tok >= TOK_) return;
    const float* x = g_ckv + (long long)tok * (RANK_ + DROPE_) + RANK_;
    float* o = g_krope + (long long)tok * DROPE_;
    float pos = (float)pos_ids[tok];
    for (int j = 0; j < 32; j++) {
        float th = pos * g_invfreq[j];
        float c = cosf(th), sn = sinf(th);
        float x1 = x[2*j], x2 = x[2*j+1];
        o[j]      = x1 * c - x2 * sn;
        o[j + 32] = x2 * c + x1 * sn;
    }
}

// ---- pack kernels (layout transforms + TF32 truncation at source) ----
__global__ void pack_q_kernel() {
    long long idx = (long long)blockIdx.x * 256 + threadIdx.x;
    const long long total = (long long)TOK_ * H_ * DQ_;
    if (idx >= total) return;
    int d = (int)(idx % DQ_);
    int h = (int)((idx / DQ_) % H_);
    long long tok = idx / ((long long)DQ_ * H_);
    int b = (int)(tok / S_), s = (int)(tok % S_);
    float val = (d < DNOPE_)
        ? g_q[(tok * H_ + h) * DQ_ + d]
        : g_qrope[(tok * H_ + h) * DROPE_ + (d - DNOPE_)];
    g_Qp[(((long long)(b * H_ + h)) * S_ + s) * DQ_ + d] = tf32r(val);
}

__global__ void pack_k_kernel() {
    long long idx = (long long)blockIdx.x * 256 + threadIdx.x;
    const long long total = (long long)TOK_ * H_ * DQ_;
    if (idx >= total) return;
    int d = (int)(idx % DQ_);
    int h = (int)((idx / DQ_) % H_);
    long long tok = idx / ((long long)DQ_ * H_);
    int b = (int)(tok / S_), s = (int)(tok % S_);
    float val = (d < DNOPE_)
        ? g_kv[(tok * H_ + h) * (DNOPE_ + DV_) + d]
        : g_krope[tok * DROPE_ + (d - DNOPE_)];
    g_Kp[(((long long)(b * H_ + h)) * S_ + s) * DQ_ + d] = tf32r(val);
}

__global__ void pack_v_kernel() {
    long long idx = (long long)blockIdx.x * 256 + threadIdx.x;
    const long long total = (long long)TOK_ * H_ * DV_;
    if (idx >= total) return;
    int d = (int)(idx % DV_);
    int h = (int)((idx / DV_) % H_);
    long long tok = idx / ((long long)DV_ * H_);
    int b = (int)(tok / S_), s = (int)(tok % S_);
    g_Vp[(((long long)(b * H_ + h)) * S_ + s) * DV_ + d] =
        tf32r(g_kv[(tok * H_ + h) * (DNOPE_ + DV_) + DNOPE_ + d]);
}

// ---- fused flash attention (fp32 math, TF32-truncated operands, causal) ----
#define FBR 64
#define FBC 64
#define QK_STR 193
#define V_STR  132
#define P_STR  68

__global__ void __launch_bounds__(256) flash_kernel(
    const float* __restrict__ Qp, const float* __restrict__ Kp,
    const float* __restrict__ Vp, float* __restrict__ outfl)
{
    extern __shared__ float sm[];
    float* Qs = sm;
    float* Ks = sm + FBR * QK_STR;
    float* Vs = Ks + FBC * QK_STR;
    float* Ps = Vs + FBC * V_STR;

    const int z  = blockIdx.y;
    const int q0 = blockIdx.x * FBR;
    const int tid = threadIdx.x;
    const int tx = tid & 15, ty = tid >> 4;

    const float scale = 0.07216878364870323f;
    const float* Qg = Qp + ((long long)z * S_ + q0) * DQ_;
    const float* Kg = Kp + (long long)z * S_ * DQ_;
    const float* Vg = Vp + (long long)z * S_ * DV_;

    for (int i = tid; i < FBR * 48; i += 256) {
        int r = i / 48, c4 = (i % 48) * 4;
        float4 v = *(const float4*)(Qg + (long long)r * DQ_ + c4);
        Qs[r*QK_STR + c4 + 0] = v.x; Qs[r*QK_STR + c4 + 1] = v.y;
        Qs[r*QK_STR + c4 + 2] = v.z; Qs[r*QK_STR + c4 + 3] = v.w;
    }

    float m_run[4], l_run[4], o[4][8];
    #pragma unroll
    for (int i = 0; i < 4; i++) {
        m_run[i] = -INFINITY; l_run[i] = 0.f;
        #pragma unroll
        for (int j = 0; j < 8; j++) o[i][j] = 0.f;
    }

    const int ntiles = blockIdx.x + 1;
    for (int t = 0; t < ntiles; t++) {
        const int k0 = t * FBC;
        __syncthreads();
        for (int i = tid; i < FBC * 48; i += 256) {
            int r = i / 48, c4 = (i % 48) * 4;
            float4 v = *(const float4*)(Kg + (long long)(k0 + r) * DQ_ + c4);
            Ks[r*QK_STR + c4 + 0] = v.x; Ks[r*QK_STR + c4 + 1] = v.y;
            Ks[r*QK_STR + c4 + 2] = v.z; Ks[r*QK_STR + c4 + 3] = v.w;
        }
        for (int i = tid; i < FBC * 32; i += 256) {
            int r = i / 32, c4 = (i % 32) * 4;
            float4 v = *(const float4*)(Vg + (long long)(k0 + r) * DV_ + c4);
            *(float4*)(Vs + r*V_STR + c4) = v;
        }
        __syncthreads();

        float s[4][4];
        #pragma unroll
        for (int i = 0; i < 4; i++)
            #pragma unroll
            for (int j = 0; j < 4; j++) s[i][j] = 0.f;
        for (int d = 0; d < DQ_; d++) {
            float a[4], b4[4];
            #pragma unroll
            for (int i = 0; i < 4; i++) a[i] = Qs[(ty*4+i)*QK_STR + d];
            #pragma unroll
            for (int j = 0; j < 4; j++) b4[j] = Ks[(tx*4+j)*QK_STR + d];
            #pragma unroll
            for (int i = 0; i < 4; i++)
                #pragma unroll
                for (int j = 0; j < 4; j++)
                    s[i][j] = fmaf(a[i], b4[j], s[i][j]);
        }
        #pragma unroll
        for (int i = 0; i < 4; i++) {
            int qrow = q0 + ty*4 + i;
            #pragma unroll
            for (int j = 0; j < 4; j++) {
                int kcol = k0 + tx*4 + j;
                s[i][j] = (kcol <= qrow) ? s[i][j] * scale : -INFINITY;
            }
        }
        #pragma unroll
        for (int i = 0; i < 4; i++) {
            float mt = fmaxf(fmaxf(s[i][0], s[i][1]), fmaxf(s[i][2], s[i][3]));
            #pragma unroll
            for (int off = 8; off; off >>= 1)
                mt = fmaxf(mt, __shfl_xor_sync(0xffffffffu, mt, off));
            float m_new = fmaxf(m_run[i], mt);
            float alpha = expf(m_run[i] - m_new);
            float ps = 0.f;
            #pragma unroll
            for (int j = 0; j < 4; j++) { s[i][j] = expf(s[i][j] - m_new); ps += s[i][j]; }
            #pragma unroll
            for (int off = 8; off; off >>= 1)
                ps += __shfl_xor_sync(0xffffffffu, ps, off);
            l_run[i] = l_run[i] * alpha + ps;
            m_run[i] = m_new;
            #pragma unroll
            for (int j = 0; j < 8; j++) o[i][j] *= alpha;
            *(float4*)(Ps + (ty*4+i)*P_STR + tx*4) =
                make_float4(tf32r(s[i][0]), tf32r(s[i][1]), tf32r(s[i][2]), tf32r(s[i][3]));
        }
        __syncthreads();
        for (int kk = 0; kk < FBC; kk++) {
            float p4[4];
            #pragma unroll
            for (int i = 0; i < 4; i++) p4[i] = Ps[(ty*4+i)*P_STR + kk];
            float4 v0 = *(const float4*)(Vs + kk*V_STR + tx*8);
            float4 v1 = *(const float4*)(Vs + kk*V_STR + tx*8 + 4);
            #pragma unroll
            for (int i = 0; i < 4; i++) {
                o[i][0] = fmaf(p4[i], v0.x, o[i][0]);
                o[i][1] = fmaf(p4[i], v0.y, o[i][1]);
                o[i][2] = fmaf(p4[i], v0.z, o[i][2]);
                o[i][3] = fmaf(p4[i], v0.w, o[i][3]);
                o[i][4] = fmaf(p4[i], v1.x, o[i][4]);
                o[i][5] = fmaf(p4[i], v1.y, o[i][5]);
                o[i][6] = fmaf(p4[i], v1.z, o[i][6]);
                o[i][7] = fmaf(p4[i], v1.w, o[i][7]);
            }
        }
    }

    const int b = z >> 4, h = z & 15;
    #pragma unroll
    for (int i = 0; i < 4; i++) {
        float inv = 1.f / l_run[i];
        long long tok = (long long)b * S_ + q0 + ty*4 + i;
        float* dst = outfl + tok * (H_*DV_) + h * DV_ + tx*8;
        #pragma unroll
        for (int j = 0; j < 8; j++) dst[j] = o[i][j] * inv;
    }
}

// ---- silu ----
__global__ void silu_mul2_kernel() {
    long long idx = (long long)blockIdx.x * 256 + threadIdx.x;
    if (idx >= (long long)TOK_ * INTER_) return;
    float g = g_gate[idx];
    float sig = 1.f / (1.f + expf(-g));
    g_gate[idx] = g * sig * g_up[idx];
}

static inline dim3 g1(int M, int N) { return dim3((N + 127) / 128, (M + 127) / 128, 1); }

extern "C" void kernel_launch(void* const* d_in, const int* in_sizes, int n_in,
                              void* d_out, int out_size)
{
    const float* hidden = (const float*)d_in[0];
    const int*   pos    = (const int*)  d_in[1];
    const float* Wq     = (const float*)d_in[2];
    const float* Wkva   = (const float*)d_in[3];
    const float* w_kvln = (const float*)d_in[4];
    const float* Wkvb   = (const float*)d_in[5];
    const float* Wo     = (const float*)d_in[6];
    const float* Wg     = (const float*)d_in[7];
    const float* Wu     = (const float*)d_in[8];
    const float* Wd     = (const float*)d_in[9];
    const float* w_ln1  = (const float*)d_in[10];
    const float* w_ln2  = (const float*)d_in[11];
    float* out = (float*)d_out;

    float *p_xln, *p_q, *p_ckv, *p_cln, *p_kv, *p_Q, *p_K, *p_V, *p_afl, *p_x2, *p_y, *p_g, *p_u;
    cudaGetSymbolAddress((void**)&p_xln, g_xln);
    cudaGetSymbolAddress((void**)&p_q,   g_q);
    cudaGetSymbolAddress((void**)&p_ckv, g_ckv);
    cudaGetSymbolAddress((void**)&p_cln, g_cln);
    cudaGetSymbolAddress((void**)&p_kv,  g_kv);
    cudaGetSymbolAddress((void**)&p_Q,   g_Qp);
    cudaGetSymbolAddress((void**)&p_K,   g_Kp);
    cudaGetSymbolAddress((void**)&p_V,   g_Vp);
    cudaGetSymbolAddress((void**)&p_afl, g_attnfl);
    cudaGetSymbolAddress((void**)&p_x2,  g_x2);
    cudaGetSymbolAddress((void**)&p_y,   g_y);
    cudaGetSymbolAddress((void**)&p_g,   g_gate);
    cudaGetSymbolAddress((void**)&p_u,   g_up);

    const int flash_smem = (FBR*QK_STR + FBC*QK_STR + FBC*V_STR + FBR*P_STR) * 4;
    cudaFuncSetAttribute(flash_kernel, cudaFuncAttributeMaxDynamicSharedMemorySize, flash_smem);

    init_invfreq2_kernel<<<1, 32>>>();

    rmsnorm2_kernel<<<TOK_, 256>>>(hidden, w_ln1, p_xln, HID_, HID_);

    gemm_tc_kernel<0><<<g1(TOK_, H_*DQ_), 256>>>(p_xln, Wq, p_q, nullptr, TOK_, H_*DQ_, HID_);
    gemm_tc_kernel<0><<<g1(TOK_, RANK_+DROPE_), 256>>>(p_xln, Wkva, p_ckv, nullptr, TOK_, RANK_+DROPE_, HID_);

    rmsnorm2_kernel<<<TOK_, 256>>>(p_ckv, w_kvln, p_cln, RANK_, RANK_+DROPE_);

    gemm_tc_kernel<0><<<g1(TOK_, H_*(DNOPE_+DV_)), 256>>>(p_cln, Wkvb, p_kv, nullptr, TOK_, H_*(DNOPE_+DV_), RANK_);

    rope_q_kernel<<<(TOK_*H_ + 255)/256, 256>>>(pos);
    rope_k_kernel<<<(TOK_ + 255)/256, 256>>>(pos);

    {
        long long tq = (long long)TOK_*H_*DQ_;
        pack_q_kernel<<<(unsigned)((tq + 255)/256), 256>>>();
        pack_k_kernel<<<(unsigned)((tq + 255)/256), 256>>>();
        long long tv = (long long)TOK_*H_*DV_;
        pack_v_kernel<<<(unsigned)((tv + 255)/256), 256>>>();
    }

    flash_kernel<<<dim3(S_/FBR, B_*H_), 256, flash_smem>>>(p_Q, p_K, p_V, p_afl);

    gemm_tc_kernel<1><<<g1(TOK_, HID_), 256>>>(p_afl, Wo, p_x2, hidden, TOK_, HID_, H_*DV_);

    rmsnorm2_kernel<<<TOK_, 256>>>(p_x2, w_ln2, p_y, HID_, HID_);

    gemm_tc_kernel<0><<<g1(TOK_, INTER_), 256>>>(p_y, Wg, p_g, nullptr, TOK_, INTER_, HID_);
    gemm_tc_kernel<0><<<g1(TOK_, INTER_), 256>>>(p_y, Wu, p_u, nullptr, TOK_, INTER_, HID_);

    silu_mul2_kernel<<<(unsigned)(((long long)TOK_*INTER_ + 255) / 256), 256>>>();

    gemm_tc_kernel<1><<<g1(TOK_, HID_), 256>>>(p_g, Wd, out, p_x2, TOK_, HID_, INTER_);
}

// round 9
// speedup vs baseline: 11.0360x; 1.1934x over previous
#include <cuda_runtime.h>
#include <math.h>
#include <stdint.h>

#define B_      2
#define S_      2048
#define HID_    2048
#define H_      16
#define DQ_     192
#define DNOPE_  128
#define DROPE_  64
#define DV_     128
#define RANK_   512
#define INTER_  10944
#define TOK_    (B_*S_)
#define NEG_INF (-3.4028235e38f)

__device__ __forceinline__ float tf32r(float x) {
    float r;
    asm("cvt.rna.tf32.f32 %0, %1;" : "=f"(r) : "f"(x));
    return r;
}

__device__ __forceinline__ void mma_tf32(float* c, const uint32_t* a, const uint32_t* b) {
    asm volatile(
        "mma.sync.aligned.m16n8k8.row.col.f32.tf32.tf32.f32 "
        "{%0,%1,%2,%3}, {%4,%5,%6,%7}, {%8,%9}, {%0,%1,%2,%3};\n"
        : "+f"(c[0]), "+f"(c[1]), "+f"(c[2]), "+f"(c[3])
        : "r"(a[0]), "r"(a[1]), "r"(a[2]), "r"(a[3]), "r"(b[0]), "r"(b[1]));
}

__device__ __forceinline__ void cp_async16(void* smem_dst, const void* gsrc, unsigned bytes) {
    unsigned saddr = (unsigned)__cvta_generic_to_shared(smem_dst);
    asm volatile("cp.async.cg.shared.global [%0], [%1], 16, %2;"
                 :: "r"(saddr), "l"(gsrc), "r"(bytes));
}

// ---------------- device scratch ----------------
__device__ float g_invfreq[32];
__device__ float g_xln    [TOK_*HID_];
__device__ float g_q      [TOK_*H_*DQ_];
__device__ float g_ckv    [TOK_*(RANK_+DROPE_)];
__device__ float g_cln    [TOK_*RANK_];
__device__ float g_kv     [TOK_*H_*(DNOPE_+DV_)];
__device__ float g_qrope  [TOK_*H_*DROPE_];
__device__ float g_krope  [TOK_*DROPE_];
__device__ float g_Qp     [(size_t)B_*H_*S_*DQ_];
__device__ float g_Kp     [(size_t)B_*H_*S_*DQ_];
__device__ float g_Vt     [(size_t)B_*H_*DV_*S_];
__device__ float g_attnfl [TOK_*H_*DV_];
__device__ float g_x2     [TOK_*HID_];
__device__ float g_y      [TOK_*HID_];
__device__ float g_gate   [TOK_*INTER_];
__device__ float g_up     [TOK_*INTER_];
// pre-truncated weights
__device__ float g_tWq   [(size_t)H_*DQ_*HID_];
__device__ float g_tWkva [(size_t)(RANK_+DROPE_)*HID_];
__device__ float g_tWkvb [(size_t)H_*(DNOPE_+DV_)*RANK_];
__device__ float g_tWo   [(size_t)HID_*H_*DV_];
__device__ float g_tWg   [(size_t)INTER_*HID_];
__device__ float g_tWu   [(size_t)INTER_*HID_];
__device__ float g_tWd   [(size_t)HID_*INTER_];

// ---- weight pre-truncation (float4 grid-stride) ----
__global__ void trunc_kernel(const float* __restrict__ src, float* __restrict__ dst, long long n4) {
    long long i = (long long)blockIdx.x * blockDim.x + threadIdx.x;
    long long stride = (long long)gridDim.x * blockDim.x;
    for (; i < n4; i += stride) {
        float4 v = ((const float4*)src)[i];
        v.x = tf32r(v.x); v.y = tf32r(v.y); v.z = tf32r(v.z); v.w = tf32r(v.w);
        ((float4*)dst)[i] = v;
    }
}

// ---- yarn inv_freq ----
__global__ void init_invfreq2_kernel() {
    int j = threadIdx.x;
    if (j >= 32) return;
    const double dim = 64.0, base = 10000.0, orig_max = 4096.0;
    const double two_pi = 6.283185307179586476925286766559;
    double cd_fast = dim * log(orig_max / (32.0 * two_pi)) / (2.0 * log(base));
    double cd_slow = dim * log(orig_max / ( 1.0 * two_pi)) / (2.0 * log(base));
    double lowd  = floor(cd_fast); if (lowd < 0.0) lowd = 0.0;
    double highd = ceil(cd_slow);  if (highd > dim - 1.0) highd = dim - 1.0;
    double hid = (lowd == highd) ? highd + 0.001 : highd;
    double ar = (2.0 * (double)j) / dim;
    double freq_extra = 1.0 / pow(base, ar);
    double freq_inter = 1.0 / (40.0 * pow(base, ar));
    double ramp = ((double)j - lowd) / (hid - lowd);
    if (ramp < 0.0) ramp = 0.0;
    if (ramp > 1.0) ramp = 1.0;
    double mask = 1.0 - ramp;
    g_invfreq[j] = (float)(freq_inter * (1.0 - mask) + freq_extra * mask);
}

// ---- RMSNorm (output TF32-truncated: feeds matmuls only) ----
__global__ void rmsnorm2_kernel(const float* __restrict__ x, const float* __restrict__ w,
                                float* __restrict__ out, int dim, int in_stride)
{
    const long long row = blockIdx.x;
    const float* xr = x + row * (long long)in_stride;
    __shared__ float buf[256];
    float partial = 0.f;
    for (int i = threadIdx.x; i < dim; i += 256) { float v = xr[i]; partial += v * v; }
    buf[threadIdx.x] = partial;
    __syncthreads();
    for (int stride = 128; stride > 0; stride >>= 1) {
        if (threadIdx.x < stride) buf[threadIdx.x] += buf[threadIdx.x + stride];
        __syncthreads();
    }
    float scale = rsqrtf(buf[0] / (float)dim + 1e-6f);
    for (int i = threadIdx.x; i < dim; i += 256)
        out[row * (long long)dim + i] = tf32r(xr[i] * scale * w[i]);
}

// ---- GEMM v3: cp.async 2-stage pipeline, no in-loop cvt ----
// C = A[M,K] @ Bw[N,K]^T (+R). Operands must be pre-truncated. M%128==0, K%32==0.
#define GA(st,r,c) sA[((st)*128 + (r))*36 + (c)]
#define GB(st,r,c) sB[((st)*128 + (r))*36 + (c)]
template<int MODE>
__global__ void __launch_bounds__(256) gemm_tc3(
    const float* __restrict__ A, const float* __restrict__ Bw,
    float* __restrict__ C, const float* __restrict__ R,
    int M, int N, int K)
{
    extern __shared__ float smem[];
    float* sA = smem;                     // [2][128][36]
    float* sB = smem + 2*128*36;
    const int m0 = blockIdx.y * 128, n0 = blockIdx.x * 128;
    const int tid = threadIdx.x;
    const int warp = tid >> 5, lane = tid & 31;
    const int wm = (warp >> 2) * 64;
    const int wn = (warp & 3) * 32;
    const int lr = lane >> 2;
    const int lc = lane & 3;

    float acc[4][4][4];
    #pragma unroll
    for (int mt = 0; mt < 4; mt++)
        #pragma unroll
        for (int nt = 0; nt < 4; nt++)
            #pragma unroll
            for (int i = 0; i < 4; i++) acc[mt][nt][i] = 0.f;

    const int KT = K >> 5;

    // prefetch tile 0
    {
        const int k0 = 0;
        #pragma unroll
        for (int i = 0; i < 4; i++) {
            int idx = tid + i * 256;
            int r = idx >> 3, c4 = (idx & 7) * 4;
            cp_async16(&GA(0, r, c4), A + (long long)(m0 + r) * K + k0 + c4, 16);
            int gn = n0 + r;
            int gnc = gn < N ? gn : 0;
            cp_async16(&GB(0, r, c4), Bw + (long long)gnc * K + k0 + c4, gn < N ? 16u : 0u);
        }
        asm volatile("cp.async.commit_group;");
    }

    for (int kt = 0; kt < KT; kt++) {
        const int st = kt & 1;
        if (kt + 1 < KT) {
            const int k0 = (kt + 1) << 5;
            #pragma unroll
            for (int i = 0; i < 4; i++) {
                int idx = tid + i * 256;
                int r = idx >> 3, c4 = (idx & 7) * 4;
                cp_async16(&GA(st ^ 1, r, c4), A + (long long)(m0 + r) * K + k0 + c4, 16);
                int gn = n0 + r;
                int gnc = gn < N ? gn : 0;
                cp_async16(&GB(st ^ 1, r, c4), Bw + (long long)gnc * K + k0 + c4, gn < N ? 16u : 0u);
            }
            asm volatile("cp.async.commit_group;");
            asm volatile("cp.async.wait_group 1;");
        } else {
            asm volatile("cp.async.wait_group 0;");
        }
        __syncthreads();

        #pragma unroll
        for (int ks = 0; ks < 32; ks += 8) {
            uint32_t af[4][4], bf[4][2];
            #pragma unroll
            for (int mt = 0; mt < 4; mt++) {
                int row = wm + mt * 16 + lr;
                af[mt][0] = __float_as_uint(GA(st, row,     ks + lc));
                af[mt][1] = __float_as_uint(GA(st, row + 8, ks + lc));
                af[mt][2] = __float_as_uint(GA(st, row,     ks + lc + 4));
                af[mt][3] = __float_as_uint(GA(st, row + 8, ks + lc + 4));
            }
            #pragma unroll
            for (int nt = 0; nt < 4; nt++) {
                int col = wn + nt * 8 + lr;
                bf[nt][0] = __float_as_uint(GB(st, col, ks + lc));
                bf[nt][1] = __float_as_uint(GB(st, col, ks + lc + 4));
            }
            #pragma unroll
            for (int mt = 0; mt < 4; mt++)
                #pragma unroll
                for (int nt = 0; nt < 4; nt++)
                    mma_tf32(acc[mt][nt], af[mt], bf[nt]);
        }
        __syncthreads();
    }

    #pragma unroll
    for (int mt = 0; mt < 4; mt++) {
        #pragma unroll
        for (int nt = 0; nt < 4; nt++) {
            int mm = m0 + wm + mt * 16 + lr;
            int nn = n0 + wn + nt * 8 + lc * 2;
            #pragma unroll
            for (int half = 0; half < 2; half++) {
                int mrow = mm + half * 8;
                float v0 = acc[mt][nt][half * 2 + 0];
                float v1 = acc[mt][nt][half * 2 + 1];
                if (nn < N) {
                    float o = v0;
                    if (MODE == 1) o += R[(long long)mrow * N + nn];
                    C[(long long)mrow * N + nn] = o;
                }
                if (nn + 1 < N) {
                    float o = v1;
                    if (MODE == 1) o += R[(long long)mrow * N + nn + 1];
                    C[(long long)mrow * N + nn + 1] = o;
                }
            }
        }
    }
}

// ---- RoPE ----
__global__ void rope_q_kernel(const int* __restrict__ pos_ids) {
    int idx = blockIdx.x * 256 + threadIdx.x;
    if (idx >= TOK_ * H_) return;
    int tok = idx / H_;
    const float* x = g_q + (long long)idx * DQ_ + DNOPE_;
    float* o = g_qrope + (long long)idx * DROPE_;
    float pos = (float)pos_ids[tok];
    for (int j = 0; j < 32; j++) {
        float th = pos * g_invfreq[j];
        float c = cosf(th), sn = sinf(th);
        float x1 = x[2*j], x2 = x[2*j+1];
        o[j]      = x1 * c - x2 * sn;
        o[j + 32] = x2 * c + x1 * sn;
    }
}

__global__ void rope_k_kernel(const int* __restrict__ pos_ids) {
    int tok = blockIdx.x * 256 + threadIdx.x;
    if (tok >= TOK_) return;
    const float* x = g_ckv + (long long)tok * (RANK_ + DROPE_) + RANK_;
    float* o = g_krope + (long long)tok * DROPE_;
    float pos = (float)pos_ids[tok];
    for (int j = 0; j < 32; j++) {
        float th = pos * g_invfreq[j];
        float c = cosf(th), sn = sinf(th);
        float x1 = x[2*j], x2 = x[2*j+1];
        o[j]      = x1 * c - x2 * sn;
        o[j + 32] = x2 * c + x1 * sn;
    }
}

// ---- pack Q/K (TF32-truncated); V transposed via smem tiles ----
__global__ void pack_q_kernel() {
    long long idx = (long long)blockIdx.x * 256 + threadIdx.x;
    const long long total = (long long)TOK_ * H_ * DQ_;
    if (idx >= total) return;
    int d = (int)(idx % DQ_);
    int h = (int)((idx / DQ_) % H_);
    long long tok = idx / ((long long)DQ_ * H_);
    int b = (int)(tok / S_), s = (int)(tok % S_);
    float val = (d < DNOPE_)
        ? g_q[(tok * H_ + h) * DQ_ + d]
        : g_qrope[(tok * H_ + h) * DROPE_ + (d - DNOPE_)];
    g_Qp[(((long long)(b * H_ + h)) * S_ + s) * DQ_ + d] = tf32r(val);
}

__global__ void pack_k_kernel() {
    long long idx = (long long)blockIdx.x * 256 + threadIdx.x;
    const long long total = (long long)TOK_ * H_ * DQ_;
    if (idx >= total) return;
    int d = (int)(idx % DQ_);
    int h = (int)((idx / DQ_) % H_);
    long long tok = idx / ((long long)DQ_ * H_);
    int b = (int)(tok / S_), s = (int)(tok % S_);
    float val = (d < DNOPE_)
        ? g_kv[(tok * H_ + h) * (DNOPE_ + DV_) + d]
        : g_krope[tok * DROPE_ + (d - DNOPE_)];
    g_Kp[(((long long)(b * H_ + h)) * S_ + s) * DQ_ + d] = tf32r(val);
}

__global__ void transpose_v_kernel() {   // g_kv [tok][h][128+d] -> g_Vt [z][d][s]
    __shared__ float t[32][33];
    int z = blockIdx.z;
    int d0 = blockIdx.y * 32, s0 = blockIdx.x * 32;
    int b = z >> 4, h = z & 15;
    int tx = threadIdx.x, ty0 = threadIdx.y;   // 32 x 8
    #pragma unroll
    for (int dy = 0; dy < 32; dy += 8) {
        int ty = ty0 + dy;
        t[ty][tx] = g_kv[(((long long)b * S_ + s0 + ty) * H_ + h) * (DNOPE_ + DV_) + DNOPE_ + d0 + tx];
    }
    __syncthreads();
    #pragma unroll
    for (int dy = 0; dy < 32; dy += 8) {
        int ty = ty0 + dy;
        g_Vt[((long long)z * DV_ + d0 + ty) * S_ + s0 + tx] = tf32r(t[tx][ty]);
    }
}

// ---- tensor-core flash attention (causal, online softmax) ----
#define FQ_STR 196
#define FS_STR 68
#define FV_STR 68
#define FLASH_SMEM ((2*64*FQ_STR + 128*FV_STR + 64*FS_STR + 192) * 4)

__global__ void __launch_bounds__(256) flash_mma_kernel(
    const float* __restrict__ Qp, const float* __restrict__ Kp,
    const float* __restrict__ Vt, float* __restrict__ outfl)
{
    extern __shared__ float sm[];
    float* Qs = sm;                        // 64 x 196
    float* Ks = Qs + 64*FQ_STR;            // 64 x 196
    float* Vs = Ks + 64*FQ_STR;            // 128 x 68
    float* Ss = Vs + 128*FV_STR;           // 64 x 68
    float* m_s = Ss + 64*FS_STR;
    float* l_s = m_s + 64;
    float* a_s = l_s + 64;

    const int z = blockIdx.y;
    const int q0 = blockIdx.x * 64;
    const int tid = threadIdx.x;
    const int warp = tid >> 5, lane = tid & 31;
    const int lr = lane >> 2, lc = lane & 3;
    const int wm = (warp & 3) * 16;        // rows for this warp
    const int wn_qk = (warp >> 2) * 32;    // QK col half
    const int wn_pv = (warp >> 2) * 64;    // PV col half

    const float scale = 0.07216878364870323f; // 192^-0.5
    const float* Qg = Qp + ((long long)z * S_ + q0) * DQ_;
    const float* Kg = Kp + (long long)z * S_ * DQ_;
    const float* Vg = Vt + (long long)z * DV_ * S_;

    for (int i = tid; i < 64 * 48; i += 256) {
        int r = i / 48, c4 = (i % 48) * 4;
        *(float4*)(Qs + r * FQ_STR + c4) = *(const float4*)(Qg + (long long)r * DQ_ + c4);
    }
    if (tid < 64) { m_s[tid] = -1e30f; l_s[tid] = 0.f; }

    float oacc[8][4];
    #pragma unroll
    for (int nt = 0; nt < 8; nt++)
        #pragma unroll
        for (int i = 0; i < 4; i++) oacc[nt][i] = 0.f;

    for (int t = 0; t <= blockIdx.x; t++) {
        const int k0 = t * 64;
        __syncthreads();   // previous PV / init done before K,V,Ss overwrite
        for (int i = tid; i < 64 * 48; i += 256) {
            int r = i / 48, c4 = (i % 48) * 4;
            *(float4*)(Ks + r * FQ_STR + c4) = *(const float4*)(Kg + (long long)(k0 + r) * DQ_ + c4);
        }
        for (int i = tid; i < 128 * 16; i += 256) {
            int r = i >> 4, c4 = (i & 15) * 4;
            *(float4*)(Vs + r * FV_STR + c4) = *(const float4*)(Vg + (long long)r * S_ + k0 + c4);
        }
        __syncthreads();

        // QK^T : 16 rows x 32 cols per warp
        float sc[4][4];
        #pragma unroll
        for (int nt = 0; nt < 4; nt++)
            #pragma unroll
            for (int i = 0; i < 4; i++) sc[nt][i] = 0.f;
        #pragma unroll
        for (int ks = 0; ks < DQ_; ks += 8) {
            uint32_t af[4], bf[4][2];
            af[0] = __float_as_uint(Qs[(wm + lr    ) * FQ_STR + ks + lc]);
            af[1] = __float_as_uint(Qs[(wm + lr + 8) * FQ_STR + ks + lc]);
            af[2] = __float_as_uint(Qs[(wm + lr    ) * FQ_STR + ks + lc + 4]);
            af[3] = __float_as_uint(Qs[(wm + lr + 8) * FQ_STR + ks + lc + 4]);
            #pragma unroll
            for (int nt = 0; nt < 4; nt++) {
                int col = wn_qk + nt * 8 + lr;
                bf[nt][0] = __float_as_uint(Ks[col * FQ_STR + ks + lc]);
                bf[nt][1] = __float_as_uint(Ks[col * FQ_STR + ks + lc + 4]);
            }
            #pragma unroll
            for (int nt = 0; nt < 4; nt++)
                mma_tf32(sc[nt], af, bf[nt]);
        }
        // scale + causal mask + store scores
        #pragma unroll
        for (int nt = 0; nt < 4; nt++) {
            int c = wn_qk + nt * 8 + lc * 2;
            int r0 = wm + lr, r1 = wm + lr + 8;
            float v00 = sc[nt][0] * scale, v01 = sc[nt][1] * scale;
            float v10 = sc[nt][2] * scale, v11 = sc[nt][3] * scale;
            if (k0 + c     > q0 + r0) v00 = -1e30f;
            if (k0 + c + 1 > q0 + r0) v01 = -1e30f;
            if (k0 + c     > q0 + r1) v10 = -1e30f;
            if (k0 + c + 1 > q0 + r1) v11 = -1e30f;
            *(float2*)(Ss + r0 * FS_STR + c) = make_float2(v00, v01);
            *(float2*)(Ss + r1 * FS_STR + c) = make_float2(v10, v11);
        }
        __syncthreads();

        // online softmax: 4 threads per row, 16 cols each
        {
            int r = tid >> 2, p4 = tid & 3;
            int cb = p4 * 16;
            float mx = -1e30f;
            #pragma unroll
            for (int j = 0; j < 16; j++) mx = fmaxf(mx, Ss[r * FS_STR + cb + j]);
            mx = fmaxf(mx, __shfl_xor_sync(0xffffffffu, mx, 1));
            mx = fmaxf(mx, __shfl_xor_sync(0xffffffffu, mx, 2));
            float m_old = m_s[r];
            float m_new = fmaxf(m_old, mx);
            float alpha = __expf(m_old - m_new);
            float es = 0.f;
            #pragma unroll
            for (int j = 0; j < 16; j++) {
                float e = __expf(Ss[r * FS_STR + cb + j] - m_new);
                Ss[r * FS_STR + cb + j] = tf32r(e);
                es += e;
            }
            es += __shfl_xor_sync(0xffffffffu, es, 1);
            es += __shfl_xor_sync(0xffffffffu, es, 2);
            if (p4 == 0) {
                l_s[r] = l_s[r] * alpha + es;
                m_s[r] = m_new;
                a_s[r] = alpha;
            }
        }
        __syncthreads();

        // PV: rescale then accumulate. 16 rows x 64 cols per warp.
        {
            float a0 = a_s[wm + lr], a1 = a_s[wm + lr + 8];
            #pragma unroll
            for (int nt = 0; nt < 8; nt++) {
                oacc[nt][0] *= a0; oacc[nt][1] *= a0;
                oacc[nt][2] *= a1; oacc[nt][3] *= a1;
            }
            #pragma unroll
            for (int ks = 0; ks < 64; ks += 8) {
                uint32_t af[4], bf[8][2];
                af[0] = __float_as_uint(Ss[(wm + lr    ) * FS_STR + ks + lc]);
                af[1] = __float_as_uint(Ss[(wm + lr + 8) * FS_STR + ks + lc]);
                af[2] = __float_as_uint(Ss[(wm + lr    ) * FS_STR + ks + lc + 4]);
                af[3] = __float_as_uint(Ss[(wm + lr + 8) * FS_STR + ks + lc + 4]);
                #pragma unroll
                for (int nt = 0; nt < 8; nt++) {
                    int col = wn_pv + nt * 8 + lr;
                    bf[nt][0] = __float_as_uint(Vs[col * FV_STR + ks + lc]);
                    bf[nt][1] = __float_as_uint(Vs[col * FV_STR + ks + lc + 4]);
                }
                #pragma unroll
                for (int nt = 0; nt < 8; nt++)
                    mma_tf32(oacc[nt], af, bf[nt]);
            }
        }
    }
    __syncthreads();

    // epilogue: divide by l, truncate (feeds Wo matmul), write [tok, h*128+d]
    {
        const int b = z >> 4, h = z & 15;
        float il0 = 1.f / l_s[wm + lr];
        float il1 = 1.f / l_s[wm + lr + 8];
        long long tok0 = (long long)b * S_ + q0 + wm + lr;
        long long tok1 = tok0 + 8;
        #pragma unroll
        for (int nt = 0; nt < 8; nt++) {
            int c = wn_pv + nt * 8 + lc * 2;
            *(float2*)(outfl + tok0 * (H_*DV_) + h * DV_ + c) =
                make_float2(tf32r(oacc[nt][0] * il0), tf32r(oacc[nt][1] * il0));
            *(float2*)(outfl + tok1 * (H_*DV_) + h * DV_ + c) =
                make_float2(tf32r(oacc[nt][2] * il1), tf32r(oacc[nt][3] * il1));
        }
    }
}

// ---- silu (output truncated: feeds Wd matmul only) ----
__global__ void silu_mul2_kernel() {
    long long idx = (long long)blockIdx.x * 256 + threadIdx.x;
    if (idx >= (long long)TOK_ * INTER_) return;
    float g = g_gate[idx];
    float sig = 1.f / (1.f + expf(-g));
    g_gate[idx] = tf32r(g * sig * g_up[idx]);
}

static inline dim3 g1(int M, int N) { return dim3((N + 127) / 128, (M + 127) / 128, 1); }

extern "C" void kernel_launch(void* const* d_in, const int* in_sizes, int n_in,
                              void* d_out, int out_size)
{
    const float* hidden = (const float*)d_in[0];
    const int*   pos    = (const int*)  d_in[1];
    const float* Wq     = (const float*)d_in[2];
    const float* Wkva   = (const float*)d_in[3];
    const float* w_kvln = (const float*)d_in[4];
    const float* Wkvb   = (const float*)d_in[5];
    const float* Wo     = (const float*)d_in[6];
    const float* Wg     = (const float*)d_in[7];
    const float* Wu     = (const float*)d_in[8];
    const float* Wd     = (const float*)d_in[9];
    const float* w_ln1  = (const float*)d_in[10];
    const float* w_ln2  = (const float*)d_in[11];
    float* out = (float*)d_out;

    float *p_xln, *p_q, *p_ckv, *p_cln, *p_kv, *p_Q, *p_K, *p_V, *p_afl, *p_x2, *p_y, *p_g, *p_u;
    float *t_wq, *t_wkva, *t_wkvb, *t_wo, *t_wg, *t_wu, *t_wd;
    cudaGetSymbolAddress((void**)&p_xln, g_xln);
    cudaGetSymbolAddress((void**)&p_q,   g_q);
    cudaGetSymbolAddress((void**)&p_ckv, g_ckv);
    cudaGetSymbolAddress((void**)&p_cln, g_cln);
    cudaGetSymbolAddress((void**)&p_kv,  g_kv);
    cudaGetSymbolAddress((void**)&p_Q,   g_Qp);
    cudaGetSymbolAddress((void**)&p_K,   g_Kp);
    cudaGetSymbolAddress((void**)&p_V,   g_Vt);
    cudaGetSymbolAddress((void**)&p_afl, g_attnfl);
    cudaGetSymbolAddress((void**)&p_x2,  g_x2);
    cudaGetSymbolAddress((void**)&p_y,   g_y);
    cudaGetSymbolAddress((void**)&p_g,   g_gate);
    cudaGetSymbolAddress((void**)&p_u,   g_up);
    cudaGetSymbolAddress((void**)&t_wq,   g_tWq);
    cudaGetSymbolAddress((void**)&t_wkva, g_tWkva);
    cudaGetSymbolAddress((void**)&t_wkvb, g_tWkvb);
    cudaGetSymbolAddress((void**)&t_wo,   g_tWo);
    cudaGetSymbolAddress((void**)&t_wg,   g_tWg);
    cudaGetSymbolAddress((void**)&t_wu,   g_tWu);
    cudaGetSymbolAddress((void**)&t_wd,   g_tWd);

    const int gemm_smem = 2 * 2 * 128 * 36 * 4;     // 73728
    cudaFuncSetAttribute(gemm_tc3<0>, cudaFuncAttributeMaxDynamicSharedMemorySize, gemm_smem);
    cudaFuncSetAttribute(gemm_tc3<1>, cudaFuncAttributeMaxDynamicSharedMemorySize, gemm_smem);
    cudaFuncSetAttribute(flash_mma_kernel, cudaFuncAttributeMaxDynamicSharedMemorySize, FLASH_SMEM);

    init_invfreq2_kernel<<<1, 32>>>();

    // pre-truncate weights (once per replay; HBM-bound ~110us)
    trunc_kernel<<<1184, 256>>>(Wq,   t_wq,   (long long)H_*DQ_*HID_/4);
    trunc_kernel<<<1184, 256>>>(Wkva, t_wkva, (long long)(RANK_+DROPE_)*HID_/4);
    trunc_kernel<<<1184, 256>>>(Wkvb, t_wkvb, (long long)H_*(DNOPE_+DV_)*RANK_/4);
    trunc_kernel<<<1184, 256>>>(Wo,   t_wo,   (long long)HID_*H_*DV_/4);
    trunc_kernel<<<1184, 256>>>(Wg,   t_wg,   (long long)INTER_*HID_/4);
    trunc_kernel<<<1184, 256>>>(Wu,   t_wu,   (long long)INTER_*HID_/4);
    trunc_kernel<<<1184, 256>>>(Wd,   t_wd,   (long long)HID_*INTER_/4);

    rmsnorm2_kernel<<<TOK_, 256>>>(hidden, w_ln1, p_xln, HID_, HID_);

    gemm_tc3<0><<<g1(TOK_, H_*DQ_), 256, gemm_smem>>>(p_xln, t_wq, p_q, nullptr, TOK_, H_*DQ_, HID_);
    gemm_tc3<0><<<g1(TOK_, RANK_+DROPE_), 256, gemm_smem>>>(p_xln, t_wkva, p_ckv, nullptr, TOK_, RANK_+DROPE_, HID_);

    rmsnorm2_kernel<<<TOK_, 256>>>(p_ckv, w_kvln, p_cln, RANK_, RANK_+DROPE_);

    gemm_tc3<0><<<g1(TOK_, H_*(DNOPE_+DV_)), 256, gemm_smem>>>(p_cln, t_wkvb, p_kv, nullptr, TOK_, H_*(DNOPE_+DV_), RANK_);

    rope_q_kernel<<<(TOK_*H_ + 255)/256, 256>>>(pos);
    rope_k_kernel<<<(TOK_ + 255)/256, 256>>>(pos);

    {
        long long tq = (long long)TOK_*H_*DQ_;
        pack_q_kernel<<<(unsigned)((tq + 255)/256), 256>>>();
        pack_k_kernel<<<(unsigned)((tq + 255)/256), 256>>>();
        transpose_v_kernel<<<dim3(S_/32, DV_/32, B_*H_), dim3(32, 8)>>>();
    }

    flash_mma_kernel<<<dim3(S_/64, B_*H_), 256, FLASH_SMEM>>>(p_Q, p_K, p_V, p_afl);

    gemm_tc3<1><<<g1(TOK_, HID_), 256, gemm_smem>>>(p_afl, t_wo, p_x2, hidden, TOK_, HID_, H_*DV_);

    rmsnorm2_kernel<<<TOK_, 256>>>(p_x2, w_ln2, p_y, HID_, HID_);

    gemm_tc3<0><<<g1(TOK_, INTER_), 256, gemm_smem>>>(p_y, t_wg, p_g, nullptr, TOK_, INTER_, HID_);
    gemm_tc3<0><<<g1(TOK_, INTER_), 256, gemm_smem>>>(p_y, t_wu, p_u, nullptr, TOK_, INTER_, HID_);

    silu_mul2_kernel<<<(unsigned)(((long long)TOK_*INTER_ + 255) / 256), 256>>>();

    gemm_tc3<1><<<g1(TOK_, HID_), 256, gemm_smem>>>(p_g, t_wd, out, p_x2, TOK_, HID_, INTER_);
}

// round 10
// speedup vs baseline: 12.1654x; 1.1023x over previous
#include <cuda_runtime.h>
#include <math.h>
#include <stdint.h>

#define B_      2
#define S_      2048
#define HID_    2048
#define H_      16
#define DQ_     192
#define DNOPE_  128
#define DROPE_  64
#define DV_     128
#define RANK_   512
#define INTER_  10944
#define TOK_    (B_*S_)

__device__ __forceinline__ float tf32r(float x) {
    float r;
    asm("cvt.rna.tf32.f32 %0, %1;" : "=f"(r) : "f"(x));
    return r;
}

__device__ __forceinline__ void mma_tf32(float* c, const uint32_t* a, const uint32_t* b) {
    asm volatile(
        "mma.sync.aligned.m16n8k8.row.col.f32.tf32.tf32.f32 "
        "{%0,%1,%2,%3}, {%4,%5,%6,%7}, {%8,%9}, {%0,%1,%2,%3};\n"
        : "+f"(c[0]), "+f"(c[1]), "+f"(c[2]), "+f"(c[3])
        : "r"(a[0]), "r"(a[1]), "r"(a[2]), "r"(a[3]), "r"(b[0]), "r"(b[1]));
}

__device__ __forceinline__ void cp_async16(void* smem_dst, const void* gsrc, unsigned bytes) {
    unsigned saddr = (unsigned)__cvta_generic_to_shared(smem_dst);
    asm volatile("cp.async.cg.shared.global [%0], [%1], 16, %2;"
                 :: "r"(saddr), "l"(gsrc), "r"(bytes));
}

// ---------------- device scratch ----------------
__device__ float g_invfreq[32];
__device__ float g_xln    [TOK_*HID_];
__device__ float g_q      [TOK_*H_*DQ_];
__device__ float g_ckv    [TOK_*(RANK_+DROPE_)];
__device__ float g_cln    [TOK_*RANK_];
__device__ float g_kv     [TOK_*H_*(DNOPE_+DV_)];
__device__ float g_Vt     [(size_t)B_*H_*DV_*S_];
__device__ float g_attnfl [TOK_*H_*DV_];
__device__ float g_x2     [TOK_*HID_];
__device__ float g_y      [TOK_*HID_];
__device__ float g_gate   [TOK_*INTER_];
__device__ float g_act    [TOK_*INTER_];
// pre-truncated weights
__device__ float g_tWq   [(size_t)H_*DQ_*HID_];
__device__ float g_tWkva [(size_t)(RANK_+DROPE_)*HID_];
__device__ float g_tWkvb [(size_t)H_*(DNOPE_+DV_)*RANK_];
__device__ float g_tWo   [(size_t)HID_*H_*DV_];
__device__ float g_tWg   [(size_t)INTER_*HID_];
__device__ float g_tWu   [(size_t)INTER_*HID_];
__device__ float g_tWd   [(size_t)HID_*INTER_];

// ---- weight pre-truncation ----
__global__ void trunc_kernel(const float* __restrict__ src, float* __restrict__ dst, long long n4) {
    long long i = (long long)blockIdx.x * blockDim.x + threadIdx.x;
    long long stride = (long long)gridDim.x * blockDim.x;
    for (; i < n4; i += stride) {
        float4 v = ((const float4*)src)[i];
        v.x = tf32r(v.x); v.y = tf32r(v.y); v.z = tf32r(v.z); v.w = tf32r(v.w);
        ((float4*)dst)[i] = v;
    }
}

// ---- yarn inv_freq ----
__global__ void init_invfreq2_kernel() {
    int j = threadIdx.x;
    if (j >= 32) return;
    const double dim = 64.0, base = 10000.0, orig_max = 4096.0;
    const double two_pi = 6.283185307179586476925286766559;
    double cd_fast = dim * log(orig_max / (32.0 * two_pi)) / (2.0 * log(base));
    double cd_slow = dim * log(orig_max / ( 1.0 * two_pi)) / (2.0 * log(base));
    double lowd  = floor(cd_fast); if (lowd < 0.0) lowd = 0.0;
    double highd = ceil(cd_slow);  if (highd > dim - 1.0) highd = dim - 1.0;
    double hid = (lowd == highd) ? highd + 0.001 : highd;
    double ar = (2.0 * (double)j) / dim;
    double freq_extra = 1.0 / pow(base, ar);
    double freq_inter = 1.0 / (40.0 * pow(base, ar));
    double ramp = ((double)j - lowd) / (hid - lowd);
    if (ramp < 0.0) ramp = 0.0;
    if (ramp > 1.0) ramp = 1.0;
    double mask = 1.0 - ramp;
    g_invfreq[j] = (float)(freq_inter * (1.0 - mask) + freq_extra * mask);
}

// ---- RMSNorm (output TF32-truncated: feeds matmuls only) ----
__global__ void rmsnorm2_kernel(const float* __restrict__ x, const float* __restrict__ w,
                                float* __restrict__ out, int dim, int in_stride)
{
    const long long row = blockIdx.x;
    const float* xr = x + row * (long long)in_stride;
    __shared__ float buf[256];
    float partial = 0.f;
    for (int i = threadIdx.x; i < dim; i += 256) { float v = xr[i]; partial += v * v; }
    buf[threadIdx.x] = partial;
    __syncthreads();
    for (int stride = 128; stride > 0; stride >>= 1) {
        if (threadIdx.x < stride) buf[threadIdx.x] += buf[threadIdx.x + stride];
        __syncthreads();
    }
    float scale = rsqrtf(buf[0] / (float)dim + 1e-6f);
    for (int i = threadIdx.x; i < dim; i += 256)
        out[row * (long long)dim + i] = tf32r(xr[i] * scale * w[i]);
}

// ---- GEMM v4: 128x256 tile, 2-stage cp.async, 8 warps each 64x64 ----
// C = A[M,K] @ Bw[N,K]^T. MODE 0: plain  MODE 1: +=R  MODE 2: C=tf32r(silu(R)*acc)
// Operands pre-truncated. M%128==0, K%32==0.
#define GA(st,r,c) sA[((st)*128 + (r))*36 + (c)]
#define GB(st,r,c) sB[((st)*256 + (r))*36 + (c)]
template<int MODE>
__global__ void __launch_bounds__(256, 1) gemm_tc4(
    const float* __restrict__ A, const float* __restrict__ Bw,
    float* __restrict__ C, const float* __restrict__ R,
    int M, int N, int K)
{
    extern __shared__ float smem[];
    float* sA = smem;                     // [2][128][36]
    float* sB = smem + 2*128*36;          // [2][256][36]
    const int m0 = blockIdx.y * 128, n0 = blockIdx.x * 256;
    const int tid = threadIdx.x;
    const int warp = tid >> 5, lane = tid & 31;
    const int wm = (warp >> 2) * 64;      // 2 warp-rows
    const int wn = (warp & 3) * 64;       // 4 warp-cols
    const int lr = lane >> 2;
    const int lc = lane & 3;

    float acc[4][8][4];
    #pragma unroll
    for (int mt = 0; mt < 4; mt++)
        #pragma unroll
        for (int nt = 0; nt < 8; nt++)
            #pragma unroll
            for (int i = 0; i < 4; i++) acc[mt][nt][i] = 0.f;

    const int KT = K >> 5;

    // prefetch stage 0
    {
        #pragma unroll
        for (int i = 0; i < 4; i++) {
            int idx = tid + i * 256;
            int r = idx >> 3, c4 = (idx & 7) * 4;
            cp_async16(&GA(0, r, c4), A + (long long)(m0 + r) * K + c4, 16);
        }
        #pragma unroll
        for (int i = 0; i < 8; i++) {
            int idx = tid + i * 256;
            int r = idx >> 3, c4 = (idx & 7) * 4;
            int gn = n0 + r;
            int gnc = gn < N ? gn : 0;
            cp_async16(&GB(0, r, c4), Bw + (long long)gnc * K + c4, gn < N ? 16u : 0u);
        }
        asm volatile("cp.async.commit_group;");
    }

    for (int kt = 0; kt < KT; kt++) {
        const int st = kt & 1;
        if (kt + 1 < KT) {
            const int k0 = (kt + 1) << 5;
            #pragma unroll
            for (int i = 0; i < 4; i++) {
                int idx = tid + i * 256;
                int r = idx >> 3, c4 = (idx & 7) * 4;
                cp_async16(&GA(st ^ 1, r, c4), A + (long long)(m0 + r) * K + k0 + c4, 16);
            }
            #pragma unroll
            for (int i = 0; i < 8; i++) {
                int idx = tid + i * 256;
                int r = idx >> 3, c4 = (idx & 7) * 4;
                int gn = n0 + r;
                int gnc = gn < N ? gn : 0;
                cp_async16(&GB(st ^ 1, r, c4), Bw + (long long)gnc * K + k0 + c4, gn < N ? 16u : 0u);
            }
            asm volatile("cp.async.commit_group;");
            asm volatile("cp.async.wait_group 1;");
        } else {
            asm volatile("cp.async.wait_group 0;");
        }
        __syncthreads();

        #pragma unroll
        for (int ks = 0; ks < 32; ks += 8) {
            uint32_t af[4][4], bf[8][2];
            #pragma unroll
            for (int mt = 0; mt < 4; mt++) {
                int row = wm + mt * 16 + lr;
                af[mt][0] = __float_as_uint(GA(st, row,     ks + lc));
                af[mt][1] = __float_as_uint(GA(st, row + 8, ks + lc));
                af[mt][2] = __float_as_uint(GA(st, row,     ks + lc + 4));
                af[mt][3] = __float_as_uint(GA(st, row + 8, ks + lc + 4));
            }
            #pragma unroll
            for (int nt = 0; nt < 8; nt++) {
                int col = wn + nt * 8 + lr;
                bf[nt][0] = __float_as_uint(GB(st, col, ks + lc));
                bf[nt][1] = __float_as_uint(GB(st, col, ks + lc + 4));
            }
            #pragma unroll
            for (int mt = 0; mt < 4; mt++)
                #pragma unroll
                for (int nt = 0; nt < 8; nt++)
                    mma_tf32(acc[mt][nt], af[mt], bf[nt]);
        }
        __syncthreads();
    }

    #pragma unroll
    for (int mt = 0; mt < 4; mt++) {
        #pragma unroll
        for (int nt = 0; nt < 8; nt++) {
            int mmb = m0 + wm + mt * 16 + lr;
            int nn = n0 + wn + nt * 8 + lc * 2;
            #pragma unroll
            for (int half = 0; half < 2; half++) {
                int mrow = mmb + half * 8;
                #pragma unroll
                for (int q = 0; q < 2; q++) {
                    int nc = nn + q;
                    if (nc >= N) continue;
                    float v = acc[mt][nt][half * 2 + q];
                    long long off = (long long)mrow * N + nc;
                    if (MODE == 1) v += R[off];
                    if (MODE == 2) {
                        float g = R[off];
                        float sig = 1.f / (1.f + expf(-g));
                        v = tf32r(g * sig * v);
                    }
                    C[off] = v;
                }
            }
        }
    }
}

// ---- RoPE in place (register-buffered) ----
__global__ void rope_q_kernel(const int* __restrict__ pos_ids) {
    int idx = blockIdx.x * 256 + threadIdx.x;
    if (idx >= TOK_ * H_) return;
    int tok = idx / H_;
    float* x = g_q + (long long)idx * DQ_ + DNOPE_;
    float pos = (float)pos_ids[tok];
    float xv[64];
    #pragma unroll
    for (int i = 0; i < 64; i++) xv[i] = x[i];
    #pragma unroll
    for (int j = 0; j < 32; j++) {
        float th = pos * g_invfreq[j];
        float c = cosf(th), sn = sinf(th);
        float x1 = xv[2*j], x2 = xv[2*j+1];
        x[j]      = x1 * c - x2 * sn;
        x[j + 32] = x2 * c + x1 * sn;
    }
}

__global__ void rope_k_kernel(const int* __restrict__ pos_ids) {
    int tok = blockIdx.x * 256 + threadIdx.x;
    if (tok >= TOK_) return;
    float* x = g_ckv + (long long)tok * (RANK_ + DROPE_) + RANK_;
    float pos = (float)pos_ids[tok];
    float xv[64];
    #pragma unroll
    for (int i = 0; i < 64; i++) xv[i] = x[i];
    #pragma unroll
    for (int j = 0; j < 32; j++) {
        float th = pos * g_invfreq[j];
        float c = cosf(th), sn = sinf(th);
        float x1 = xv[2*j], x2 = xv[2*j+1];
        x[j]      = x1 * c - x2 * sn;
        x[j + 32] = x2 * c + x1 * sn;
    }
}

// ---- V transpose: g_kv [tok][h][128+d] -> g_Vt [z][d][s] (TF32-truncated) ----
__global__ void transpose_v_kernel() {
    __shared__ float t[32][33];
    int z = blockIdx.z;
    int d0 = blockIdx.y * 32, s0 = blockIdx.x * 32;
    int b = z >> 4, h = z & 15;
    int tx = threadIdx.x, ty0 = threadIdx.y;
    #pragma unroll
    for (int dy = 0; dy < 32; dy += 8) {
        int ty = ty0 + dy;
        t[ty][tx] = g_kv[(((long long)b * S_ + s0 + ty) * H_ + h) * (DNOPE_ + DV_) + DNOPE_ + d0 + tx];
    }
    __syncthreads();
    #pragma unroll
    for (int dy = 0; dy < 32; dy += 8) {
        int ty = ty0 + dy;
        g_Vt[((long long)z * DV_ + d0 + ty) * S_ + s0 + tx] = tf32r(t[tx][ty]);
    }
}

// ---- tensor-core flash attention, direct-read Q/K (causal, online softmax) ----
#define FQ_STR 196
#define FS_STR 68
#define FV_STR 68
#define FLASH_SMEM ((2*64*FQ_STR + 128*FV_STR + 64*FS_STR + 192) * 4)

__global__ void __launch_bounds__(256) flash_mma_kernel(float* __restrict__ outfl)
{
    extern __shared__ float sm[];
    float* Qs = sm;                        // 64 x 196
    float* Ks = Qs + 64*FQ_STR;            // 64 x 196
    float* Vs = Ks + 64*FQ_STR;            // 128 x 68
    float* Ss = Vs + 128*FV_STR;           // 64 x 68
    float* m_s = Ss + 64*FS_STR;
    float* l_s = m_s + 64;
    float* a_s = l_s + 64;

    const int z = blockIdx.y;
    const int b = z >> 4, h = z & 15;
    const int q0 = blockIdx.x * 64;
    const int tid = threadIdx.x;
    const int warp = tid >> 5, lane = tid & 31;
    const int lr = lane >> 2, lc = lane & 3;
    const int wm = (warp & 3) * 16;
    const int wn_qk = (warp >> 2) * 32;
    const int wn_pv = (warp >> 2) * 64;

    const float scale = 0.07216878364870323f; // 192^-0.5
    const float* Vg = g_Vt + (long long)z * DV_ * S_;

    // Q tile direct from g_q (rope already applied in place)
    for (int i = tid; i < 64 * 48; i += 256) {
        int r = i / 48, c4 = (i % 48) * 4;
        float4 v = *(const float4*)(g_q + (((long long)b * S_ + q0 + r) * H_ + h) * DQ_ + c4);
        Qs[r*FQ_STR + c4+0] = tf32r(v.x); Qs[r*FQ_STR + c4+1] = tf32r(v.y);
        Qs[r*FQ_STR + c4+2] = tf32r(v.z); Qs[r*FQ_STR + c4+3] = tf32r(v.w);
    }
    if (tid < 64) { m_s[tid] = -1e30f; l_s[tid] = 0.f; }

    float oacc[8][4];
    #pragma unroll
    for (int nt = 0; nt < 8; nt++)
        #pragma unroll
        for (int i = 0; i < 4; i++) oacc[nt][i] = 0.f;

    for (int t = 0; t <= blockIdx.x; t++) {
        const int k0 = t * 64;
        __syncthreads();
        // K tile: nope from g_kv, rope from g_ckv (roped in place)
        for (int i = tid; i < 64 * 48; i += 256) {
            int r = i / 48, c4 = (i % 48) * 4;
            long long tok = (long long)b * S_ + k0 + r;
            float4 v;
            if (c4 < DNOPE_)
                v = *(const float4*)(g_kv + (tok * H_ + h) * (DNOPE_ + DV_) + c4);
            else
                v = *(const float4*)(g_ckv + tok * (RANK_ + DROPE_) + RANK_ + (c4 - DNOPE_));
            Ks[r*FQ_STR + c4+0] = tf32r(v.x); Ks[r*FQ_STR + c4+1] = tf32r(v.y);
            Ks[r*FQ_STR + c4+2] = tf32r(v.z); Ks[r*FQ_STR + c4+3] = tf32r(v.w);
        }
        for (int i = tid; i < 128 * 16; i += 256) {
            int r = i >> 4, c4 = (i & 15) * 4;
            *(float4*)(Vs + r * FV_STR + c4) = *(const float4*)(Vg + (long long)r * S_ + k0 + c4);
        }
        __syncthreads();

        // QK^T : 16 rows x 32 cols per warp
        float sc[4][4];
        #pragma unroll
        for (int nt = 0; nt < 4; nt++)
            #pragma unroll
            for (int i = 0; i < 4; i++) sc[nt][i] = 0.f;
        #pragma unroll
        for (int ks = 0; ks < DQ_; ks += 8) {
            uint32_t af[4], bf[4][2];
            af[0] = __float_as_uint(Qs[(wm + lr    ) * FQ_STR + ks + lc]);
            af[1] = __float_as_uint(Qs[(wm + lr + 8) * FQ_STR + ks + lc]);
            af[2] = __float_as_uint(Qs[(wm + lr    ) * FQ_STR + ks + lc + 4]);
            af[3] = __float_as_uint(Qs[(wm + lr + 8) * FQ_STR + ks + lc + 4]);
            #pragma unroll
            for (int nt = 0; nt < 4; nt++) {
                int col = wn_qk + nt * 8 + lr;
                bf[nt][0] = __float_as_uint(Ks[col * FQ_STR + ks + lc]);
                bf[nt][1] = __float_as_uint(Ks[col * FQ_STR + ks + lc + 4]);
            }
            #pragma unroll
            for (int nt = 0; nt < 4; nt++)
                mma_tf32(sc[nt], af, bf[nt]);
        }
        #pragma unroll
        for (int nt = 0; nt < 4; nt++) {
            int c = wn_qk + nt * 8 + lc * 2;
            int r0 = wm + lr, r1 = wm + lr + 8;
            float v00 = sc[nt][0] * scale, v01 = sc[nt][1] * scale;
            float v10 = sc[nt][2] * scale, v11 = sc[nt][3] * scale;
            if (k0 + c     > q0 + r0) v00 = -1e30f;
            if (k0 + c + 1 > q0 + r0) v01 = -1e30f;
            if (k0 + c     > q0 + r1) v10 = -1e30f;
            if (k0 + c + 1 > q0 + r1) v11 = -1e30f;
            *(float2*)(Ss + r0 * FS_STR + c) = make_float2(v00, v01);
            *(float2*)(Ss + r1 * FS_STR + c) = make_float2(v10, v11);
        }
        __syncthreads();

        // online softmax: 4 threads per row
        {
            int r = tid >> 2, p4 = tid & 3;
            int cb = p4 * 16;
            float mx = -1e30f;
            #pragma unroll
            for (int j = 0; j < 16; j++) mx = fmaxf(mx, Ss[r * FS_STR + cb + j]);
            mx = fmaxf(mx, __shfl_xor_sync(0xffffffffu, mx, 1));
            mx = fmaxf(mx, __shfl_xor_sync(0xffffffffu, mx, 2));
            float m_old = m_s[r];
            float m_new = fmaxf(m_old, mx);
            float alpha = __expf(m_old - m_new);
            float es = 0.f;
            #pragma unroll
            for (int j = 0; j < 16; j++) {
                float e = __expf(Ss[r * FS_STR + cb + j] - m_new);
                Ss[r * FS_STR + cb + j] = tf32r(e);
                es += e;
            }
            es += __shfl_xor_sync(0xffffffffu, es, 1);
            es += __shfl_xor_sync(0xffffffffu, es, 2);
            if (p4 == 0) {
                l_s[r] = l_s[r] * alpha + es;
                m_s[r] = m_new;
                a_s[r] = alpha;
            }
        }
        __syncthreads();

        // PV
        {
            float a0 = a_s[wm + lr], a1 = a_s[wm + lr + 8];
            #pragma unroll
            for (int nt = 0; nt < 8; nt++) {
                oacc[nt][0] *= a0; oacc[nt][1] *= a0;
                oacc[nt][2] *= a1; oacc[nt][3] *= a1;
            }
            #pragma unroll
            for (int ks = 0; ks < 64; ks += 8) {
                uint32_t af[4], bf[8][2];
                af[0] = __float_as_uint(Ss[(wm + lr    ) * FS_STR + ks + lc]);
                af[1] = __float_as_uint(Ss[(wm + lr + 8) * FS_STR + ks + lc]);
                af[2] = __float_as_uint(Ss[(wm + lr    ) * FS_STR + ks + lc + 4]);
                af[3] = __float_as_uint(Ss[(wm + lr + 8) * FS_STR + ks + lc + 4]);
                #pragma unroll
                for (int nt = 0; nt < 8; nt++) {
                    int col = wn_pv + nt * 8 + lr;
                    bf[nt][0] = __float_as_uint(Vs[col * FV_STR + ks + lc]);
                    bf[nt][1] = __float_as_uint(Vs[col * FV_STR + ks + lc + 4]);
                }
                #pragma unroll
                for (int nt = 0; nt < 8; nt++)
                    mma_tf32(oacc[nt], af, bf[nt]);
            }
        }
    }
    __syncthreads();

    {
        float il0 = 1.f / l_s[wm + lr];
        float il1 = 1.f / l_s[wm + lr + 8];
        long long tok0 = (long long)b * S_ + q0 + wm + lr;
        long long tok1 = tok0 + 8;
        #pragma unroll
        for (int nt = 0; nt < 8; nt++) {
            int c = wn_pv + nt * 8 + lc * 2;
            *(float2*)(outfl + tok0 * (H_*DV_) + h * DV_ + c) =
                make_float2(tf32r(oacc[nt][0] * il0), tf32r(oacc[nt][1] * il0));
            *(float2*)(outfl + tok1 * (H_*DV_) + h * DV_ + c) =
                make_float2(tf32r(oacc[nt][2] * il1), tf32r(oacc[nt][3] * il1));
        }
    }
}

static inline dim3 g4(int M, int N) { return dim3((N + 255) / 256, M / 128, 1); }

extern "C" void kernel_launch(void* const* d_in, const int* in_sizes, int n_in,
                              void* d_out, int out_size)
{
    const float* hidden = (const float*)d_in[0];
    const int*   pos    = (const int*)  d_in[1];
    const float* Wq     = (const float*)d_in[2];
    const float* Wkva   = (const float*)d_in[3];
    const float* w_kvln = (const float*)d_in[4];
    const float* Wkvb   = (const float*)d_in[5];
    const float* Wo     = (const float*)d_in[6];
    const float* Wg     = (const float*)d_in[7];
    const float* Wu     = (const float*)d_in[8];
    const float* Wd     = (const float*)d_in[9];
    const float* w_ln1  = (const float*)d_in[10];
    const float* w_ln2  = (const float*)d_in[11];
    float* out = (float*)d_out;

    float *p_xln, *p_q, *p_ckv, *p_cln, *p_kv, *p_afl, *p_x2, *p_y, *p_g, *p_a;
    float *t_wq, *t_wkva, *t_wkvb, *t_wo, *t_wg, *t_wu, *t_wd;
    cudaGetSymbolAddress((void**)&p_xln, g_xln);
    cudaGetSymbolAddress((void**)&p_q,   g_q);
    cudaGetSymbolAddress((void**)&p_ckv, g_ckv);
    cudaGetSymbolAddress((void**)&p_cln, g_cln);
    cudaGetSymbolAddress((void**)&p_kv,  g_kv);
    cudaGetSymbolAddress((void**)&p_afl, g_attnfl);
    cudaGetSymbolAddress((void**)&p_x2,  g_x2);
    cudaGetSymbolAddress((void**)&p_y,   g_y);
    cudaGetSymbolAddress((void**)&p_g,   g_gate);
    cudaGetSymbolAddress((void**)&p_a,   g_act);
    cudaGetSymbolAddress((void**)&t_wq,   g_tWq);
    cudaGetSymbolAddress((void**)&t_wkva, g_tWkva);
    cudaGetSymbolAddress((void**)&t_wkvb, g_tWkvb);
    cudaGetSymbolAddress((void**)&t_wo,   g_tWo);
    cudaGetSymbolAddress((void**)&t_wg,   g_tWg);
    cudaGetSymbolAddress((void**)&t_wu,   g_tWu);
    cudaGetSymbolAddress((void**)&t_wd,   g_tWd);

    const int gemm_smem = (2*128*36 + 2*256*36) * 4;   // 110592
    cudaFuncSetAttribute(gemm_tc4<0>, cudaFuncAttributeMaxDynamicSharedMemorySize, gemm_smem);
    cudaFuncSetAttribute(gemm_tc4<1>, cudaFuncAttributeMaxDynamicSharedMemorySize, gemm_smem);
    cudaFuncSetAttribute(gemm_tc4<2>, cudaFuncAttributeMaxDynamicSharedMemorySize, gemm_smem);
    cudaFuncSetAttribute(flash_mma_kernel, cudaFuncAttributeMaxDynamicSharedMemorySize, FLASH_SMEM);

    init_invfreq2_kernel<<<1, 32>>>();

    trunc_kernel<<<1184, 256>>>(Wq,   t_wq,   (long long)H_*DQ_*HID_/4);
    trunc_kernel<<<1184, 256>>>(Wkva, t_wkva, (long long)(RANK_+DROPE_)*HID_/4);
    trunc_kernel<<<1184, 256>>>(Wkvb, t_wkvb, (long long)H_*(DNOPE_+DV_)*RANK_/4);
    trunc_kernel<<<1184, 256>>>(Wo,   t_wo,   (long long)HID_*H_*DV_/4);
    trunc_kernel<<<1184, 256>>>(Wg,   t_wg,   (long long)INTER_*HID_/4);
    trunc_kernel<<<1184, 256>>>(Wu,   t_wu,   (long long)INTER_*HID_/4);
    trunc_kernel<<<1184, 256>>>(Wd,   t_wd,   (long long)HID_*INTER_/4);

    rmsnorm2_kernel<<<TOK_, 256>>>(hidden, w_ln1, p_xln, HID_, HID_);

    gemm_tc4<0><<<g4(TOK_, H_*DQ_), 256, gemm_smem>>>(p_xln, t_wq, p_q, nullptr, TOK_, H_*DQ_, HID_);
    gemm_tc4<0><<<g4(TOK_, RANK_+DROPE_), 256, gemm_smem>>>(p_xln, t_wkva, p_ckv, nullptr, TOK_, RANK_+DROPE_, HID_);

    rmsnorm2_kernel<<<TOK_, 256>>>(p_ckv, w_kvln, p_cln, RANK_, RANK_+DROPE_);

    gemm_tc4<0><<<g4(TOK_, H_*(DNOPE_+DV_)), 256, gemm_smem>>>(p_cln, t_wkvb, p_kv, nullptr, TOK_, H_*(DNOPE_+DV_), RANK_);

    rope_q_kernel<<<(TOK_*H_ + 255)/256, 256>>>(pos);
    rope_k_kernel<<<(TOK_ + 255)/256, 256>>>(pos);
    transpose_v_kernel<<<dim3(S_/32, DV_/32, B_*H_), dim3(32, 8)>>>();

    flash_mma_kernel<<<dim3(S_/64, B_*H_), 256, FLASH_SMEM>>>(p_afl);

    gemm_tc4<1><<<g4(TOK_, HID_), 256, gemm_smem>>>(p_afl, t_wo, p_x2, hidden, TOK_, HID_, H_*DV_);

    rmsnorm2_kernel<<<TOK_, 256>>>(p_x2, w_ln2, p_y, HID_, HID_);

    gemm_tc4<0><<<g4(TOK_, INTER_), 256, gemm_smem>>>(p_y, t_wg, p_g, nullptr, TOK_, INTER_, HID_);
    // up GEMM fused with silu(gate)*up epilogue -> g_act
    gemm_tc4<2><<<g4(TOK_, INTER_), 256, gemm_smem>>>(p_y, t_wu, p_a, p_g, TOK_, INTER_, HID_);

    gemm_tc4<1><<<g4(TOK_, HID_), 256, gemm_smem>>>(p_a, t_wd, out, p_x2, TOK_, HID_, INTER_);
}

// round 11
// speedup vs baseline: 12.2385x; 1.0060x over previous
#include <cuda_runtime.h>
#include <math.h>
#include <stdint.h>

#define B_      2
#define S_      2048
#define HID_    2048
#define H_      16
#define DQ_     192
#define DNOPE_  128
#define DROPE_  64
#define DV_     128
#define RANK_   512
#define INTER_  10944
#define TOK_    (B_*S_)

__device__ __forceinline__ float tf32r(float x) {
    float r;
    asm("cvt.rna.tf32.f32 %0, %1;" : "=f"(r) : "f"(x));
    return r;
}

__device__ __forceinline__ void mma_tf32(float* c, const uint32_t* a, const uint32_t* b) {
    asm volatile(
        "mma.sync.aligned.m16n8k8.row.col.f32.tf32.tf32.f32 "
        "{%0,%1,%2,%3}, {%4,%5,%6,%7}, {%8,%9}, {%0,%1,%2,%3};\n"
        : "+f"(c[0]), "+f"(c[1]), "+f"(c[2]), "+f"(c[3])
        : "r"(a[0]), "r"(a[1]), "r"(a[2]), "r"(a[3]), "r"(b[0]), "r"(b[1]));
}

__device__ __forceinline__ void cp_async16(void* smem_dst, const void* gsrc, unsigned bytes) {
    unsigned saddr = (unsigned)__cvta_generic_to_shared(smem_dst);
    asm volatile("cp.async.cg.shared.global [%0], [%1], 16, %2;"
                 :: "r"(saddr), "l"(gsrc), "r"(bytes));
}

// ---------------- device scratch ----------------
__device__ float g_invfreq[32];
__device__ float g_xln    [TOK_*HID_];
__device__ float g_q      [TOK_*H_*DQ_];
__device__ float g_ckv    [TOK_*(RANK_+DROPE_)];
__device__ float g_cln    [TOK_*RANK_];
__device__ float g_kv     [TOK_*H_*(DNOPE_+DV_)];
__device__ float g_Vt     [(size_t)B_*H_*DV_*S_];
__device__ float g_attnfl [TOK_*H_*DV_];
__device__ float g_x2     [TOK_*HID_];
__device__ float g_y      [TOK_*HID_];
__device__ float g_gate   [TOK_*INTER_];
__device__ float g_act    [TOK_*INTER_];
// pre-truncated weights
__device__ float g_tWq   [(size_t)H_*DQ_*HID_];
__device__ float g_tWkva [(size_t)(RANK_+DROPE_)*HID_];
__device__ float g_tWkvb [(size_t)H_*(DNOPE_+DV_)*RANK_];
__device__ float g_tWo   [(size_t)HID_*H_*DV_];
__device__ float g_tWg   [(size_t)INTER_*HID_];
__device__ float g_tWu   [(size_t)INTER_*HID_];
__device__ float g_tWd   [(size_t)HID_*INTER_];

// ---- weight pre-truncation ----
__global__ void trunc_kernel(const float* __restrict__ src, float* __restrict__ dst, long long n4) {
    long long i = (long long)blockIdx.x * blockDim.x + threadIdx.x;
    long long stride = (long long)gridDim.x * blockDim.x;
    for (; i < n4; i += stride) {
        float4 v = ((const float4*)src)[i];
        v.x = tf32r(v.x); v.y = tf32r(v.y); v.z = tf32r(v.z); v.w = tf32r(v.w);
        ((float4*)dst)[i] = v;
    }
}

// ---- yarn inv_freq ----
__global__ void init_invfreq2_kernel() {
    int j = threadIdx.x;
    if (j >= 32) return;
    const double dim = 64.0, base = 10000.0, orig_max = 4096.0;
    const double two_pi = 6.283185307179586476925286766559;
    double cd_fast = dim * log(orig_max / (32.0 * two_pi)) / (2.0 * log(base));
    double cd_slow = dim * log(orig_max / ( 1.0 * two_pi)) / (2.0 * log(base));
    double lowd  = floor(cd_fast); if (lowd < 0.0) lowd = 0.0;
    double highd = ceil(cd_slow);  if (highd > dim - 1.0) highd = dim - 1.0;
    double hid = (lowd == highd) ? highd + 0.001 : highd;
    double ar = (2.0 * (double)j) / dim;
    double freq_extra = 1.0 / pow(base, ar);
    double freq_inter = 1.0 / (40.0 * pow(base, ar));
    double ramp = ((double)j - lowd) / (hid - lowd);
    if (ramp < 0.0) ramp = 0.0;
    if (ramp > 1.0) ramp = 1.0;
    double mask = 1.0 - ramp;
    g_invfreq[j] = (float)(freq_inter * (1.0 - mask) + freq_extra * mask);
}

// ---- RMSNorm (output TF32-truncated: feeds matmuls only) ----
__global__ void rmsnorm2_kernel(const float* __restrict__ x, const float* __restrict__ w,
                                float* __restrict__ out, int dim, int in_stride)
{
    const long long row = blockIdx.x;
    const float* xr = x + row * (long long)in_stride;
    __shared__ float buf[256];
    float partial = 0.f;
    for (int i = threadIdx.x; i < dim; i += 256) { float v = xr[i]; partial += v * v; }
    buf[threadIdx.x] = partial;
    __syncthreads();
    for (int stride = 128; stride > 0; stride >>= 1) {
        if (threadIdx.x < stride) buf[threadIdx.x] += buf[threadIdx.x + stride];
        __syncthreads();
    }
    float scale = rsqrtf(buf[0] / (float)dim + 1e-6f);
    for (int i = threadIdx.x; i < dim; i += 256)
        out[row * (long long)dim + i] = tf32r(xr[i] * scale * w[i]);
}

// ---- GEMM v5: 128x256 tile, 3-stage cp.async, 8 warps each 64x64 ----
// C = A[M,K] @ Bw[N,K]^T. MODE 0: plain  MODE 1: +=R  MODE 2: C=tf32r(silu(R)*acc)
// Operands pre-truncated. M%128==0, K%32==0.
#define GSTAGES 3
#define GA(st,r,c) sA[((st)*128 + (r))*36 + (c)]
#define GB(st,r,c) sB[((st)*256 + (r))*36 + (c)]
template<int MODE>
__global__ void __launch_bounds__(256, 1) gemm_tc5(
    const float* __restrict__ A, const float* __restrict__ Bw,
    float* __restrict__ C, const float* __restrict__ R,
    int M, int N, int K)
{
    extern __shared__ float smem[];
    float* sA = smem;                          // [3][128][36]
    float* sB = smem + GSTAGES*128*36;         // [3][256][36]
    const int m0 = blockIdx.y * 128, n0 = blockIdx.x * 256;
    const int tid = threadIdx.x;
    const int warp = tid >> 5, lane = tid & 31;
    const int wm = (warp >> 2) * 64;
    const int wn = (warp & 3) * 64;
    const int lr = lane >> 2;
    const int lc = lane & 3;

    float acc[4][8][4];
    #pragma unroll
    for (int mt = 0; mt < 4; mt++)
        #pragma unroll
        for (int nt = 0; nt < 8; nt++)
            #pragma unroll
            for (int i = 0; i < 4; i++) acc[mt][nt][i] = 0.f;

    const int KT = K >> 5;

    // prefetch stages 0 and 1
    #pragma unroll
    for (int ps = 0; ps < 2; ps++) {
        const int k0 = ps << 5;
        #pragma unroll
        for (int i = 0; i < 4; i++) {
            int idx = tid + i * 256;
            int r = idx >> 3, c4 = (idx & 7) * 4;
            cp_async16(&GA(ps, r, c4), A + (long long)(m0 + r) * K + k0 + c4, 16);
        }
        #pragma unroll
        for (int i = 0; i < 8; i++) {
            int idx = tid + i * 256;
            int r = idx >> 3, c4 = (idx & 7) * 4;
            int gn = n0 + r;
            int gnc = gn < N ? gn : 0;
            cp_async16(&GB(ps, r, c4), Bw + (long long)gnc * K + k0 + c4, gn < N ? 16u : 0u);
        }
        asm volatile("cp.async.commit_group;");
    }

    int st = 0;        // compute slot
    int sl = 2;        // prefetch slot (for kt+2)
    for (int kt = 0; kt < KT; kt++) {
        if (kt + 2 < KT) {
            const int k0 = (kt + 2) << 5;
            #pragma unroll
            for (int i = 0; i < 4; i++) {
                int idx = tid + i * 256;
                int r = idx >> 3, c4 = (idx & 7) * 4;
                cp_async16(&GA(sl, r, c4), A + (long long)(m0 + r) * K + k0 + c4, 16);
            }
            #pragma unroll
            for (int i = 0; i < 8; i++) {
                int idx = tid + i * 256;
                int r = idx >> 3, c4 = (idx & 7) * 4;
                int gn = n0 + r;
                int gnc = gn < N ? gn : 0;
                cp_async16(&GB(sl, r, c4), Bw + (long long)gnc * K + k0 + c4, gn < N ? 16u : 0u);
            }
            asm volatile("cp.async.commit_group;");
            asm volatile("cp.async.wait_group 2;");
        } else if (kt + 1 < KT) {
            asm volatile("cp.async.wait_group 1;");
        } else {
            asm volatile("cp.async.wait_group 0;");
        }
        __syncthreads();

        #pragma unroll
        for (int ks = 0; ks < 32; ks += 8) {
            uint32_t af[4][4], bf[8][2];
            #pragma unroll
            for (int mt = 0; mt < 4; mt++) {
                int row = wm + mt * 16 + lr;
                af[mt][0] = __float_as_uint(GA(st, row,     ks + lc));
                af[mt][1] = __float_as_uint(GA(st, row + 8, ks + lc));
                af[mt][2] = __float_as_uint(GA(st, row,     ks + lc + 4));
                af[mt][3] = __float_as_uint(GA(st, row + 8, ks + lc + 4));
            }
            #pragma unroll
            for (int nt = 0; nt < 8; nt++) {
                int col = wn + nt * 8 + lr;
                bf[nt][0] = __float_as_uint(GB(st, col, ks + lc));
                bf[nt][1] = __float_as_uint(GB(st, col, ks + lc + 4));
            }
            #pragma unroll
            for (int mt = 0; mt < 4; mt++)
                #pragma unroll
                for (int nt = 0; nt < 8; nt++)
                    mma_tf32(acc[mt][nt], af[mt], bf[nt]);
        }
        __syncthreads();
        st = (st + 1 == GSTAGES) ? 0 : st + 1;
        sl = (sl + 1 == GSTAGES) ? 0 : sl + 1;
    }

    #pragma unroll
    for (int mt = 0; mt < 4; mt++) {
        #pragma unroll
        for (int nt = 0; nt < 8; nt++) {
            int mmb = m0 + wm + mt * 16 + lr;
            int nn = n0 + wn + nt * 8 + lc * 2;
            #pragma unroll
            for (int half = 0; half < 2; half++) {
                int mrow = mmb + half * 8;
                #pragma unroll
                for (int q = 0; q < 2; q++) {
                    int nc = nn + q;
                    if (nc >= N) continue;
                    float v = acc[mt][nt][half * 2 + q];
                    long long off = (long long)mrow * N + nc;
                    if (MODE == 1) v += R[off];
                    if (MODE == 2) {
                        float g = R[off];
                        float sig = 1.f / (1.f + expf(-g));
                        v = tf32r(g * sig * v);
                    }
                    C[off] = v;
                }
            }
        }
    }
}

// ---- RoPE in place (register-buffered) ----
__global__ void rope_q_kernel(const int* __restrict__ pos_ids) {
    int idx = blockIdx.x * 256 + threadIdx.x;
    if (idx >= TOK_ * H_) return;
    int tok = idx / H_;
    float* x = g_q + (long long)idx * DQ_ + DNOPE_;
    float pos = (float)pos_ids[tok];
    float xv[64];
    #pragma unroll
    for (int i = 0; i < 64; i++) xv[i] = x[i];
    #pragma unroll
    for (int j = 0; j < 32; j++) {
        float th = pos * g_invfreq[j];
        float c = cosf(th), sn = sinf(th);
        float x1 = xv[2*j], x2 = xv[2*j+1];
        x[j]      = x1 * c - x2 * sn;
        x[j + 32] = x2 * c + x1 * sn;
    }
}

__global__ void rope_k_kernel(const int* __restrict__ pos_ids) {
    int tok = blockIdx.x * 256 + threadIdx.x;
    if (tok >= TOK_) return;
    float* x = g_ckv + (long long)tok * (RANK_ + DROPE_) + RANK_;
    float pos = (float)pos_ids[tok];
    float xv[64];
    #pragma unroll
    for (int i = 0; i < 64; i++) xv[i] = x[i];
    #pragma unroll
    for (int j = 0; j < 32; j++) {
        float th = pos * g_invfreq[j];
        float c = cosf(th), sn = sinf(th);
        float x1 = xv[2*j], x2 = xv[2*j+1];
        x[j]      = x1 * c - x2 * sn;
        x[j + 32] = x2 * c + x1 * sn;
    }
}

// ---- V transpose: g_kv [tok][h][128+d] -> g_Vt [z][d][s] (TF32-truncated) ----
__global__ void transpose_v_kernel() {
    __shared__ float t[32][33];
    int z = blockIdx.z;
    int d0 = blockIdx.y * 32, s0 = blockIdx.x * 32;
    int b = z >> 4, h = z & 15;
    int tx = threadIdx.x, ty0 = threadIdx.y;
    #pragma unroll
    for (int dy = 0; dy < 32; dy += 8) {
        int ty = ty0 + dy;
        t[ty][tx] = g_kv[(((long long)b * S_ + s0 + ty) * H_ + h) * (DNOPE_ + DV_) + DNOPE_ + d0 + tx];
    }
    __syncthreads();
    #pragma unroll
    for (int dy = 0; dy < 32; dy += 8) {
        int ty = ty0 + dy;
        g_Vt[((long long)z * DV_ + d0 + ty) * S_ + s0 + tx] = tf32r(t[tx][ty]);
    }
}

// ---- tensor-core flash attention, direct-read Q/K (causal, online softmax) ----
#define FQ_STR 196
#define FS_STR 68
#define FV_STR 68
#define FLASH_SMEM ((2*64*FQ_STR + 128*FV_STR + 64*FS_STR + 192) * 4)

__global__ void __launch_bounds__(256) flash_mma_kernel(float* __restrict__ outfl)
{
    extern __shared__ float sm[];
    float* Qs = sm;                        // 64 x 196
    float* Ks = Qs + 64*FQ_STR;            // 64 x 196
    float* Vs = Ks + 64*FQ_STR;            // 128 x 68
    float* Ss = Vs + 128*FV_STR;           // 64 x 68
    float* m_s = Ss + 64*FS_STR;
    float* l_s = m_s + 64;
    float* a_s = l_s + 64;

    const int z = blockIdx.y;
    const int b = z >> 4, h = z & 15;
    const int q0 = blockIdx.x * 64;
    const int tid = threadIdx.x;
    const int warp = tid >> 5, lane = tid & 31;
    const int lr = lane >> 2, lc = lane & 3;
    const int wm = (warp & 3) * 16;
    const int wn_qk = (warp >> 2) * 32;
    const int wn_pv = (warp >> 2) * 64;

    const float scale = 0.07216878364870323f; // 192^-0.5
    const float* Vg = g_Vt + (long long)z * DV_ * S_;

    for (int i = tid; i < 64 * 48; i += 256) {
        int r = i / 48, c4 = (i % 48) * 4;
        float4 v = *(const float4*)(g_q + (((long long)b * S_ + q0 + r) * H_ + h) * DQ_ + c4);
        Qs[r*FQ_STR + c4+0] = tf32r(v.x); Qs[r*FQ_STR + c4+1] = tf32r(v.y);
        Qs[r*FQ_STR + c4+2] = tf32r(v.z); Qs[r*FQ_STR + c4+3] = tf32r(v.w);
    }
    if (tid < 64) { m_s[tid] = -1e30f; l_s[tid] = 0.f; }

    float oacc[8][4];
    #pragma unroll
    for (int nt = 0; nt < 8; nt++)
        #pragma unroll
        for (int i = 0; i < 4; i++) oacc[nt][i] = 0.f;

    for (int t = 0; t <= blockIdx.x; t++) {
        const int k0 = t * 64;
        __syncthreads();
        for (int i = tid; i < 64 * 48; i += 256) {
            int r = i / 48, c4 = (i % 48) * 4;
            long long tok = (long long)b * S_ + k0 + r;
            float4 v;
            if (c4 < DNOPE_)
                v = *(const float4*)(g_kv + (tok * H_ + h) * (DNOPE_ + DV_) + c4);
            else
                v = *(const float4*)(g_ckv + tok * (RANK_ + DROPE_) + RANK_ + (c4 - DNOPE_));
            Ks[r*FQ_STR + c4+0] = tf32r(v.x); Ks[r*FQ_STR + c4+1] = tf32r(v.y);
            Ks[r*FQ_STR + c4+2] = tf32r(v.z); Ks[r*FQ_STR + c4+3] = tf32r(v.w);
        }
        for (int i = tid; i < 128 * 16; i += 256) {
            int r = i >> 4, c4 = (i & 15) * 4;
            *(float4*)(Vs + r * FV_STR + c4) = *(const float4*)(Vg + (long long)r * S_ + k0 + c4);
        }
        __syncthreads();

        float sc[4][4];
        #pragma unroll
        for (int nt = 0; nt < 4; nt++)
            #pragma unroll
            for (int i = 0; i < 4; i++) sc[nt][i] = 0.f;
        #pragma unroll
        for (int ks = 0; ks < DQ_; ks += 8) {
            uint32_t af[4], bf[4][2];
            af[0] = __float_as_uint(Qs[(wm + lr    ) * FQ_STR + ks + lc]);
            af[1] = __float_as_uint(Qs[(wm + lr + 8) * FQ_STR + ks + lc]);
            af[2] = __float_as_uint(Qs[(wm + lr    ) * FQ_STR + ks + lc + 4]);
            af[3] = __float_as_uint(Qs[(wm + lr + 8) * FQ_STR + ks + lc + 4]);
            #pragma unroll
            for (int nt = 0; nt < 4; nt++) {
                int col = wn_qk + nt * 8 + lr;
                bf[nt][0] = __float_as_uint(Ks[col * FQ_STR + ks + lc]);
                bf[nt][1] = __float_as_uint(Ks[col * FQ_STR + ks + lc + 4]);
            }
            #pragma unroll
            for (int nt = 0; nt < 4; nt++)
                mma_tf32(sc[nt], af, bf[nt]);
        }
        #pragma unroll
        for (int nt = 0; nt < 4; nt++) {
            int c = wn_qk + nt * 8 + lc * 2;
            int r0 = wm + lr, r1 = wm + lr + 8;
            float v00 = sc[nt][0] * scale, v01 = sc[nt][1] * scale;
            float v10 = sc[nt][2] * scale, v11 = sc[nt][3] * scale;
            if (k0 + c     > q0 + r0) v00 = -1e30f;
            if (k0 + c + 1 > q0 + r0) v01 = -1e30f;
            if (k0 + c     > q0 + r1) v10 = -1e30f;
            if (k0 + c + 1 > q0 + r1) v11 = -1e30f;
            *(float2*)(Ss + r0 * FS_STR + c) = make_float2(v00, v01);
            *(float2*)(Ss + r1 * FS_STR + c) = make_float2(v10, v11);
        }
        __syncthreads();

        {
            int r = tid >> 2, p4 = tid & 3;
            int cb = p4 * 16;
            float mx = -1e30f;
            #pragma unroll
            for (int j = 0; j < 16; j++) mx = fmaxf(mx, Ss[r * FS_STR + cb + j]);
            mx = fmaxf(mx, __shfl_xor_sync(0xffffffffu, mx, 1));
            mx = fmaxf(mx, __shfl_xor_sync(0xffffffffu, mx, 2));
            float m_old = m_s[r];
            float m_new = fmaxf(m_old, mx);
            float alpha = __expf(m_old - m_new);
            float es = 0.f;
            #pragma unroll
            for (int j = 0; j < 16; j++) {
                float e = __expf(Ss[r * FS_STR + cb + j] - m_new);
                Ss[r * FS_STR + cb + j] = tf32r(e);
                es += e;
            }
            es += __shfl_xor_sync(0xffffffffu, es, 1);
            es += __shfl_xor_sync(0xffffffffu, es, 2);
            if (p4 == 0) {
                l_s[r] = l_s[r] * alpha + es;
                m_s[r] = m_new;
                a_s[r] = alpha;
            }
        }
        __syncthreads();

        {
            float a0 = a_s[wm + lr], a1 = a_s[wm + lr + 8];
            #pragma unroll
            for (int nt = 0; nt < 8; nt++) {
                oacc[nt][0] *= a0; oacc[nt][1] *= a0;
                oacc[nt][2] *= a1; oacc[nt][3] *= a1;
            }
            #pragma unroll
            for (int ks = 0; ks < 64; ks += 8) {
                uint32_t af[4], bf[8][2];
                af[0] = __float_as_uint(Ss[(wm + lr    ) * FS_STR + ks + lc]);
                af[1] = __float_as_uint(Ss[(wm + lr + 8) * FS_STR + ks + lc]);
                af[2] = __float_as_uint(Ss[(wm + lr    ) * FS_STR + ks + lc + 4]);
                af[3] = __float_as_uint(Ss[(wm + lr + 8) * FS_STR + ks + lc + 4]);
                #pragma unroll
                for (int nt = 0; nt < 8; nt++) {
                    int col = wn_pv + nt * 8 + lr;
                    bf[nt][0] = __float_as_uint(Vs[col * FV_STR + ks + lc]);
                    bf[nt][1] = __float_as_uint(Vs[col * FV_STR + ks + lc + 4]);
                }
                #pragma unroll
                for (int nt = 0; nt < 8; nt++)
                    mma_tf32(oacc[nt], af, bf[nt]);
            }
        }
    }
    __syncthreads();

    {
        float il0 = 1.f / l_s[wm + lr];
        float il1 = 1.f / l_s[wm + lr + 8];
        long long tok0 = (long long)b * S_ + q0 + wm + lr;
        long long tok1 = tok0 + 8;
        #pragma unroll
        for (int nt = 0; nt < 8; nt++) {
            int c = wn_pv + nt * 8 + lc * 2;
            *(float2*)(outfl + tok0 * (H_*DV_) + h * DV_ + c) =
                make_float2(tf32r(oacc[nt][0] * il0), tf32r(oacc[nt][1] * il0));
            *(float2*)(outfl + tok1 * (H_*DV_) + h * DV_ + c) =
                make_float2(tf32r(oacc[nt][2] * il1), tf32r(oacc[nt][3] * il1));
        }
    }
}

static inline dim3 g5(int M, int N) { return dim3((N + 255) / 256, M / 128, 1); }

extern "C" void kernel_launch(void* const* d_in, const int* in_sizes, int n_in,
                              void* d_out, int out_size)
{
    const float* hidden = (const float*)d_in[0];
    const int*   pos    = (const int*)  d_in[1];
    const float* Wq     = (const float*)d_in[2];
    const float* Wkva   = (const float*)d_in[3];
    const float* w_kvln = (const float*)d_in[4];
    const float* Wkvb   = (const float*)d_in[5];
    const float* Wo     = (const float*)d_in[6];
    const float* Wg     = (const float*)d_in[7];
    const float* Wu     = (const float*)d_in[8];
    const float* Wd     = (const float*)d_in[9];
    const float* w_ln1  = (const float*)d_in[10];
    const float* w_ln2  = (const float*)d_in[11];
    float* out = (float*)d_out;

    float *p_xln, *p_q, *p_ckv, *p_cln, *p_kv, *p_afl, *p_x2, *p_y, *p_g, *p_a;
    float *t_wq, *t_wkva, *t_wkvb, *t_wo, *t_wg, *t_wu, *t_wd;
    cudaGetSymbolAddress((void**)&p_xln, g_xln);
    cudaGetSymbolAddress((void**)&p_q,   g_q);
    cudaGetSymbolAddress((void**)&p_ckv, g_ckv);
    cudaGetSymbolAddress((void**)&p_cln, g_cln);
    cudaGetSymbolAddress((void**)&p_kv,  g_kv);
    cudaGetSymbolAddress((void**)&p_afl, g_attnfl);
    cudaGetSymbolAddress((void**)&p_x2,  g_x2);
    cudaGetSymbolAddress((void**)&p_y,   g_y);
    cudaGetSymbolAddress((void**)&p_g,   g_gate);
    cudaGetSymbolAddress((void**)&p_a,   g_act);
    cudaGetSymbolAddress((void**)&t_wq,   g_tWq);
    cudaGetSymbolAddress((void**)&t_wkva, g_tWkva);
    cudaGetSymbolAddress((void**)&t_wkvb, g_tWkvb);
    cudaGetSymbolAddress((void**)&t_wo,   g_tWo);
    cudaGetSymbolAddress((void**)&t_wg,   g_tWg);
    cudaGetSymbolAddress((void**)&t_wu,   g_tWu);
    cudaGetSymbolAddress((void**)&t_wd,   g_tWd);

    const int gemm_smem = GSTAGES * (128*36 + 256*36) * 4;   // 165888
    cudaFuncSetAttribute(gemm_tc5<0>, cudaFuncAttributeMaxDynamicSharedMemorySize, gemm_smem);
    cudaFuncSetAttribute(gemm_tc5<1>, cudaFuncAttributeMaxDynamicSharedMemorySize, gemm_smem);
    cudaFuncSetAttribute(gemm_tc5<2>, cudaFuncAttributeMaxDynamicSharedMemorySize, gemm_smem);
    cudaFuncSetAttribute(flash_mma_kernel, cudaFuncAttributeMaxDynamicSharedMemorySize, FLASH_SMEM);

    // launch order tuned so ncu (-s 5 -c 1) captures launch #6 = gemm Wq
    init_invfreq2_kernel<<<1, 32>>>();                                                    // 1
    trunc_kernel<<<1184, 256>>>(Wq,   t_wq,   (long long)H_*DQ_*HID_/4);                  // 2
    trunc_kernel<<<1184, 256>>>(Wkva, t_wkva, (long long)(RANK_+DROPE_)*HID_/4);          // 3
    trunc_kernel<<<1184, 256>>>(Wkvb, t_wkvb, (long long)H_*(DNOPE_+DV_)*RANK_/4);        // 4
    rmsnorm2_kernel<<<TOK_, 256>>>(hidden, w_ln1, p_xln, HID_, HID_);                     // 5
    gemm_tc5<0><<<g5(TOK_, H_*DQ_), 256, gemm_smem>>>(p_xln, t_wq, p_q, nullptr,          // 6 <- ncu
        TOK_, H_*DQ_, HID_);
    gemm_tc5<0><<<g5(TOK_, RANK_+DROPE_), 256, gemm_smem>>>(p_xln, t_wkva, p_ckv, nullptr,
        TOK_, RANK_+DROPE_, HID_);

    rmsnorm2_kernel<<<TOK_, 256>>>(p_ckv, w_kvln, p_cln, RANK_, RANK_+DROPE_);

    gemm_tc5<0><<<g5(TOK_, H_*(DNOPE_+DV_)), 256, gemm_smem>>>(p_cln, t_wkvb, p_kv, nullptr,
        TOK_, H_*(DNOPE_+DV_), RANK_);

    rope_q_kernel<<<(TOK_*H_ + 255)/256, 256>>>(pos);
    rope_k_kernel<<<(TOK_ + 255)/256, 256>>>(pos);
    transpose_v_kernel<<<dim3(S_/32, DV_/32, B_*H_), dim3(32, 8)>>>();

    flash_mma_kernel<<<dim3(S_/64, B_*H_), 256, FLASH_SMEM>>>(p_afl);

    trunc_kernel<<<1184, 256>>>(Wo, t_wo, (long long)HID_*H_*DV_/4);
    gemm_tc5<1><<<g5(TOK_, HID_), 256, gemm_smem>>>(p_afl, t_wo, p_x2, hidden, TOK_, HID_, H_*DV_);

    rmsnorm2_kernel<<<TOK_, 256>>>(p_x2, w_ln2, p_y, HID_, HID_);

    trunc_kernel<<<1184, 256>>>(Wg, t_wg, (long long)INTER_*HID_/4);
    gemm_tc5<0><<<g5(TOK_, INTER_), 256, gemm_smem>>>(p_y, t_wg, p_g, nullptr, TOK_, INTER_, HID_);
    trunc_kernel<<<1184, 256>>>(Wu, t_wu, (long long)INTER_*HID_/4);
    gemm_tc5<2><<<g5(TOK_, INTER_), 256, gemm_smem>>>(p_y, t_wu, p_a, p_g, TOK_, INTER_, HID_);

    trunc_kernel<<<1184, 256>>>(Wd, t_wd, (long long)HID_*INTER_/4);
    gemm_tc5<1><<<g5(TOK_, HID_), 256, gemm_smem>>>(p_a, t_wd, out, p_x2, TOK_, HID_, INTER_);
}

// round 14
// speedup vs baseline: 20.9899x; 1.7151x over previous
#include <cuda_runtime.h>
#include <cuda_fp16.h>
#include <math.h>
#include <stdint.h>

#define B_      2
#define S_      2048
#define HID_    2048
#define H_      16
#define DQ_     192
#define DNOPE_  128
#define DROPE_  64
#define DV_     128
#define RANK_   512
#define INTER_  10944
#define TOK_    (B_*S_)

__device__ __forceinline__ float tf32r(float x) {
    float r;
    asm("cvt.rna.tf32.f32 %0, %1;" : "=f"(r) : "f"(x));
    return r;
}

__device__ __forceinline__ void mma_f16(float* c, const uint32_t* a, const uint32_t* b) {
    asm volatile(
        "mma.sync.aligned.m16n8k16.row.col.f32.f16.f16.f32 "
        "{%0,%1,%2,%3}, {%4,%5,%6,%7}, {%8,%9}, {%0,%1,%2,%3};\n"
        : "+f"(c[0]), "+f"(c[1]), "+f"(c[2]), "+f"(c[3])
        : "r"(a[0]), "r"(a[1]), "r"(a[2]), "r"(a[3]), "r"(b[0]), "r"(b[1]));
}

__device__ __forceinline__ void cp_async16s(uint32_t saddr, const void* g) {
    asm volatile("cp.async.cg.shared.global [%0], [%1], 16;" :: "r"(saddr), "l"(g));
}

__device__ __forceinline__ uint32_t smem_to_u32(const void* p) {
    uint32_t a;
    asm("{ .reg .u64 t; cvta.to.shared.u64 t, %1; cvt.u32.u64 %0, t; }" : "=r"(a) : "l"(p));
    return a;
}

// ---------------- device scratch ----------------
__device__ float  g_invfreq[32];
__device__ __half g_xln    [TOK_*HID_];
__device__ float  g_q      [TOK_*H_*DQ_];
__device__ float  g_ckv    [TOK_*(RANK_+DROPE_)];
__device__ __half g_cln    [TOK_*RANK_];
__device__ float  g_kv     [TOK_*H_*(DNOPE_+DV_)];
__device__ __half g_Vt     [(size_t)B_*H_*DV_*S_];
__device__ __half g_attnfl [TOK_*H_*DV_];
__device__ float  g_x2     [TOK_*HID_];
__device__ __half g_y      [TOK_*HID_];
__device__ float  g_gate   [TOK_*INTER_];
__device__ __half g_act    [TOK_*INTER_];
// pre-truncated (tf32-rounded, stored fp16 — exact for normal range) weights
__device__ __half g_tWq   [(size_t)H_*DQ_*HID_];
__device__ __half g_tWkva [(size_t)(RANK_+DROPE_)*HID_];
__device__ __half g_tWkvb [(size_t)H_*(DNOPE_+DV_)*RANK_];
__device__ __half g_tWo   [(size_t)HID_*H_*DV_];
__device__ __half g_tWg   [(size_t)INTER_*HID_];
__device__ __half g_tWu   [(size_t)INTER_*HID_];
__device__ __half g_tWd   [(size_t)HID_*INTER_];

// ---- weight pre-truncation: f32 -> tf32 round -> f16 (exact) ----
__global__ void trunc_kernel(const float* __restrict__ src, __half* __restrict__ dst, long long n4) {
    long long i = (long long)blockIdx.x * blockDim.x + threadIdx.x;
    long long stride = (long long)gridDim.x * blockDim.x;
    for (; i < n4; i += stride) {
        float4 v = ((const float4*)src)[i];
        __half2 h0 = __floats2half2_rn(tf32r(v.x), tf32r(v.y));
        __half2 h1 = __floats2half2_rn(tf32r(v.z), tf32r(v.w));
        uint2 o;
        o.x = *(uint32_t*)&h0; o.y = *(uint32_t*)&h1;
        ((uint2*)dst)[i] = o;
    }
}

// ---- yarn inv_freq ----
__global__ void init_invfreq2_kernel() {
    int j = threadIdx.x;
    if (j >= 32) return;
    const double dim = 64.0, base = 10000.0, orig_max = 4096.0;
    const double two_pi = 6.283185307179586476925286766559;
    double cd_fast = dim * log(orig_max / (32.0 * two_pi)) / (2.0 * log(base));
    double cd_slow = dim * log(orig_max / ( 1.0 * two_pi)) / (2.0 * log(base));
    double lowd  = floor(cd_fast); if (lowd < 0.0) lowd = 0.0;
    double highd = ceil(cd_slow);  if (highd > dim - 1.0) highd = dim - 1.0;
    double hid = (lowd == highd) ? highd + 0.001 : highd;
    double ar = (2.0 * (double)j) / dim;
    double freq_extra = 1.0 / pow(base, ar);
    double freq_inter = 1.0 / (40.0 * pow(base, ar));
    double ramp = ((double)j - lowd) / (hid - lowd);
    if (ramp < 0.0) ramp = 0.0;
    if (ramp > 1.0) ramp = 1.0;
    double mask = 1.0 - ramp;
    g_invfreq[j] = (float)(freq_inter * (1.0 - mask) + freq_extra * mask);
}

// ---- RMSNorm -> half output (feeds matmuls only) ----
__global__ void rmsnorm_h_kernel(const float* __restrict__ x, const float* __restrict__ w,
                                 __half* __restrict__ out, int dim, int in_stride)
{
    const long long row = blockIdx.x;
    const float* xr = x + row * (long long)in_stride;
    __shared__ float buf[256];
    float partial = 0.f;
    for (int i = threadIdx.x; i < dim; i += 256) { float v = xr[i]; partial += v * v; }
    buf[threadIdx.x] = partial;
    __syncthreads();
    for (int stride = 128; stride > 0; stride >>= 1) {
        if (threadIdx.x < stride) buf[threadIdx.x] += buf[threadIdx.x + stride];
        __syncthreads();
    }
    float scale = rsqrtf(buf[0] / (float)dim + 1e-6f);
    for (int i = threadIdx.x; i < dim; i += 256)
        out[row * (long long)dim + i] = __float2half(tf32r(xr[i] * scale * w[i]));
}

// ---- fp16 tensor-core GEMM: C = A[M,K] @ Bw[N,K]^T ----
// 128x256 tile, BK=64 halves, double-buffered cp.async, 8 warps each 64x64.
// MODE 0: plain (CT=float)  MODE 1: +=R (CT=float)  MODE 2: C=half(tf32(silu(R)*acc)) (CT=half)
#define HA_BYTES  (128*144)                 // 18432
#define HB_BYTES  (256*144)                 // 36864
#define HGEMM_SMEM (2*(HA_BYTES+HB_BYTES))  // 110592
template<int MODE, typename CT>
__global__ void __launch_bounds__(256, 1) gemm_h(
    const __half* __restrict__ A, const __half* __restrict__ Bw,
    CT* __restrict__ C, const float* __restrict__ R,
    int M, int N, int K)
{
    extern __shared__ char smem[];
    const uint32_t smem_base = smem_to_u32(smem);
    uint32_t* sw = (uint32_t*)smem;
    const uint32_t aoff[2] = {0u, (uint32_t)(HA_BYTES + HB_BYTES)};
    const uint32_t boff[2] = {(uint32_t)HA_BYTES, (uint32_t)(2*HA_BYTES + HB_BYTES)};

    const int m0 = blockIdx.y * 128, n0 = blockIdx.x * 256;
    const int tid = threadIdx.x;
    const int warp = tid >> 5, lane = tid & 31;
    const int wm = (warp >> 2) * 64;
    const int wn = (warp & 3) * 64;
    const int lr = lane >> 2;
    const int lc = lane & 3;

    float acc[4][8][4];
    #pragma unroll
    for (int mt = 0; mt < 4; mt++)
        #pragma unroll
        for (int nt = 0; nt < 8; nt++)
            #pragma unroll
            for (int i = 0; i < 4; i++) acc[mt][nt][i] = 0.f;

    const int KT = K >> 6;

    // prefetch chunk 0 -> stage 0
    {
        #pragma unroll
        for (int i = 0; i < 4; i++) {
            int idx = tid + i * 256;
            int r = idx >> 3, c16 = idx & 7;
            cp_async16s(smem_base + aoff[0] + r * 144 + c16 * 16,
                        A + (long long)(m0 + r) * K + c16 * 8);
        }
        #pragma unroll
        for (int i = 0; i < 8; i++) {
            int idx = tid + i * 256;
            int r = idx >> 3, c16 = idx & 7;
            int gn = n0 + r; if (gn >= N) gn = N - 1;
            cp_async16s(smem_base + boff[0] + r * 144 + c16 * 16,
                        Bw + (long long)gn * K + c16 * 8);
        }
        asm volatile("cp.async.commit_group;");
    }

    for (int kt = 0; kt < KT; kt++) {
        const int st = kt & 1;
        if (kt + 1 < KT) {
            const int k0 = (kt + 1) << 6;
            const int nx = st ^ 1;
            #pragma unroll
            for (int i = 0; i < 4; i++) {
                int idx = tid + i * 256;
                int r = idx >> 3, c16 = idx & 7;
                cp_async16s(smem_base + aoff[nx] + r * 144 + c16 * 16,
                            A + (long long)(m0 + r) * K + k0 + c16 * 8);
            }
            #pragma unroll
            for (int i = 0; i < 8; i++) {
                int idx = tid + i * 256;
                int r = idx >> 3, c16 = idx & 7;
                int gn = n0 + r; if (gn >= N) gn = N - 1;
                cp_async16s(smem_base + boff[nx] + r * 144 + c16 * 16,
                            Bw + (long long)gn * K + k0 + c16 * 8);
            }
            asm volatile("cp.async.commit_group;");
            asm volatile("cp.async.wait_group 1;");
        } else {
            asm volatile("cp.async.wait_group 0;");
        }
        __syncthreads();

        const uint32_t awb = aoff[st] >> 2;
        const uint32_t bwb = boff[st] >> 2;
        #pragma unroll
        for (int kw = 0; kw < 32; kw += 8) {
            uint32_t af[4][4], bf[8][2];
            #pragma unroll
            for (int mt = 0; mt < 4; mt++) {
                int row = wm + mt * 16 + lr;
                af[mt][0] = sw[awb + (row    ) * 36 + kw + lc];
                af[mt][1] = sw[awb + (row + 8) * 36 + kw + lc];
                af[mt][2] = sw[awb + (row    ) * 36 + kw + 4 + lc];
                af[mt][3] = sw[awb + (row + 8) * 36 + kw + 4 + lc];
            }
            #pragma unroll
            for (int nt = 0; nt < 8; nt++) {
                int col = wn + nt * 8 + lr;
                bf[nt][0] = sw[bwb + col * 36 + kw + lc];
                bf[nt][1] = sw[bwb + col * 36 + kw + 4 + lc];
            }
            #pragma unroll
            for (int mt = 0; mt < 4; mt++)
                #pragma unroll
                for (int nt = 0; nt < 8; nt++)
                    mma_f16(acc[mt][nt], af[mt], bf[nt]);
        }
        __syncthreads();
    }

    #pragma unroll
    for (int mt = 0; mt < 4; mt++) {
        #pragma unroll
        for (int nt = 0; nt < 8; nt++) {
            int mmb = m0 + wm + mt * 16 + lr;
            int nn = n0 + wn + nt * 8 + lc * 2;
            #pragma unroll
            for (int half_ = 0; half_ < 2; half_++) {
                int mrow = mmb + half_ * 8;
                #pragma unroll
                for (int q = 0; q < 2; q++) {
                    int nc = nn + q;
                    if (nc >= N) continue;
                    float v = acc[mt][nt][half_ * 2 + q];
                    long long off = (long long)mrow * N + nc;
                    if (MODE == 1) {
                        C[off] = (CT)(v + R[off]);
                    } else if (MODE == 2) {
                        float gg = R[off];
                        float sig = 1.f / (1.f + expf(-gg));
                        C[off] = (CT)__float2half(tf32r(gg * sig * v));
                    } else {
                        C[off] = (CT)v;
                    }
                }
            }
        }
    }
}

// ---- RoPE in place (fp32) ----
__global__ void rope_q_kernel(const int* __restrict__ pos_ids) {
    int idx = blockIdx.x * 256 + threadIdx.x;
    if (idx >= TOK_ * H_) return;
    int tok = idx / H_;
    float* x = g_q + (long long)idx * DQ_ + DNOPE_;
    float pos = (float)pos_ids[tok];
    float xv[64];
    #pragma unroll
    for (int i = 0; i < 64; i++) xv[i] = x[i];
    #pragma unroll
    for (int j = 0; j < 32; j++) {
        float th = pos * g_invfreq[j];
        float c = cosf(th), sn = sinf(th);
        float x1 = xv[2*j], x2 = xv[2*j+1];
        x[j]      = x1 * c - x2 * sn;
        x[j + 32] = x2 * c + x1 * sn;
    }
}

__global__ void rope_k_kernel(const int* __restrict__ pos_ids) {
    int tok = blockIdx.x * 256 + threadIdx.x;
    if (tok >= TOK_) return;
    float* x = g_ckv + (long long)tok * (RANK_ + DROPE_) + RANK_;
    float pos = (float)pos_ids[tok];
    float xv[64];
    #pragma unroll
    for (int i = 0; i < 64; i++) xv[i] = x[i];
    #pragma unroll
    for (int j = 0; j < 32; j++) {
        float th = pos * g_invfreq[j];
        float c = cosf(th), sn = sinf(th);
        float x1 = xv[2*j], x2 = xv[2*j+1];
        x[j]      = x1 * c - x2 * sn;
        x[j + 32] = x2 * c + x1 * sn;
    }
}

// ---- V transpose: g_kv [tok][h][128+d] -> g_Vt half [z][d][s] ----
__global__ void transpose_v_kernel() {
    __shared__ float t[32][33];
    int z = blockIdx.z;
    int d0 = blockIdx.y * 32, s0 = blockIdx.x * 32;
    int b = z >> 4, h = z & 15;
    int tx = threadIdx.x, ty0 = threadIdx.y;
    #pragma unroll
    for (int dy = 0; dy < 32; dy += 8) {
        int ty = ty0 + dy;
        t[ty][tx] = g_kv[(((long long)b * S_ + s0 + ty) * H_ + h) * (DNOPE_ + DV_) + DNOPE_ + d0 + tx];
    }
    __syncthreads();
    #pragma unroll
    for (int dy = 0; dy < 32; dy += 8) {
        int ty = ty0 + dy;
        g_Vt[((long long)z * DV_ + d0 + ty) * S_ + s0 + tx] = __float2half(t[tx][ty]);
    }
}

// ---- fp16 tensor-core flash attention (causal, online softmax, reversed order) ----
#define FQS_OFF 0                         // Q: 64 rows x 200 halves (stride 100 words)
#define FKS_OFF 25600                     // K: same
#define FVS_OFF 51200                     // V: 128 rows x 72 halves (stride 36 words, 144B)
#define FSS_OFF 69632                     // scores fp32: 64 x 68
#define FPH_OFF 87040                     // P half: 64 x 72
#define FML_OFF 96256                     // m/l/a: 3 x 64 floats
#define FLASH_SMEM (FML_OFF + 768)

__global__ void __launch_bounds__(256) flash_h_kernel(__half* __restrict__ outfl)
{
    extern __shared__ char smem[];
    uint32_t* qw = (uint32_t*)(smem + FQS_OFF);
    uint32_t* kw = (uint32_t*)(smem + FKS_OFF);
    uint32_t* vw = (uint32_t*)(smem + FVS_OFF);
    float*    Ss = (float*)(smem + FSS_OFF);
    __half*   Ph = (__half*)(smem + FPH_OFF);
    uint32_t* pw = (uint32_t*)(smem + FPH_OFF);
    float*    m_s = (float*)(smem + FML_OFF);
    float*    l_s = m_s + 64;
    float*    a_s = l_s + 64;
    const uint32_t smem_base = smem_to_u32(smem);

    const int z = blockIdx.y;
    const int b = z >> 4, h = z & 15;
    const int qt = gridDim.x - 1 - blockIdx.x;
    const int q0 = qt * 64;
    const int tid = threadIdx.x;
    const int warp = tid >> 5, lane = tid & 31;
    const int lr = lane >> 2, lc = lane & 3;
    const int wm = (warp & 3) * 16;
    const int wn_qk = (warp >> 2) * 32;
    const int wn_pv = (warp >> 2) * 64;
    const float scale = 0.07216878364870323f; // 192^-0.5
    const __half* Vg = g_Vt + (long long)z * DV_ * S_;

    // Q tile: fp32 -> half
    for (int i = tid; i < 64 * 48; i += 256) {
        int r = i / 48, c4 = (i % 48) * 4;
        float4 v = *(const float4*)(g_q + (((long long)b * S_ + q0 + r) * H_ + h) * DQ_ + c4);
        __half2 h0 = __floats2half2_rn(v.x, v.y);
        __half2 h1 = __floats2half2_rn(v.z, v.w);
        qw[r * 100 + c4/2    ] = *(uint32_t*)&h0;
        qw[r * 100 + c4/2 + 1] = *(uint32_t*)&h1;
    }
    if (tid < 64) { m_s[tid] = -1e30f; l_s[tid] = 0.f; }

    float oacc[8][4];
    #pragma unroll
    for (int nt = 0; nt < 8; nt++)
        #pragma unroll
        for (int i = 0; i < 4; i++) oacc[nt][i] = 0.f;

    for (int t = 0; t <= qt; t++) {
        const int k0 = t * 64;
        __syncthreads();
        // K tile
        for (int i = tid; i < 64 * 48; i += 256) {
            int r = i / 48, c4 = (i % 48) * 4;
            long long tok = (long long)b * S_ + k0 + r;
            float4 v;
            if (c4 < DNOPE_)
                v = *(const float4*)(g_kv + (tok * H_ + h) * (DNOPE_ + DV_) + c4);
            else
                v = *(const float4*)(g_ckv + tok * (RANK_ + DROPE_) + RANK_ + (c4 - DNOPE_));
            __half2 h0 = __floats2half2_rn(v.x, v.y);
            __half2 h1 = __floats2half2_rn(v.z, v.w);
            kw[r * 100 + c4/2    ] = *(uint32_t*)&h0;
            kw[r * 100 + c4/2 + 1] = *(uint32_t*)&h1;
        }
        // V tile: 128 rows x 64 halves = 8 x 16B chunks per row  (R13 bug: was 4)
        for (int i = tid; i < 128 * 8; i += 256) {
            int r = i >> 3, c16 = i & 7;
            cp_async16s(smem_base + FVS_OFF + r * 144 + c16 * 16,
                        Vg + (long long)r * S_ + k0 + c16 * 8);
        }
        asm volatile("cp.async.commit_group; cp.async.wait_group 0;" ::: "memory");
        __syncthreads();

        // QK^T : 16 rows x 32 cols per warp
        float sc[4][4];
        #pragma unroll
        for (int nt = 0; nt < 4; nt++)
            #pragma unroll
            for (int i = 0; i < 4; i++) sc[nt][i] = 0.f;
        #pragma unroll
        for (int kk = 0; kk < 96; kk += 8) {
            uint32_t af[4], bf[4][2];
            af[0] = qw[(wm + lr    ) * 100 + kk + lc];
            af[1] = qw[(wm + lr + 8) * 100 + kk + lc];
            af[2] = qw[(wm + lr    ) * 100 + kk + 4 + lc];
            af[3] = qw[(wm + lr + 8) * 100 + kk + 4 + lc];
            #pragma unroll
            for (int nt = 0; nt < 4; nt++) {
                int col = wn_qk + nt * 8 + lr;
                bf[nt][0] = kw[col * 100 + kk + lc];
                bf[nt][1] = kw[col * 100 + kk + 4 + lc];
            }
            #pragma unroll
            for (int nt = 0; nt < 4; nt++)
                mma_f16(sc[nt], af, bf[nt]);
        }
        #pragma unroll
        for (int nt = 0; nt < 4; nt++) {
            int c = wn_qk + nt * 8 + lc * 2;
            int r0 = wm + lr, r1 = wm + lr + 8;
            float v00 = sc[nt][0] * scale, v01 = sc[nt][1] * scale;
            float v10 = sc[nt][2] * scale, v11 = sc[nt][3] * scale;
            if (k0 + c     > q0 + r0) v00 = -1e30f;
            if (k0 + c + 1 > q0 + r0) v01 = -1e30f;
            if (k0 + c     > q0 + r1) v10 = -1e30f;
            if (k0 + c + 1 > q0 + r1) v11 = -1e30f;
            *(float2*)(Ss + r0 * 68 + c) = make_float2(v00, v01);
            *(float2*)(Ss + r1 * 68 + c) = make_float2(v10, v11);
        }
        __syncthreads();

        // online softmax: 4 threads per row
        {
            int r = tid >> 2, p4 = tid & 3;
            int cb = p4 * 16;
            float mx = -1e30f;
            #pragma unroll
            for (int j = 0; j < 16; j++) mx = fmaxf(mx, Ss[r * 68 + cb + j]);
            mx = fmaxf(mx, __shfl_xor_sync(0xffffffffu, mx, 1));
            mx = fmaxf(mx, __shfl_xor_sync(0xffffffffu, mx, 2));
            float m_old = m_s[r];
            float m_new = fmaxf(m_old, mx);
            float alpha = __expf(m_old - m_new);
            float es = 0.f;
            #pragma unroll
            for (int j = 0; j < 16; j++) {
                float e = __expf(Ss[r * 68 + cb + j] - m_new);
                Ph[r * 72 + cb + j] = __float2half(e);
                es += e;
            }
            es += __shfl_xor_sync(0xffffffffu, es, 1);
            es += __shfl_xor_sync(0xffffffffu, es, 2);
            if (p4 == 0) {
                l_s[r] = l_s[r] * alpha + es;
                m_s[r] = m_new;
                a_s[r] = alpha;
            }
        }
        __syncthreads();

        // PV
        {
            float a0 = a_s[wm + lr], a1 = a_s[wm + lr + 8];
            #pragma unroll
            for (int nt = 0; nt < 8; nt++) {
                oacc[nt][0] *= a0; oacc[nt][1] *= a0;
                oacc[nt][2] *= a1; oacc[nt][3] *= a1;
            }
            #pragma unroll
            for (int kk = 0; kk < 32; kk += 8) {
                uint32_t af[4], bf[8][2];
                af[0] = pw[(wm + lr    ) * 36 + kk + lc];
                af[1] = pw[(wm + lr + 8) * 36 + kk + lc];
                af[2] = pw[(wm + lr    ) * 36 + kk + 4 + lc];
                af[3] = pw[(wm + lr + 8) * 36 + kk + 4 + lc];
                #pragma unroll
                for (int nt = 0; nt < 8; nt++) {
                    int col = wn_pv + nt * 8 + lr;
                    bf[nt][0] = vw[col * 36 + kk + lc];
                    bf[nt][1] = vw[col * 36 + kk + 4 + lc];
                }
                #pragma unroll
                for (int nt = 0; nt < 8; nt++)
                    mma_f16(oacc[nt], af, bf[nt]);
            }
        }
    }
    __syncthreads();

    // epilogue
    {
        float il0 = 1.f / l_s[wm + lr];
        float il1 = 1.f / l_s[wm + lr + 8];
        long long tok0 = (long long)b * S_ + q0 + wm + lr;
        long long tok1 = tok0 + 8;
        #pragma unroll
        for (int nt = 0; nt < 8; nt++) {
            int c = wn_pv + nt * 8 + lc * 2;
            __half2 o0 = __floats2half2_rn(tf32r(oacc[nt][0] * il0), tf32r(oacc[nt][1] * il0));
            __half2 o1 = __floats2half2_rn(tf32r(oacc[nt][2] * il1), tf32r(oacc[nt][3] * il1));
            *(__half2*)(outfl + tok0 * (H_*DV_) + h * DV_ + c) = o0;
            *(__half2*)(outfl + tok1 * (H_*DV_) + h * DV_ + c) = o1;
        }
    }
}

static inline dim3 gh(int M, int N) { return dim3((N + 255) / 256, M / 128, 1); }

extern "C" void kernel_launch(void* const* d_in, const int* in_sizes, int n_in,
                              void* d_out, int out_size)
{
    const float* hidden = (const float*)d_in[0];
    const int*   pos    = (const int*)  d_in[1];
    const float* Wq     = (const float*)d_in[2];
    const float* Wkva   = (const float*)d_in[3];
    const float* w_kvln = (const float*)d_in[4];
    const float* Wkvb   = (const float*)d_in[5];
    const float* Wo     = (const float*)d_in[6];
    const float* Wg     = (const float*)d_in[7];
    const float* Wu     = (const float*)d_in[8];
    const float* Wd     = (const float*)d_in[9];
    const float* w_ln1  = (const float*)d_in[10];
    const float* w_ln2  = (const float*)d_in[11];
    float* out = (float*)d_out;

    float *p_q, *p_ckv, *p_kv, *p_x2, *p_g;
    __half *p_xln, *p_cln, *p_afl, *p_y, *p_a;
    __half *t_wq, *t_wkva, *t_wkvb, *t_wo, *t_wg, *t_wu, *t_wd;
    cudaGetSymbolAddress((void**)&p_xln, g_xln);
    cudaGetSymbolAddress((void**)&p_q,   g_q);
    cudaGetSymbolAddress((void**)&p_ckv, g_ckv);
    cudaGetSymbolAddress((void**)&p_cln, g_cln);
    cudaGetSymbolAddress((void**)&p_kv,  g_kv);
    cudaGetSymbolAddress((void**)&p_afl, g_attnfl);
    cudaGetSymbolAddress((void**)&p_x2,  g_x2);
    cudaGetSymbolAddress((void**)&p_y,   g_y);
    cudaGetSymbolAddress((void**)&p_g,   g_gate);
    cudaGetSymbolAddress((void**)&p_a,   g_act);
    cudaGetSymbolAddress((void**)&t_wq,   g_tWq);
    cudaGetSymbolAddress((void**)&t_wkva, g_tWkva);
    cudaGetSymbolAddress((void**)&t_wkvb, g_tWkvb);
    cudaGetSymbolAddress((void**)&t_wo,   g_tWo);
    cudaGetSymbolAddress((void**)&t_wg,   g_tWg);
    cudaGetSymbolAddress((void**)&t_wu,   g_tWu);
    cudaGetSymbolAddress((void**)&t_wd,   g_tWd);

    cudaFuncSetAttribute(gemm_h<0,float>,  cudaFuncAttributeMaxDynamicSharedMemorySize, HGEMM_SMEM);
    cudaFuncSetAttribute(gemm_h<1,float>,  cudaFuncAttributeMaxDynamicSharedMemorySize, HGEMM_SMEM);
    cudaFuncSetAttribute(gemm_h<2,__half>, cudaFuncAttributeMaxDynamicSharedMemorySize, HGEMM_SMEM);
    cudaFuncSetAttribute(flash_h_kernel,   cudaFuncAttributeMaxDynamicSharedMemorySize, FLASH_SMEM);

    // order chosen so ncu (-s 5 -c 1) captures launch #6 = Wq GEMM
    init_invfreq2_kernel<<<1, 32>>>();                                                // 1
    trunc_kernel<<<1184, 256>>>(Wq,   t_wq,   (long long)H_*DQ_*HID_/4);              // 2
    trunc_kernel<<<1184, 256>>>(Wkva, t_wkva, (long long)(RANK_+DROPE_)*HID_/4);      // 3
    trunc_kernel<<<1184, 256>>>(Wkvb, t_wkvb, (long long)H_*(DNOPE_+DV_)*RANK_/4);    // 4
    rmsnorm_h_kernel<<<TOK_, 256>>>(hidden, w_ln1, p_xln, HID_, HID_);                // 5
    gemm_h<0,float><<<gh(TOK_, H_*DQ_), 256, HGEMM_SMEM>>>(p_xln, t_wq, p_q, nullptr, // 6
        TOK_, H_*DQ_, HID_);
    gemm_h<0,float><<<gh(TOK_, RANK_+DROPE_), 256, HGEMM_SMEM>>>(p_xln, t_wkva, p_ckv, nullptr,
        TOK_, RANK_+DROPE_, HID_);

    rmsnorm_h_kernel<<<TOK_, 256>>>(p_ckv, w_kvln, p_cln, RANK_, RANK_+DROPE_);

    gemm_h<0,float><<<gh(TOK_, H_*(DNOPE_+DV_)), 256, HGEMM_SMEM>>>(p_cln, t_wkvb, p_kv, nullptr,
        TOK_, H_*(DNOPE_+DV_), RANK_);

    rope_q_kernel<<<(TOK_*H_ + 255)/256, 256>>>(pos);
    rope_k_kernel<<<(TOK_ + 255)/256, 256>>>(pos);
    transpose_v_kernel<<<dim3(S_/32, DV_/32, B_*H_), dim3(32, 8)>>>();

    flash_h_kernel<<<dim3(S_/64, B_*H_), 256, FLASH_SMEM>>>(p_afl);

    trunc_kernel<<<1184, 256>>>(Wo, t_wo, (long long)HID_*H_*DV_/4);
    gemm_h<1,float><<<gh(TOK_, HID_), 256, HGEMM_SMEM>>>(p_afl, t_wo, p_x2, hidden, TOK_, HID_, H_*DV_);

    rmsnorm_h_kernel<<<TOK_, 256>>>(p_x2, w_ln2, p_y, HID_, HID_);

    trunc_kernel<<<1184, 256>>>(Wg, t_wg, (long long)INTER_*HID_/4);
    gemm_h<0,float><<<gh(TOK_, INTER_), 256, HGEMM_SMEM>>>(p_y, t_wg, p_g, nullptr, TOK_, INTER_, HID_);
    trunc_kernel<<<1184, 256>>>(Wu, t_wu, (long long)INTER_*HID_/4);
    gemm_h<2,__half><<<gh(TOK_, INTER_), 256, HGEMM_SMEM>>>(p_y, t_wu, p_a, p_g, TOK_, INTER_, HID_);

    trunc_kernel<<<1184, 256>>>(Wd, t_wd, (long long)HID_*INTER_/4);
    gemm_h<1,float><<<gh(TOK_, HID_), 256, HGEMM_SMEM>>>(p_a, t_wd, out, p_x2, TOK_, HID_, INTER_);
}

// round 15
// speedup vs baseline: 21.0207x; 1.0015x over previous
#include <cuda_runtime.h>
#include <cuda_fp16.h>
#include <math.h>
#include <stdint.h>

#define B_      2
#define S_      2048
#define HID_    2048
#define H_      16
#define DQ_     192
#define DNOPE_  128
#define DROPE_  64
#define DV_     128
#define RANK_   512
#define INTER_  10944
#define TOK_    (B_*S_)

__device__ __forceinline__ float tf32r(float x) {
    float r;
    asm("cvt.rna.tf32.f32 %0, %1;" : "=f"(r) : "f"(x));
    return r;
}

__device__ __forceinline__ void mma_f16(float* c, const uint32_t* a, const uint32_t* b) {
    asm volatile(
        "mma.sync.aligned.m16n8k16.row.col.f32.f16.f16.f32 "
        "{%0,%1,%2,%3}, {%4,%5,%6,%7}, {%8,%9}, {%0,%1,%2,%3};\n"
        : "+f"(c[0]), "+f"(c[1]), "+f"(c[2]), "+f"(c[3])
        : "r"(a[0]), "r"(a[1]), "r"(a[2]), "r"(a[3]), "r"(b[0]), "r"(b[1]));
}

__device__ __forceinline__ void ldsm4(uint32_t& r0, uint32_t& r1, uint32_t& r2, uint32_t& r3, uint32_t addr) {
    asm volatile("ldmatrix.sync.aligned.m8n8.x4.shared.b16 {%0,%1,%2,%3}, [%4];"
        : "=r"(r0), "=r"(r1), "=r"(r2), "=r"(r3) : "r"(addr));
}

__device__ __forceinline__ void cp_async16s(uint32_t saddr, const void* g) {
    asm volatile("cp.async.cg.shared.global [%0], [%1], 16;" :: "r"(saddr), "l"(g));
}

__device__ __forceinline__ uint32_t smem_to_u32(const void* p) {
    uint32_t a;
    asm("{ .reg .u64 t; cvta.to.shared.u64 t, %1; cvt.u32.u64 %0, t; }" : "=r"(a) : "l"(p));
    return a;
}

// ---------------- device scratch ----------------
__device__ float  g_invfreq[32];
__device__ __half g_xln    [TOK_*HID_];
__device__ float  g_q      [TOK_*H_*DQ_];
__device__ float  g_ckv    [TOK_*(RANK_+DROPE_)];
__device__ __half g_cln    [TOK_*RANK_];
__device__ float  g_kv     [TOK_*H_*(DNOPE_+DV_)];
__device__ __half g_Vt     [(size_t)B_*H_*DV_*S_];
__device__ __half g_attnfl [TOK_*H_*DV_];
__device__ float  g_x2     [TOK_*HID_];
__device__ __half g_y      [TOK_*HID_];
__device__ float  g_gate   [TOK_*INTER_];
__device__ __half g_act    [TOK_*INTER_];
__device__ __half g_tWq   [(size_t)H_*DQ_*HID_];
__device__ __half g_tWkva [(size_t)(RANK_+DROPE_)*HID_];
__device__ __half g_tWkvb [(size_t)H_*(DNOPE_+DV_)*RANK_];
__device__ __half g_tWo   [(size_t)HID_*H_*DV_];
__device__ __half g_tWg   [(size_t)INTER_*HID_];
__device__ __half g_tWu   [(size_t)INTER_*HID_];
__device__ __half g_tWd   [(size_t)HID_*INTER_];

// ---- weight pre-truncation: f32 -> tf32 round -> f16 (exact) ----
__global__ void trunc_kernel(const float* __restrict__ src, __half* __restrict__ dst, long long n4) {
    long long i = (long long)blockIdx.x * blockDim.x + threadIdx.x;
    long long stride = (long long)gridDim.x * blockDim.x;
    for (; i < n4; i += stride) {
        float4 v = ((const float4*)src)[i];
        __half2 h0 = __floats2half2_rn(tf32r(v.x), tf32r(v.y));
        __half2 h1 = __floats2half2_rn(tf32r(v.z), tf32r(v.w));
        uint2 o;
        o.x = *(uint32_t*)&h0; o.y = *(uint32_t*)&h1;
        ((uint2*)dst)[i] = o;
    }
}

// ---- yarn inv_freq ----
__global__ void init_invfreq2_kernel() {
    int j = threadIdx.x;
    if (j >= 32) return;
    const double dim = 64.0, base = 10000.0, orig_max = 4096.0;
    const double two_pi = 6.283185307179586476925286766559;
    double cd_fast = dim * log(orig_max / (32.0 * two_pi)) / (2.0 * log(base));
    double cd_slow = dim * log(orig_max / ( 1.0 * two_pi)) / (2.0 * log(base));
    double lowd  = floor(cd_fast); if (lowd < 0.0) lowd = 0.0;
    double highd = ceil(cd_slow);  if (highd > dim - 1.0) highd = dim - 1.0;
    double hid = (lowd == highd) ? highd + 0.001 : highd;
    double ar = (2.0 * (double)j) / dim;
    double freq_extra = 1.0 / pow(base, ar);
    double freq_inter = 1.0 / (40.0 * pow(base, ar));
    double ramp = ((double)j - lowd) / (hid - lowd);
    if (ramp < 0.0) ramp = 0.0;
    if (ramp > 1.0) ramp = 1.0;
    double mask = 1.0 - ramp;
    g_invfreq[j] = (float)(freq_inter * (1.0 - mask) + freq_extra * mask);
}

// ---- RMSNorm -> half output ----
__global__ void rmsnorm_h_kernel(const float* __restrict__ x, const float* __restrict__ w,
                                 __half* __restrict__ out, int dim, int in_stride)
{
    const long long row = blockIdx.x;
    const float* xr = x + row * (long long)in_stride;
    __shared__ float buf[256];
    float partial = 0.f;
    for (int i = threadIdx.x; i < dim; i += 256) { float v = xr[i]; partial += v * v; }
    buf[threadIdx.x] = partial;
    __syncthreads();
    for (int stride = 128; stride > 0; stride >>= 1) {
        if (threadIdx.x < stride) buf[threadIdx.x] += buf[threadIdx.x + stride];
        __syncthreads();
    }
    float scale = rsqrtf(buf[0] / (float)dim + 1e-6f);
    for (int i = threadIdx.x; i < dim; i += 256)
        out[row * (long long)dim + i] = __float2half(tf32r(xr[i] * scale * w[i]));
}

// ---- fp16 tensor-core GEMM with ldmatrix fragment loads ----
// C = A[M,K] @ Bw[N,K]^T. 128x256 tile, BK=64, double-buffered cp.async.
// MODE 0: plain (CT=float)  MODE 1: +=R (CT=float)  MODE 2: C=half(tf32(silu(R)*acc)) (CT=half)
#define HA_BYTES  (128*144)
#define HB_BYTES  (256*144)
#define HGEMM_SMEM (2*(HA_BYTES+HB_BYTES))  // 110592
template<int MODE, typename CT>
__global__ void __launch_bounds__(256, 1) gemm_h(
    const __half* __restrict__ A, const __half* __restrict__ Bw,
    CT* __restrict__ C, const float* __restrict__ R,
    int M, int N, int K)
{
    extern __shared__ char smem[];
    const uint32_t smem_base = smem_to_u32(smem);
    const uint32_t aoff[2] = {0u, (uint32_t)(HA_BYTES + HB_BYTES)};
    const uint32_t boff[2] = {(uint32_t)HA_BYTES, (uint32_t)(2*HA_BYTES + HB_BYTES)};

    const int m0 = blockIdx.y * 128, n0 = blockIdx.x * 256;
    const int tid = threadIdx.x;
    const int warp = tid >> 5, lane = tid & 31;
    const int wm = (warp >> 2) * 64;
    const int wn = (warp & 3) * 64;
    const int lr = lane >> 2;
    const int lc = lane & 3;
    // ldmatrix per-lane offsets
    const uint32_t lq = lane >> 3, l8 = lane & 7;
    const uint32_t a_lane = ((lq & 1) * 8 + l8) * 144 + (lq >> 1) * 16;
    const uint32_t b_lane = ((lq >> 1) * 8 + l8) * 144 + (lq & 1) * 16;

    float acc[4][8][4];
    #pragma unroll
    for (int mt = 0; mt < 4; mt++)
        #pragma unroll
        for (int nt = 0; nt < 8; nt++)
            #pragma unroll
            for (int i = 0; i < 4; i++) acc[mt][nt][i] = 0.f;

    const int KT = K >> 6;

    // prefetch chunk 0 -> stage 0
    {
        #pragma unroll
        for (int i = 0; i < 4; i++) {
            int idx = tid + i * 256;
            int r = idx >> 3, c16 = idx & 7;
            cp_async16s(smem_base + aoff[0] + r * 144 + c16 * 16,
                        A + (long long)(m0 + r) * K + c16 * 8);
        }
        #pragma unroll
        for (int i = 0; i < 8; i++) {
            int idx = tid + i * 256;
            int r = idx >> 3, c16 = idx & 7;
            int gn = n0 + r; if (gn >= N) gn = N - 1;
            cp_async16s(smem_base + boff[0] + r * 144 + c16 * 16,
                        Bw + (long long)gn * K + c16 * 8);
        }
        asm volatile("cp.async.commit_group;");
    }

    for (int kt = 0; kt < KT; kt++) {
        const int st = kt & 1;
        if (kt + 1 < KT) {
            const int k0 = (kt + 1) << 6;
            const int nx = st ^ 1;
            #pragma unroll
            for (int i = 0; i < 4; i++) {
                int idx = tid + i * 256;
                int r = idx >> 3, c16 = idx & 7;
                cp_async16s(smem_base + aoff[nx] + r * 144 + c16 * 16,
                            A + (long long)(m0 + r) * K + k0 + c16 * 8);
            }
            #pragma unroll
            for (int i = 0; i < 8; i++) {
                int idx = tid + i * 256;
                int r = idx >> 3, c16 = idx & 7;
                int gn = n0 + r; if (gn >= N) gn = N - 1;
                cp_async16s(smem_base + boff[nx] + r * 144 + c16 * 16,
                            Bw + (long long)gn * K + k0 + c16 * 8);
            }
            asm volatile("cp.async.commit_group;");
            asm volatile("cp.async.wait_group 1;");
        } else {
            asm volatile("cp.async.wait_group 0;");
        }
        __syncthreads();

        const uint32_t ab = smem_base + aoff[st];
        const uint32_t bb = smem_base + boff[st];
        #pragma unroll
        for (int kw = 0; kw < 32; kw += 8) {          // 4 x k16 steps
            uint32_t af[4][4], bf[8][2];
            #pragma unroll
            for (int mt = 0; mt < 4; mt++)
                ldsm4(af[mt][0], af[mt][1], af[mt][2], af[mt][3],
                      ab + (wm + mt * 16) * 144 + kw * 4 + a_lane);
            #pragma unroll
            for (int ntp = 0; ntp < 4; ntp++)
                ldsm4(bf[2*ntp][0], bf[2*ntp][1], bf[2*ntp+1][0], bf[2*ntp+1][1],
                      bb + (wn + ntp * 16) * 144 + kw * 4 + b_lane);
            #pragma unroll
            for (int mt = 0; mt < 4; mt++)
                #pragma unroll
                for (int nt = 0; nt < 8; nt++)
                    mma_f16(acc[mt][nt], af[mt], bf[nt]);
        }
        __syncthreads();
    }

    #pragma unroll
    for (int mt = 0; mt < 4; mt++) {
        #pragma unroll
        for (int nt = 0; nt < 8; nt++) {
            int mmb = m0 + wm + mt * 16 + lr;
            int nn = n0 + wn + nt * 8 + lc * 2;
            #pragma unroll
            for (int half_ = 0; half_ < 2; half_++) {
                int mrow = mmb + half_ * 8;
                #pragma unroll
                for (int q = 0; q < 2; q++) {
                    int nc = nn + q;
                    if (nc >= N) continue;
                    float v = acc[mt][nt][half_ * 2 + q];
                    long long off = (long long)mrow * N + nc;
                    if (MODE == 1) {
                        C[off] = (CT)(v + R[off]);
                    } else if (MODE == 2) {
                        float gg = R[off];
                        float sig = 1.f / (1.f + expf(-gg));
                        C[off] = (CT)__float2half(tf32r(gg * sig * v));
                    } else {
                        C[off] = (CT)v;
                    }
                }
            }
        }
    }
}

// ---- RoPE in place ----
__global__ void rope_q_kernel(const int* __restrict__ pos_ids) {
    int idx = blockIdx.x * 256 + threadIdx.x;
    if (idx >= TOK_ * H_) return;
    int tok = idx / H_;
    float* x = g_q + (long long)idx * DQ_ + DNOPE_;
    float pos = (float)pos_ids[tok];
    float xv[64];
    #pragma unroll
    for (int i = 0; i < 64; i++) xv[i] = x[i];
    #pragma unroll
    for (int j = 0; j < 32; j++) {
        float th = pos * g_invfreq[j];
        float c = cosf(th), sn = sinf(th);
        float x1 = xv[2*j], x2 = xv[2*j+1];
        x[j]      = x1 * c - x2 * sn;
        x[j + 32] = x2 * c + x1 * sn;
    }
}

__global__ void rope_k_kernel(const int* __restrict__ pos_ids) {
    int tok = blockIdx.x * 256 + threadIdx.x;
    if (tok >= TOK_) return;
    float* x = g_ckv + (long long)tok * (RANK_ + DROPE_) + RANK_;
    float pos = (float)pos_ids[tok];
    float xv[64];
    #pragma unroll
    for (int i = 0; i < 64; i++) xv[i] = x[i];
    #pragma unroll
    for (int j = 0; j < 32; j++) {
        float th = pos * g_invfreq[j];
        float c = cosf(th), sn = sinf(th);
        float x1 = xv[2*j], x2 = xv[2*j+1];
        x[j]      = x1 * c - x2 * sn;
        x[j + 32] = x2 * c + x1 * sn;
    }
}

// ---- V transpose ----
__global__ void transpose_v_kernel() {
    __shared__ float t[32][33];
    int z = blockIdx.z;
    int d0 = blockIdx.y * 32, s0 = blockIdx.x * 32;
    int b = z >> 4, h = z & 15;
    int tx = threadIdx.x, ty0 = threadIdx.y;
    #pragma unroll
    for (int dy = 0; dy < 32; dy += 8) {
        int ty = ty0 + dy;
        t[ty][tx] = g_kv[(((long long)b * S_ + s0 + ty) * H_ + h) * (DNOPE_ + DV_) + DNOPE_ + d0 + tx];
    }
    __syncthreads();
    #pragma unroll
    for (int dy = 0; dy < 32; dy += 8) {
        int ty = ty0 + dy;
        g_Vt[((long long)z * DV_ + d0 + ty) * S_ + s0 + tx] = __float2half(t[tx][ty]);
    }
}

// ---- fp16 tensor-core flash attention ----
#define FQS_OFF 0
#define FKS_OFF 25600
#define FVS_OFF 51200
#define FSS_OFF 69632
#define FPH_OFF 87040
#define FML_OFF 96256
#define FLASH_SMEM (FML_OFF + 768)

__global__ void __launch_bounds__(256) flash_h_kernel(__half* __restrict__ outfl)
{
    extern __shared__ char smem[];
    uint32_t* qw = (uint32_t*)(smem + FQS_OFF);
    uint32_t* kw = (uint32_t*)(smem + FKS_OFF);
    uint32_t* vw = (uint32_t*)(smem + FVS_OFF);
    float*    Ss = (float*)(smem + FSS_OFF);
    __half*   Ph = (__half*)(smem + FPH_OFF);
    uint32_t* pw = (uint32_t*)(smem + FPH_OFF);
    float*    m_s = (float*)(smem + FML_OFF);
    float*    l_s = m_s + 64;
    float*    a_s = l_s + 64;
    const uint32_t smem_base = smem_to_u32(smem);

    const int z = blockIdx.y;
    const int b = z >> 4, h = z & 15;
    const int qt = gridDim.x - 1 - blockIdx.x;
    const int q0 = qt * 64;
    const int tid = threadIdx.x;
    const int warp = tid >> 5, lane = tid & 31;
    const int lr = lane >> 2, lc = lane & 3;
    const int wm = (warp & 3) * 16;
    const int wn_qk = (warp >> 2) * 32;
    const int wn_pv = (warp >> 2) * 64;
    const float scale = 0.07216878364870323f;
    const __half* Vg = g_Vt + (long long)z * DV_ * S_;

    for (int i = tid; i < 64 * 48; i += 256) {
        int r = i / 48, c4 = (i % 48) * 4;
        float4 v = *(const float4*)(g_q + (((long long)b * S_ + q0 + r) * H_ + h) * DQ_ + c4);
        __half2 h0 = __floats2half2_rn(v.x, v.y);
        __half2 h1 = __floats2half2_rn(v.z, v.w);
        qw[r * 100 + c4/2    ] = *(uint32_t*)&h0;
        qw[r * 100 + c4/2 + 1] = *(uint32_t*)&h1;
    }
    if (tid < 64) { m_s[tid] = -1e30f; l_s[tid] = 0.f; }

    float oacc[8][4];
    #pragma unroll
    for (int nt = 0; nt < 8; nt++)
        #pragma unroll
        for (int i = 0; i < 4; i++) oacc[nt][i] = 0.f;

    for (int t = 0; t <= qt; t++) {
        const int k0 = t * 64;
        __syncthreads();
        for (int i = tid; i < 64 * 48; i += 256) {
            int r = i / 48, c4 = (i % 48) * 4;
            long long tok = (long long)b * S_ + k0 + r;
            float4 v;
            if (c4 < DNOPE_)
                v = *(const float4*)(g_kv + (tok * H_ + h) * (DNOPE_ + DV_) + c4);
            else
                v = *(const float4*)(g_ckv + tok * (RANK_ + DROPE_) + RANK_ + (c4 - DNOPE_));
            __half2 h0 = __floats2half2_rn(v.x, v.y);
            __half2 h1 = __floats2half2_rn(v.z, v.w);
            kw[r * 100 + c4/2    ] = *(uint32_t*)&h0;
            kw[r * 100 + c4/2 + 1] = *(uint32_t*)&h1;
        }
        for (int i = tid; i < 128 * 8; i += 256) {
            int r = i >> 3, c16 = i & 7;
            cp_async16s(smem_base + FVS_OFF + r * 144 + c16 * 16,
                        Vg + (long long)r * S_ + k0 + c16 * 8);
        }
        asm volatile("cp.async.commit_group; cp.async.wait_group 0;" ::: "memory");
        __syncthreads();

        float sc[4][4];
        #pragma unroll
        for (int nt = 0; nt < 4; nt++)
            #pragma unroll
            for (int i = 0; i < 4; i++) sc[nt][i] = 0.f;
        #pragma unroll
        for (int kk = 0; kk < 96; kk += 8) {
            uint32_t af[4], bf[4][2];
            af[0] = qw[(wm + lr    ) * 100 + kk + lc];
            af[1] = qw[(wm + lr + 8) * 100 + kk + lc];
            af[2] = qw[(wm + lr    ) * 100 + kk + 4 + lc];
            af[3] = qw[(wm + lr + 8) * 100 + kk + 4 + lc];
            #pragma unroll
            for (int nt = 0; nt < 4; nt++) {
                int col = wn_qk + nt * 8 + lr;
                bf[nt][0] = kw[col * 100 + kk + lc];
                bf[nt][1] = kw[col * 100 + kk + 4 + lc];
            }
            #pragma unroll
            for (int nt = 0; nt < 4; nt++)
                mma_f16(sc[nt], af, bf[nt]);
        }
        #pragma unroll
        for (int nt = 0; nt < 4; nt++) {
            int c = wn_qk + nt * 8 + lc * 2;
            int r0 = wm + lr, r1 = wm + lr + 8;
            float v00 = sc[nt][0] * scale, v01 = sc[nt][1] * scale;
            float v10 = sc[nt][2] * scale, v11 = sc[nt][3] * scale;
            if (k0 + c     > q0 + r0) v00 = -1e30f;
            if (k0 + c + 1 > q0 + r0) v01 = -1e30f;
            if (k0 + c     > q0 + r1) v10 = -1e30f;
            if (k0 + c + 1 > q0 + r1) v11 = -1e30f;
            *(float2*)(Ss + r0 * 68 + c) = make_float2(v00, v01);
            *(float2*)(Ss + r1 * 68 + c) = make_float2(v10, v11);
        }
        __syncthreads();

        {
            int r = tid >> 2, p4 = tid & 3;
            int cb = p4 * 16;
            float mx = -1e30f;
            #pragma unroll
            for (int j = 0; j < 16; j++) mx = fmaxf(mx, Ss[r * 68 + cb + j]);
            mx = fmaxf(mx, __shfl_xor_sync(0xffffffffu, mx, 1));
            mx = fmaxf(mx, __shfl_xor_sync(0xffffffffu, mx, 2));
            float m_old = m_s[r];
            float m_new = fmaxf(m_old, mx);
            float alpha = __expf(m_old - m_new);
            float es = 0.f;
            #pragma unroll
            for (int j = 0; j < 16; j++) {
                float e = __expf(Ss[r * 68 + cb + j] - m_new);
                Ph[r * 72 + cb + j] = __float2half(e);
                es += e;
            }
            es += __shfl_xor_sync(0xffffffffu, es, 1);
            es += __shfl_xor_sync(0xffffffffu, es, 2);
            if (p4 == 0) {
                l_s[r] = l_s[r] * alpha + es;
                m_s[r] = m_new;
                a_s[r] = alpha;
            }
        }
        __syncthreads();

        {
            float a0 = a_s[wm + lr], a1 = a_s[wm + lr + 8];
            #pragma unroll
            for (int nt = 0; nt < 8; nt++) {
                oacc[nt][0] *= a0; oacc[nt][1] *= a0;
                oacc[nt][2] *= a1; oacc[nt][3] *= a1;
            }
            #pragma unroll
            for (int kk = 0; kk < 32; kk += 8) {
                uint32_t af[4], bf[8][2];
                af[0] = pw[(wm + lr    ) * 36 + kk + lc];
                af[1] = pw[(wm + lr + 8) * 36 + kk + lc];
                af[2] = pw[(wm + lr    ) * 36 + kk + 4 + lc];
                af[3] = pw[(wm + lr + 8) * 36 + kk + 4 + lc];
                #pragma unroll
                for (int nt = 0; nt < 8; nt++) {
                    int col = wn_pv + nt * 8 + lr;
                    bf[nt][0] = vw[col * 36 + kk + lc];
                    bf[nt][1] = vw[col * 36 + kk + 4 + lc];
                }
                #pragma unroll
                for (int nt = 0; nt < 8; nt++)
                    mma_f16(oacc[nt], af, bf[nt]);
            }
        }
    }
    __syncthreads();

    {
        float il0 = 1.f / l_s[wm + lr];
        float il1 = 1.f / l_s[wm + lr + 8];
        long long tok0 = (long long)b * S_ + q0 + wm + lr;
        long long tok1 = tok0 + 8;
        #pragma unroll
        for (int nt = 0; nt < 8; nt++) {
            int c = wn_pv + nt * 8 + lc * 2;
            __half2 o0 = __floats2half2_rn(tf32r(oacc[nt][0] * il0), tf32r(oacc[nt][1] * il0));
            __half2 o1 = __floats2half2_rn(tf32r(oacc[nt][2] * il1), tf32r(oacc[nt][3] * il1));
            *(__half2*)(outfl + tok0 * (H_*DV_) + h * DV_ + c) = o0;
            *(__half2*)(outfl + tok1 * (H_*DV_) + h * DV_ + c) = o1;
        }
    }
}

static inline dim3 gh(int M, int N) { return dim3((N + 255) / 256, M / 128, 1); }

extern "C" void kernel_launch(void* const* d_in, const int* in_sizes, int n_in,
                              void* d_out, int out_size)
{
    const float* hidden = (const float*)d_in[0];
    const int*   pos    = (const int*)  d_in[1];
    const float* Wq     = (const float*)d_in[2];
    const float* Wkva   = (const float*)d_in[3];
    const float* w_kvln = (const float*)d_in[4];
    const float* Wkvb   = (const float*)d_in[5];
    const float* Wo     = (const float*)d_in[6];
    const float* Wg     = (const float*)d_in[7];
    const float* Wu     = (const float*)d_in[8];
    const float* Wd     = (const float*)d_in[9];
    const float* w_ln1  = (const float*)d_in[10];
    const float* w_ln2  = (const float*)d_in[11];
    float* out = (float*)d_out;

    float *p_q, *p_ckv, *p_kv, *p_x2, *p_g;
    __half *p_xln, *p_cln, *p_afl, *p_y, *p_a;
    __half *t_wq, *t_wkva, *t_wkvb, *t_wo, *t_wg, *t_wu, *t_wd;
    cudaGetSymbolAddress((void**)&p_xln, g_xln);
    cudaGetSymbolAddress((void**)&p_q,   g_q);
    cudaGetSymbolAddress((void**)&p_ckv, g_ckv);
    cudaGetSymbolAddress((void**)&p_cln, g_cln);
    cudaGetSymbolAddress((void**)&p_kv,  g_kv);
    cudaGetSymbolAddress((void**)&p_afl, g_attnfl);
    cudaGetSymbolAddress((void**)&p_x2,  g_x2);
    cudaGetSymbolAddress((void**)&p_y,   g_y);
    cudaGetSymbolAddress((void**)&p_g,   g_gate);
    cudaGetSymbolAddress((void**)&p_a,   g_act);
    cudaGetSymbolAddress((void**)&t_wq,   g_tWq);
    cudaGetSymbolAddress((void**)&t_wkva, g_tWkva);
    cudaGetSymbolAddress((void**)&t_wkvb, g_tWkvb);
    cudaGetSymbolAddress((void**)&t_wo,   g_tWo);
    cudaGetSymbolAddress((void**)&t_wg,   g_tWg);
    cudaGetSymbolAddress((void**)&t_wu,   g_tWu);
    cudaGetSymbolAddress((void**)&t_wd,   g_tWd);

    cudaFuncSetAttribute(gemm_h<0,float>,  cudaFuncAttributeMaxDynamicSharedMemorySize, HGEMM_SMEM);
    cudaFuncSetAttribute(gemm_h<1,float>,  cudaFuncAttributeMaxDynamicSharedMemorySize, HGEMM_SMEM);
    cudaFuncSetAttribute(gemm_h<2,__half>, cudaFuncAttributeMaxDynamicSharedMemorySize, HGEMM_SMEM);
    cudaFuncSetAttribute(flash_h_kernel,   cudaFuncAttributeMaxDynamicSharedMemorySize, FLASH_SMEM);

    init_invfreq2_kernel<<<1, 32>>>();
    trunc_kernel<<<1184, 256>>>(Wq,   t_wq,   (long long)H_*DQ_*HID_/4);
    trunc_kernel<<<1184, 256>>>(Wkva, t_wkva, (long long)(RANK_+DROPE_)*HID_/4);
    trunc_kernel<<<1184, 256>>>(Wkvb, t_wkvb, (long long)H_*(DNOPE_+DV_)*RANK_/4);
    rmsnorm_h_kernel<<<TOK_, 256>>>(hidden, w_ln1, p_xln, HID_, HID_);
    gemm_h<0,float><<<gh(TOK_, H_*DQ_), 256, HGEMM_SMEM>>>(p_xln, t_wq, p_q, nullptr,
        TOK_, H_*DQ_, HID_);
    gemm_h<0,float><<<gh(TOK_, RANK_+DROPE_), 256, HGEMM_SMEM>>>(p_xln, t_wkva, p_ckv, nullptr,
        TOK_, RANK_+DROPE_, HID_);

    rmsnorm_h_kernel<<<TOK_, 256>>>(p_ckv, w_kvln, p_cln, RANK_, RANK_+DROPE_);

    gemm_h<0,float><<<gh(TOK_, H_*(DNOPE_+DV_)), 256, HGEMM_SMEM>>>(p_cln, t_wkvb, p_kv, nullptr,
        TOK_, H_*(DNOPE_+DV_), RANK_);

    rope_q_kernel<<<(TOK_*H_ + 255)/256, 256>>>(pos);
    rope_k_kernel<<<(TOK_ + 255)/256, 256>>>(pos);
    transpose_v_kernel<<<dim3(S_/32, DV_/32, B_*H_), dim3(32, 8)>>>();

    flash_h_kernel<<<dim3(S_/64, B_*H_), 256, FLASH_SMEM>>>(p_afl);

    trunc_kernel<<<1184, 256>>>(Wo, t_wo, (long long)HID_*H_*DV_/4);
    gemm_h<1,float><<<gh(TOK_, HID_), 256, HGEMM_SMEM>>>(p_afl, t_wo, p_x2, hidden, TOK_, HID_, H_*DV_);

    rmsnorm_h_kernel<<<TOK_, 256>>>(p_x2, w_ln2, p_y, HID_, HID_);

    trunc_kernel<<<1184, 256>>>(Wg, t_wg, (long long)INTER_*HID_/4);
    gemm_h<0,float><<<gh(TOK_, INTER_), 256, HGEMM_SMEM>>>(p_y, t_wg, p_g, nullptr, TOK_, INTER_, HID_);
    trunc_kernel<<<1184, 256>>>(Wu, t_wu, (long long)INTER_*HID_/4);
    gemm_h<2,__half><<<gh(TOK_, INTER_), 256, HGEMM_SMEM>>>(p_y, t_wu, p_a, p_g, TOK_, INTER_, HID_);

    trunc_kernel<<<1184, 256>>>(Wd, t_wd, (long long)HID_*INTER_/4);
    gemm_h<1,float><<<gh(TOK_, HID_), 256, HGEMM_SMEM>>>(p_a, t_wd, out, p_x2, TOK_, HID_, INTER_);
}

// round 16
// speedup vs baseline: 25.5171x; 1.2139x over previous
#include <cuda_runtime.h>
#include <cuda_fp16.h>
#include <math.h>
#include <stdint.h>

#define B_      2
#define S_      2048
#define HID_    2048
#define H_      16
#define DQ_     192
#define DNOPE_  128
#define DROPE_  64
#define DV_     128
#define RANK_   512
#define INTER_  10944
#define TOK_    (B_*S_)

__device__ __forceinline__ float tf32r(float x) {
    float r;
    asm("cvt.rna.tf32.f32 %0, %1;" : "=f"(r) : "f"(x));
    return r;
}

__device__ __forceinline__ void mma_f16(float* c, const uint32_t* a, const uint32_t* b) {
    asm volatile(
        "mma.sync.aligned.m16n8k16.row.col.f32.f16.f16.f32 "
        "{%0,%1,%2,%3}, {%4,%5,%6,%7}, {%8,%9}, {%0,%1,%2,%3};\n"
        : "+f"(c[0]), "+f"(c[1]), "+f"(c[2]), "+f"(c[3])
        : "r"(a[0]), "r"(a[1]), "r"(a[2]), "r"(a[3]), "r"(b[0]), "r"(b[1]));
}

__device__ __forceinline__ void ldsm4(uint32_t& r0, uint32_t& r1, uint32_t& r2, uint32_t& r3, uint32_t addr) {
    asm volatile("ldmatrix.sync.aligned.m8n8.x4.shared.b16 {%0,%1,%2,%3}, [%4];"
        : "=r"(r0), "=r"(r1), "=r"(r2), "=r"(r3) : "r"(addr));
}

__device__ __forceinline__ void cp_async16s(uint32_t saddr, const void* g) {
    asm volatile("cp.async.cg.shared.global [%0], [%1], 16;" :: "r"(saddr), "l"(g));
}

__device__ __forceinline__ uint32_t smem_to_u32(const void* p) {
    uint32_t a;
    asm("{ .reg .u64 t; cvta.to.shared.u64 t, %1; cvt.u32.u64 %0, t; }" : "=r"(a) : "l"(p));
    return a;
}

// ---------------- device scratch ----------------
__device__ float  g_invfreq[32];
__device__ __half g_xln    [TOK_*HID_];
__device__ float  g_q      [TOK_*H_*DQ_];
__device__ float  g_ckv    [TOK_*(RANK_+DROPE_)];
__device__ __half g_cln    [TOK_*RANK_];
__device__ float  g_kv     [TOK_*H_*(DNOPE_+DV_)];
__device__ __half g_Qh     [(size_t)B_*H_*S_*DQ_];
__device__ __half g_Kh     [(size_t)B_*H_*S_*DQ_];
__device__ __half g_Vt     [(size_t)B_*H_*DV_*S_];
__device__ __half g_attnfl [TOK_*H_*DV_];
__device__ float  g_x2     [TOK_*HID_];
__device__ __half g_y      [TOK_*HID_];
__device__ float  g_gate   [TOK_*INTER_];
__device__ __half g_act    [TOK_*INTER_];
__device__ __half g_tWq   [(size_t)H_*DQ_*HID_];
__device__ __half g_tWkva [(size_t)(RANK_+DROPE_)*HID_];
__device__ __half g_tWkvb [(size_t)H_*(DNOPE_+DV_)*RANK_];
__device__ __half g_tWo   [(size_t)HID_*H_*DV_];
__device__ __half g_tWg   [(size_t)INTER_*HID_];
__device__ __half g_tWu   [(size_t)INTER_*HID_];
__device__ __half g_tWd   [(size_t)HID_*INTER_];

// ---- weight pre-truncation: f32 -> tf32 round -> f16 (exact) ----
__global__ void trunc_kernel(const float* __restrict__ src, __half* __restrict__ dst, long long n4) {
    long long i = (long long)blockIdx.x * blockDim.x + threadIdx.x;
    long long stride = (long long)gridDim.x * blockDim.x;
    for (; i < n4; i += stride) {
        float4 v = ((const float4*)src)[i];
        __half2 h0 = __floats2half2_rn(tf32r(v.x), tf32r(v.y));
        __half2 h1 = __floats2half2_rn(tf32r(v.z), tf32r(v.w));
        uint2 o;
        o.x = *(uint32_t*)&h0; o.y = *(uint32_t*)&h1;
        ((uint2*)dst)[i] = o;
    }
}

// ---- yarn inv_freq ----
__global__ void init_invfreq2_kernel() {
    int j = threadIdx.x;
    if (j >= 32) return;
    const double dim = 64.0, base = 10000.0, orig_max = 4096.0;
    const double two_pi = 6.283185307179586476925286766559;
    double cd_fast = dim * log(orig_max / (32.0 * two_pi)) / (2.0 * log(base));
    double cd_slow = dim * log(orig_max / ( 1.0 * two_pi)) / (2.0 * log(base));
    double lowd  = floor(cd_fast); if (lowd < 0.0) lowd = 0.0;
    double highd = ceil(cd_slow);  if (highd > dim - 1.0) highd = dim - 1.0;
    double hid = (lowd == highd) ? highd + 0.001 : highd;
    double ar = (2.0 * (double)j) / dim;
    double freq_extra = 1.0 / pow(base, ar);
    double freq_inter = 1.0 / (40.0 * pow(base, ar));
    double ramp = ((double)j - lowd) / (hid - lowd);
    if (ramp < 0.0) ramp = 0.0;
    if (ramp > 1.0) ramp = 1.0;
    double mask = 1.0 - ramp;
    g_invfreq[j] = (float)(freq_inter * (1.0 - mask) + freq_extra * mask);
}

// ---- RMSNorm -> half output ----
__global__ void rmsnorm_h_kernel(const float* __restrict__ x, const float* __restrict__ w,
                                 __half* __restrict__ out, int dim, int in_stride)
{
    const long long row = blockIdx.x;
    const float* xr = x + row * (long long)in_stride;
    __shared__ float buf[256];
    float partial = 0.f;
    for (int i = threadIdx.x; i < dim; i += 256) { float v = xr[i]; partial += v * v; }
    buf[threadIdx.x] = partial;
    __syncthreads();
    for (int stride = 128; stride > 0; stride >>= 1) {
        if (threadIdx.x < stride) buf[threadIdx.x] += buf[threadIdx.x + stride];
        __syncthreads();
    }
    float scale = rsqrtf(buf[0] / (float)dim + 1e-6f);
    for (int i = threadIdx.x; i < dim; i += 256)
        out[row * (long long)dim + i] = __float2half(tf32r(xr[i] * scale * w[i]));
}

// ---- fp16 tensor-core GEMM, 128x128 tile, 2 CTAs/SM ----
// C = A[M,K] @ Bw[N,K]^T. BK=64, double-buffered cp.async, ldmatrix frags.
// MODE 0: plain (CT=float)  MODE 1: +=R (CT=float)  MODE 2: C=half(tf32(silu(R)*acc)) (CT=half)
#define H2_STAGE  (128*144)                       // bytes per operand per stage
#define H2GEMM_SMEM (4*H2_STAGE)                  // 73728
template<int MODE, typename CT>
__global__ void __launch_bounds__(256, 2) gemm_h2(
    const __half* __restrict__ A, const __half* __restrict__ Bw,
    CT* __restrict__ C, const float* __restrict__ R,
    int M, int N, int K)
{
    extern __shared__ char smem[];
    const uint32_t smem_base = smem_to_u32(smem);
    const uint32_t aoff[2] = {0u, 2u*H2_STAGE};
    const uint32_t boff[2] = {1u*H2_STAGE, 3u*H2_STAGE};

    const int m0 = blockIdx.y * 128, n0 = blockIdx.x * 128;
    const int tid = threadIdx.x;
    const int warp = tid >> 5, lane = tid & 31;
    const int wm = (warp >> 2) * 64;     // 2 warp rows x 64
    const int wn = (warp & 3) * 32;      // 4 warp cols x 32
    const int lr = lane >> 2;
    const int lc = lane & 3;
    const uint32_t lq = lane >> 3, l8 = lane & 7;
    const uint32_t a_lane = ((lq & 1) * 8 + l8) * 144 + (lq >> 1) * 16;
    const uint32_t b_lane = ((lq >> 1) * 8 + l8) * 144 + (lq & 1) * 16;

    float acc[4][4][4];
    #pragma unroll
    for (int mt = 0; mt < 4; mt++)
        #pragma unroll
        for (int nt = 0; nt < 4; nt++)
            #pragma unroll
            for (int i = 0; i < 4; i++) acc[mt][nt][i] = 0.f;

    const int KT = K >> 6;

    // prefetch chunk 0 -> stage 0 (A and B each: 128 rows x 8 chunks = 4/thread)
    {
        #pragma unroll
        for (int i = 0; i < 4; i++) {
            int idx = tid + i * 256;
            int r = idx >> 3, c16 = idx & 7;
            cp_async16s(smem_base + aoff[0] + r * 144 + c16 * 16,
                        A + (long long)(m0 + r) * K + c16 * 8);
            int gn = n0 + r; if (gn >= N) gn = N - 1;
            cp_async16s(smem_base + boff[0] + r * 144 + c16 * 16,
                        Bw + (long long)gn * K + c16 * 8);
        }
        asm volatile("cp.async.commit_group;");
    }

    for (int kt = 0; kt < KT; kt++) {
        const int st = kt & 1;
        if (kt + 1 < KT) {
            const int k0 = (kt + 1) << 6;
            const int nx = st ^ 1;
            #pragma unroll
            for (int i = 0; i < 4; i++) {
                int idx = tid + i * 256;
                int r = idx >> 3, c16 = idx & 7;
                cp_async16s(smem_base + aoff[nx] + r * 144 + c16 * 16,
                            A + (long long)(m0 + r) * K + k0 + c16 * 8);
                int gn = n0 + r; if (gn >= N) gn = N - 1;
                cp_async16s(smem_base + boff[nx] + r * 144 + c16 * 16,
                            Bw + (long long)gn * K + k0 + c16 * 8);
            }
            asm volatile("cp.async.commit_group;");
            asm volatile("cp.async.wait_group 1;");
        } else {
            asm volatile("cp.async.wait_group 0;");
        }
        __syncthreads();

        const uint32_t ab = smem_base + aoff[st];
        const uint32_t bb = smem_base + boff[st];
        #pragma unroll
        for (int kw = 0; kw < 32; kw += 8) {
            uint32_t af[4][4], bf[4][2];
            #pragma unroll
            for (int mt = 0; mt < 4; mt++)
                ldsm4(af[mt][0], af[mt][1], af[mt][2], af[mt][3],
                      ab + (wm + mt * 16) * 144 + kw * 4 + a_lane);
            #pragma unroll
            for (int ntp = 0; ntp < 2; ntp++)
                ldsm4(bf[2*ntp][0], bf[2*ntp][1], bf[2*ntp+1][0], bf[2*ntp+1][1],
                      bb + (wn + ntp * 16) * 144 + kw * 4 + b_lane);
            #pragma unroll
            for (int mt = 0; mt < 4; mt++)
                #pragma unroll
                for (int nt = 0; nt < 4; nt++)
                    mma_f16(acc[mt][nt], af[mt], bf[nt]);
        }
        __syncthreads();
    }

    #pragma unroll
    for (int mt = 0; mt < 4; mt++) {
        #pragma unroll
        for (int nt = 0; nt < 4; nt++) {
            int mmb = m0 + wm + mt * 16 + lr;
            int nn = n0 + wn + nt * 8 + lc * 2;
            #pragma unroll
            for (int half_ = 0; half_ < 2; half_++) {
                int mrow = mmb + half_ * 8;
                #pragma unroll
                for (int q = 0; q < 2; q++) {
                    int nc = nn + q;
                    if (nc >= N) continue;
                    float v = acc[mt][nt][half_ * 2 + q];
                    long long off = (long long)mrow * N + nc;
                    if (MODE == 1) {
                        C[off] = (CT)(v + R[off]);
                    } else if (MODE == 2) {
                        float gg = R[off];
                        float sig = 1.f / (1.f + expf(-gg));
                        C[off] = (CT)__float2half(tf32r(gg * sig * v));
                    } else {
                        C[off] = (CT)v;
                    }
                }
            }
        }
    }
}

// ---- RoPE in place ----
__global__ void rope_q_kernel(const int* __restrict__ pos_ids) {
    int idx = blockIdx.x * 256 + threadIdx.x;
    if (idx >= TOK_ * H_) return;
    int tok = idx / H_;
    float* x = g_q + (long long)idx * DQ_ + DNOPE_;
    float pos = (float)pos_ids[tok];
    float xv[64];
    #pragma unroll
    for (int i = 0; i < 64; i++) xv[i] = x[i];
    #pragma unroll
    for (int j = 0; j < 32; j++) {
        float th = pos * g_invfreq[j];
        float c = cosf(th), sn = sinf(th);
        float x1 = xv[2*j], x2 = xv[2*j+1];
        x[j]      = x1 * c - x2 * sn;
        x[j + 32] = x2 * c + x1 * sn;
    }
}

__global__ void rope_k_kernel(const int* __restrict__ pos_ids) {
    int tok = blockIdx.x * 256 + threadIdx.x;
    if (tok >= TOK_) return;
    float* x = g_ckv + (long long)tok * (RANK_ + DROPE_) + RANK_;
    float pos = (float)pos_ids[tok];
    float xv[64];
    #pragma unroll
    for (int i = 0; i < 64; i++) xv[i] = x[i];
    #pragma unroll
    for (int j = 0; j < 32; j++) {
        float th = pos * g_invfreq[j];
        float c = cosf(th), sn = sinf(th);
        float x1 = xv[2*j], x2 = xv[2*j+1];
        x[j]      = x1 * c - x2 * sn;
        x[j + 32] = x2 * c + x1 * sn;
    }
}

// ---- pack Q/K to half [z][s][192] (after rope) ----
__global__ void pack_q_h_kernel() {
    long long idx = (long long)blockIdx.x * 256 + threadIdx.x;
    const long long total = (long long)TOK_ * H_ * 48;
    if (idx >= total) return;
    int d4 = (int)(idx % 48);
    long long t2 = idx / 48;
    int h = (int)(t2 % H_);
    long long tok = t2 / H_;
    int b = (int)(tok / S_), s = (int)(tok % S_);
    float4 v = *(const float4*)(g_q + (tok * H_ + h) * DQ_ + d4 * 4);
    __half2 h0 = __floats2half2_rn(v.x, v.y);
    __half2 h1 = __floats2half2_rn(v.z, v.w);
    uint2 o; o.x = *(uint32_t*)&h0; o.y = *(uint32_t*)&h1;
    *(uint2*)(g_Qh + (((long long)(b * H_ + h)) * S_ + s) * DQ_ + d4 * 4) = o;
}

__global__ void pack_k_h_kernel() {
    long long idx = (long long)blockIdx.x * 256 + threadIdx.x;
    const long long total = (long long)TOK_ * H_ * 48;
    if (idx >= total) return;
    int d4 = (int)(idx % 48);
    long long t2 = idx / 48;
    int h = (int)(t2 % H_);
    long long tok = t2 / H_;
    int b = (int)(tok / S_), s = (int)(tok % S_);
    float4 v;
    if (d4 < 32) v = *(const float4*)(g_kv + (tok * H_ + h) * (DNOPE_ + DV_) + d4 * 4);
    else         v = *(const float4*)(g_ckv + tok * (RANK_ + DROPE_) + RANK_ + (d4 - 32) * 4);
    __half2 h0 = __floats2half2_rn(v.x, v.y);
    __half2 h1 = __floats2half2_rn(v.z, v.w);
    uint2 o; o.x = *(uint32_t*)&h0; o.y = *(uint32_t*)&h1;
    *(uint2*)(g_Kh + (((long long)(b * H_ + h)) * S_ + s) * DQ_ + d4 * 4) = o;
}

// ---- V transpose ----
__global__ void transpose_v_kernel() {
    __shared__ float t[32][33];
    int z = blockIdx.z;
    int d0 = blockIdx.y * 32, s0 = blockIdx.x * 32;
    int b = z >> 4, h = z & 15;
    int tx = threadIdx.x, ty0 = threadIdx.y;
    #pragma unroll
    for (int dy = 0; dy < 32; dy += 8) {
        int ty = ty0 + dy;
        t[ty][tx] = g_kv[(((long long)b * S_ + s0 + ty) * H_ + h) * (DNOPE_ + DV_) + DNOPE_ + d0 + tx];
    }
    __syncthreads();
    #pragma unroll
    for (int dy = 0; dy < 32; dy += 8) {
        int ty = ty0 + dy;
        g_Vt[((long long)z * DV_ + d0 + ty) * S_ + s0 + tx] = __float2half(t[tx][ty]);
    }
}

// ---- fp16 flash attention, half inputs via cp.async ----
#define FQS_OFF 0                         // Q: 64 rows x 400B (stride 100 words)
#define FKS_OFF 25600
#define FVS_OFF 51200                     // V: 128 rows x 144B
#define FSS_OFF 69632                     // scores fp32 64 x 68
#define FPH_OFF 87040                     // P half 64 x 72
#define FML_OFF 96256
#define FLASH_SMEM (FML_OFF + 768)

__global__ void __launch_bounds__(256) flash_h_kernel(__half* __restrict__ outfl)
{
    extern __shared__ char smem[];
    uint32_t* qw = (uint32_t*)(smem + FQS_OFF);
    uint32_t* kw = (uint32_t*)(smem + FKS_OFF);
    uint32_t* vw = (uint32_t*)(smem + FVS_OFF);
    float*    Ss = (float*)(smem + FSS_OFF);
    __half*   Ph = (__half*)(smem + FPH_OFF);
    uint32_t* pw = (uint32_t*)(smem + FPH_OFF);
    float*    m_s = (float*)(smem + FML_OFF);
    float*    l_s = m_s + 64;
    float*    a_s = l_s + 64;
    const uint32_t smem_base = smem_to_u32(smem);

    const int z = blockIdx.y;
    const int b = z >> 4, h = z & 15;
    const int qt = gridDim.x - 1 - blockIdx.x;
    const int q0 = qt * 64;
    const int tid = threadIdx.x;
    const int warp = tid >> 5, lane = tid & 31;
    const int lr = lane >> 2, lc = lane & 3;
    const int wm = (warp & 3) * 16;
    const int wn_qk = (warp >> 2) * 32;
    const int wn_pv = (warp >> 2) * 64;
    const float scale = 0.07216878364870323f;
    const __half* Qg = g_Qh + ((long long)z * S_ + q0) * DQ_;
    const __half* Kg = g_Kh + (long long)z * S_ * DQ_;
    const __half* Vg = g_Vt + (long long)z * DV_ * S_;

    // Q tile: 64 rows x 24 chunks of 16B
    for (int i = tid; i < 64 * 24; i += 256) {
        int r = i / 24, c = i % 24;
        cp_async16s(smem_base + FQS_OFF + r * 400 + c * 16,
                    Qg + (long long)r * DQ_ + c * 8);
    }
    asm volatile("cp.async.commit_group;");
    if (tid < 64) { m_s[tid] = -1e30f; l_s[tid] = 0.f; }

    float oacc[8][4];
    #pragma unroll
    for (int nt = 0; nt < 8; nt++)
        #pragma unroll
        for (int i = 0; i < 4; i++) oacc[nt][i] = 0.f;

    for (int t = 0; t <= qt; t++) {
        const int k0 = t * 64;
        __syncthreads();
        for (int i = tid; i < 64 * 24; i += 256) {
            int r = i / 24, c = i % 24;
            cp_async16s(smem_base + FKS_OFF + r * 400 + c * 16,
                        Kg + (long long)(k0 + r) * DQ_ + c * 8);
        }
        for (int i = tid; i < 128 * 8; i += 256) {
            int r = i >> 3, c16 = i & 7;
            cp_async16s(smem_base + FVS_OFF + r * 144 + c16 * 16,
                        Vg + (long long)r * S_ + k0 + c16 * 8);
        }
        asm volatile("cp.async.commit_group; cp.async.wait_group 0;" ::: "memory");
        __syncthreads();

        float sc[4][4];
        #pragma unroll
        for (int nt = 0; nt < 4; nt++)
            #pragma unroll
            for (int i = 0; i < 4; i++) sc[nt][i] = 0.f;
        #pragma unroll
        for (int kk = 0; kk < 96; kk += 8) {
            uint32_t af[4], bf[4][2];
            af[0] = qw[(wm + lr    ) * 100 + kk + lc];
            af[1] = qw[(wm + lr + 8) * 100 + kk + lc];
            af[2] = qw[(wm + lr    ) * 100 + kk + 4 + lc];
            af[3] = qw[(wm + lr + 8) * 100 + kk + 4 + lc];
            #pragma unroll
            for (int nt = 0; nt < 4; nt++) {
                int col = wn_qk + nt * 8 + lr;
                bf[nt][0] = kw[col * 100 + kk + lc];
                bf[nt][1] = kw[col * 100 + kk + 4 + lc];
            }
            #pragma unroll
            for (int nt = 0; nt < 4; nt++)
                mma_f16(sc[nt], af, bf[nt]);
        }
        #pragma unroll
        for (int nt = 0; nt < 4; nt++) {
            int c = wn_qk + nt * 8 + lc * 2;
            int r0 = wm + lr, r1 = wm + lr + 8;
            float v00 = sc[nt][0] * scale, v01 = sc[nt][1] * scale;
            float v10 = sc[nt][2] * scale, v11 = sc[nt][3] * scale;
            if (k0 + c     > q0 + r0) v00 = -1e30f;
            if (k0 + c + 1 > q0 + r0) v01 = -1e30f;
            if (k0 + c     > q0 + r1) v10 = -1e30f;
            if (k0 + c + 1 > q0 + r1) v11 = -1e30f;
            *(float2*)(Ss + r0 * 68 + c) = make_float2(v00, v01);
            *(float2*)(Ss + r1 * 68 + c) = make_float2(v10, v11);
        }
        __syncthreads();

        {
            int r = tid >> 2, p4 = tid & 3;
            int cb = p4 * 16;
            float mx = -1e30f;
            #pragma unroll
            for (int j = 0; j < 16; j++) mx = fmaxf(mx, Ss[r * 68 + cb + j]);
            mx = fmaxf(mx, __shfl_xor_sync(0xffffffffu, mx, 1));
            mx = fmaxf(mx, __shfl_xor_sync(0xffffffffu, mx, 2));
            float m_old = m_s[r];
            float m_new = fmaxf(m_old, mx);
            float alpha = __expf(m_old - m_new);
            float es = 0.f;
            #pragma unroll
            for (int j = 0; j < 16; j++) {
                float e = __expf(Ss[r * 68 + cb + j] - m_new);
                Ph[r * 72 + cb + j] = __float2half(e);
                es += e;
            }
            es += __shfl_xor_sync(0xffffffffu, es, 1);
            es += __shfl_xor_sync(0xffffffffu, es, 2);
            if (p4 == 0) {
                l_s[r] = l_s[r] * alpha + es;
                m_s[r] = m_new;
                a_s[r] = alpha;
            }
        }
        __syncthreads();

        {
            float a0 = a_s[wm + lr], a1 = a_s[wm + lr + 8];
            #pragma unroll
            for (int nt = 0; nt < 8; nt++) {
                oacc[nt][0] *= a0; oacc[nt][1] *= a0;
                oacc[nt][2] *= a1; oacc[nt][3] *= a1;
            }
            #pragma unroll
            for (int kk = 0; kk < 32; kk += 8) {
                uint32_t af[4], bf[8][2];
                af[0] = pw[(wm + lr    ) * 36 + kk + lc];
                af[1] = pw[(wm + lr + 8) * 36 + kk + lc];
                af[2] = pw[(wm + lr    ) * 36 + kk + 4 + lc];
                af[3] = pw[(wm + lr + 8) * 36 + kk + 4 + lc];
                #pragma unroll
                for (int nt = 0; nt < 8; nt++) {
                    int col = wn_pv + nt * 8 + lr;
                    bf[nt][0] = vw[col * 36 + kk + lc];
                    bf[nt][1] = vw[col * 36 + kk + 4 + lc];
                }
                #pragma unroll
                for (int nt = 0; nt < 8; nt++)
                    mma_f16(oacc[nt], af, bf[nt]);
            }
        }
    }
    __syncthreads();

    {
        float il0 = 1.f / l_s[wm + lr];
        float il1 = 1.f / l_s[wm + lr + 8];
        long long tok0 = (long long)b * S_ + q0 + wm + lr;
        long long tok1 = tok0 + 8;
        #pragma unroll
        for (int nt = 0; nt < 8; nt++) {
            int c = wn_pv + nt * 8 + lc * 2;
            __half2 o0 = __floats2half2_rn(tf32r(oacc[nt][0] * il0), tf32r(oacc[nt][1] * il0));
            __half2 o1 = __floats2half2_rn(tf32r(oacc[nt][2] * il1), tf32r(oacc[nt][3] * il1));
            *(__half2*)(outfl + tok0 * (H_*DV_) + h * DV_ + c) = o0;
            *(__half2*)(outfl + tok1 * (H_*DV_) + h * DV_ + c) = o1;
        }
    }
}

static inline dim3 g128(int M, int N) { return dim3((N + 127) / 128, M / 128, 1); }

extern "C" void kernel_launch(void* const* d_in, const int* in_sizes, int n_in,
                              void* d_out, int out_size)
{
    const float* hidden = (const float*)d_in[0];
    const int*   pos    = (const int*)  d_in[1];
    const float* Wq     = (const float*)d_in[2];
    const float* Wkva   = (const float*)d_in[3];
    const float* w_kvln = (const float*)d_in[4];
    const float* Wkvb   = (const float*)d_in[5];
    const float* Wo     = (const float*)d_in[6];
    const float* Wg     = (const float*)d_in[7];
    const float* Wu     = (const float*)d_in[8];
    const float* Wd     = (const float*)d_in[9];
    const float* w_ln1  = (const float*)d_in[10];
    const float* w_ln2  = (const float*)d_in[11];
    float* out = (float*)d_out;

    float *p_q, *p_ckv, *p_kv, *p_x2, *p_g;
    __half *p_xln, *p_cln, *p_afl, *p_y, *p_a;
    __half *t_wq, *t_wkva, *t_wkvb, *t_wo, *t_wg, *t_wu, *t_wd;
    cudaGetSymbolAddress((void**)&p_xln, g_xln);
    cudaGetSymbolAddress((void**)&p_q,   g_q);
    cudaGetSymbolAddress((void**)&p_ckv, g_ckv);
    cudaGetSymbolAddress((void**)&p_cln, g_cln);
    cudaGetSymbolAddress((void**)&p_kv,  g_kv);
    cudaGetSymbolAddress((void**)&p_afl, g_attnfl);
    cudaGetSymbolAddress((void**)&p_x2,  g_x2);
    cudaGetSymbolAddress((void**)&p_y,   g_y);
    cudaGetSymbolAddress((void**)&p_g,   g_gate);
    cudaGetSymbolAddress((void**)&p_a,   g_act);
    cudaGetSymbolAddress((void**)&t_wq,   g_tWq);
    cudaGetSymbolAddress((void**)&t_wkva, g_tWkva);
    cudaGetSymbolAddress((void**)&t_wkvb, g_tWkvb);
    cudaGetSymbolAddress((void**)&t_wo,   g_tWo);
    cudaGetSymbolAddress((void**)&t_wg,   g_tWg);
    cudaGetSymbolAddress((void**)&t_wu,   g_tWu);
    cudaGetSymbolAddress((void**)&t_wd,   g_tWd);

    cudaFuncSetAttribute(gemm_h2<0,float>,  cudaFuncAttributeMaxDynamicSharedMemorySize, H2GEMM_SMEM);
    cudaFuncSetAttribute(gemm_h2<1,float>,  cudaFuncAttributeMaxDynamicSharedMemorySize, H2GEMM_SMEM);
    cudaFuncSetAttribute(gemm_h2<2,__half>, cudaFuncAttributeMaxDynamicSharedMemorySize, H2GEMM_SMEM);
    cudaFuncSetAttribute(flash_h_kernel,    cudaFuncAttributeMaxDynamicSharedMemorySize, FLASH_SMEM);

    init_invfreq2_kernel<<<1, 32>>>();
    trunc_kernel<<<1184, 256>>>(Wq,   t_wq,   (long long)H_*DQ_*HID_/4);
    trunc_kernel<<<1184, 256>>>(Wkva, t_wkva, (long long)(RANK_+DROPE_)*HID_/4);
    trunc_kernel<<<1184, 256>>>(Wkvb, t_wkvb, (long long)H_*(DNOPE_+DV_)*RANK_/4);
    rmsnorm_h_kernel<<<TOK_, 256>>>(hidden, w_ln1, p_xln, HID_, HID_);
    gemm_h2<0,float><<<g128(TOK_, H_*DQ_), 256, H2GEMM_SMEM>>>(p_xln, t_wq, p_q, nullptr,
        TOK_, H_*DQ_, HID_);
    gemm_h2<0,float><<<g128(TOK_, RANK_+DROPE_), 256, H2GEMM_SMEM>>>(p_xln, t_wkva, p_ckv, nullptr,
        TOK_, RANK_+DROPE_, HID_);

    rmsnorm_h_kernel<<<TOK_, 256>>>(p_ckv, w_kvln, p_cln, RANK_, RANK_+DROPE_);

    gemm_h2<0,float><<<g128(TOK_, H_*(DNOPE_+DV_)), 256, H2GEMM_SMEM>>>(p_cln, t_wkvb, p_kv, nullptr,
        TOK_, H_*(DNOPE_+DV_), RANK_);

    rope_q_kernel<<<(TOK_*H_ + 255)/256, 256>>>(pos);
    rope_k_kernel<<<(TOK_ + 255)/256, 256>>>(pos);
    {
        long long tp = (long long)TOK_ * H_ * 48;
        pack_q_h_kernel<<<(unsigned)((tp + 255)/256), 256>>>();
        pack_k_h_kernel<<<(unsigned)((tp + 255)/256), 256>>>();
    }
    transpose_v_kernel<<<dim3(S_/32, DV_/32, B_*H_), dim3(32, 8)>>>();

    flash_h_kernel<<<dim3(S_/64, B_*H_), 256, FLASH_SMEM>>>(p_afl);

    trunc_kernel<<<1184, 256>>>(Wo, t_wo, (long long)HID_*H_*DV_/4);
    gemm_h2<1,float><<<g128(TOK_, HID_), 256, H2GEMM_SMEM>>>(p_afl, t_wo, p_x2, hidden, TOK_, HID_, H_*DV_);

    rmsnorm_h_kernel<<<TOK_, 256>>>(p_x2, w_ln2, p_y, HID_, HID_);

    trunc_kernel<<<1184, 256>>>(Wg, t_wg, (long long)INTER_*HID_/4);
    gemm_h2<0,float><<<g128(TOK_, INTER_), 256, H2GEMM_SMEM>>>(p_y, t_wg, p_g, nullptr, TOK_, INTER_, HID_);
    trunc_kernel<<<1184, 256>>>(Wu, t_wu, (long long)INTER_*HID_/4);
    gemm_h2<2,__half><<<g128(TOK_, INTER_), 256, H2GEMM_SMEM>>>(p_y, t_wu, p_a, p_g, TOK_, INTER_, HID_);

    trunc_kernel<<<1184, 256>>>(Wd, t_wd, (long long)HID_*INTER_/4);
    gemm_h2<1,float><<<g128(TOK_, HID_), 256, H2GEMM_SMEM>>>(p_a, t_wd, out, p_x2, TOK_, HID_, INTER_);
}

// round 17
// speedup vs baseline: 27.0931x; 1.0618x over previous
#include <cuda_runtime.h>
#include <cuda_fp16.h>
#include <math.h>
#include <stdint.h>

#define B_      2
#define S_      2048
#define HID_    2048
#define H_      16
#define DQ_     192
#define DNOPE_  128
#define DROPE_  64
#define DV_     128
#define RANK_   512
#define INTER_  10944
#define TOK_    (B_*S_)

__device__ __forceinline__ float tf32r(float x) {
    float r;
    asm("cvt.rna.tf32.f32 %0, %1;" : "=f"(r) : "f"(x));
    return r;
}

__device__ __forceinline__ void mma_f16(float* c, const uint32_t* a, const uint32_t* b) {
    asm volatile(
        "mma.sync.aligned.m16n8k16.row.col.f32.f16.f16.f32 "
        "{%0,%1,%2,%3}, {%4,%5,%6,%7}, {%8,%9}, {%0,%1,%2,%3};\n"
        : "+f"(c[0]), "+f"(c[1]), "+f"(c[2]), "+f"(c[3])
        : "r"(a[0]), "r"(a[1]), "r"(a[2]), "r"(a[3]), "r"(b[0]), "r"(b[1]));
}

__device__ __forceinline__ void ldsm4(uint32_t& r0, uint32_t& r1, uint32_t& r2, uint32_t& r3, uint32_t addr) {
    asm volatile("ldmatrix.sync.aligned.m8n8.x4.shared.b16 {%0,%1,%2,%3}, [%4];"
        : "=r"(r0), "=r"(r1), "=r"(r2), "=r"(r3) : "r"(addr));
}

__device__ __forceinline__ void cp_async16s(uint32_t saddr, const void* g) {
    asm volatile("cp.async.cg.shared.global [%0], [%1], 16;" :: "r"(saddr), "l"(g));
}

__device__ __forceinline__ uint32_t smem_to_u32(const void* p) {
    uint32_t a;
    asm("{ .reg .u64 t; cvta.to.shared.u64 t, %1; cvt.u32.u64 %0, t; }" : "=r"(a) : "l"(p));
    return a;
}

// ---------------- device scratch ----------------
__device__ float  g_invfreq[32];
__device__ __half g_xln    [TOK_*HID_];
__device__ float  g_q      [TOK_*H_*DQ_];
__device__ float  g_ckv    [TOK_*(RANK_+DROPE_)];
__device__ __half g_cln    [TOK_*RANK_];
__device__ float  g_kv     [TOK_*H_*(DNOPE_+DV_)];
__device__ __half g_Qh     [(size_t)B_*H_*S_*DQ_];
__device__ __half g_Kh     [(size_t)B_*H_*S_*DQ_];
__device__ __half g_Vt     [(size_t)B_*H_*DV_*S_];
__device__ __half g_attnfl [TOK_*H_*DV_];
__device__ float  g_x2     [TOK_*HID_];
__device__ __half g_y      [TOK_*HID_];
__device__ __half g_act    [TOK_*INTER_];
__device__ __half g_tWq   [(size_t)H_*DQ_*HID_];
__device__ __half g_tWkva [(size_t)(RANK_+DROPE_)*HID_];
__device__ __half g_tWkvb [(size_t)H_*(DNOPE_+DV_)*RANK_];
__device__ __half g_tWo   [(size_t)HID_*H_*DV_];
__device__ __half g_tWg   [(size_t)INTER_*HID_];
__device__ __half g_tWu   [(size_t)INTER_*HID_];
__device__ __half g_tWd   [(size_t)HID_*INTER_];

// ---- weight pre-truncation: f32 -> tf32 round -> f16 (exact) ----
__global__ void trunc_kernel(const float* __restrict__ src, __half* __restrict__ dst, long long n4) {
    long long i = (long long)blockIdx.x * blockDim.x + threadIdx.x;
    long long stride = (long long)gridDim.x * blockDim.x;
    for (; i < n4; i += stride) {
        float4 v = ((const float4*)src)[i];
        __half2 h0 = __floats2half2_rn(tf32r(v.x), tf32r(v.y));
        __half2 h1 = __floats2half2_rn(tf32r(v.z), tf32r(v.w));
        uint2 o;
        o.x = *(uint32_t*)&h0; o.y = *(uint32_t*)&h1;
        ((uint2*)dst)[i] = o;
    }
}

// ---- yarn inv_freq ----
__global__ void init_invfreq2_kernel() {
    int j = threadIdx.x;
    if (j >= 32) return;
    const double dim = 64.0, base = 10000.0, orig_max = 4096.0;
    const double two_pi = 6.283185307179586476925286766559;
    double cd_fast = dim * log(orig_max / (32.0 * two_pi)) / (2.0 * log(base));
    double cd_slow = dim * log(orig_max / ( 1.0 * two_pi)) / (2.0 * log(base));
    double lowd  = floor(cd_fast); if (lowd < 0.0) lowd = 0.0;
    double highd = ceil(cd_slow);  if (highd > dim - 1.0) highd = dim - 1.0;
    double hid = (lowd == highd) ? highd + 0.001 : highd;
    double ar = (2.0 * (double)j) / dim;
    double freq_extra = 1.0 / pow(base, ar);
    double freq_inter = 1.0 / (40.0 * pow(base, ar));
    double ramp = ((double)j - lowd) / (hid - lowd);
    if (ramp < 0.0) ramp = 0.0;
    if (ramp > 1.0) ramp = 1.0;
    double mask = 1.0 - ramp;
    g_invfreq[j] = (float)(freq_inter * (1.0 - mask) + freq_extra * mask);
}

// ---- RMSNorm -> half output ----
__global__ void rmsnorm_h_kernel(const float* __restrict__ x, const float* __restrict__ w,
                                 __half* __restrict__ out, int dim, int in_stride)
{
    const long long row = blockIdx.x;
    const float* xr = x + row * (long long)in_stride;
    __shared__ float buf[256];
    float partial = 0.f;
    for (int i = threadIdx.x; i < dim; i += 256) { float v = xr[i]; partial += v * v; }
    buf[threadIdx.x] = partial;
    __syncthreads();
    for (int stride = 128; stride > 0; stride >>= 1) {
        if (threadIdx.x < stride) buf[threadIdx.x] += buf[threadIdx.x + stride];
        __syncthreads();
    }
    float scale = rsqrtf(buf[0] / (float)dim + 1e-6f);
    for (int i = threadIdx.x; i < dim; i += 256)
        out[row * (long long)dim + i] = __float2half(tf32r(xr[i] * scale * w[i]));
}

// ---- fp16 GEMM, 128x128 tile, 3-stage cp.async, 2 CTAs/SM ----
// MODE 0: plain (CT=float)  MODE 1: +=R (CT=float)
#define H3_STAGE  (2*128*144)                     // A+B per stage, bytes (36864)
#define H3GEMM_SMEM (3*H3_STAGE)                  // 110592
template<int MODE, typename CT>
__global__ void __launch_bounds__(256, 2) gemm_h3(
    const __half* __restrict__ A, const __half* __restrict__ Bw,
    CT* __restrict__ C, const float* __restrict__ R,
    int M, int N, int K)
{
    extern __shared__ char smem[];
    const uint32_t smem_base = smem_to_u32(smem);

    const int m0 = blockIdx.y * 128, n0 = blockIdx.x * 128;
    const int tid = threadIdx.x;
    const int warp = tid >> 5, lane = tid & 31;
    const int wm = (warp >> 2) * 64;
    const int wn = (warp & 3) * 32;
    const int lr = lane >> 2;
    const int lc = lane & 3;
    const uint32_t lq = lane >> 3, l8 = lane & 7;
    const uint32_t a_lane = ((lq & 1) * 8 + l8) * 144 + (lq >> 1) * 16;
    const uint32_t b_lane = ((lq >> 1) * 8 + l8) * 144 + (lq & 1) * 16;

    float acc[4][4][4];
    #pragma unroll
    for (int mt = 0; mt < 4; mt++)
        #pragma unroll
        for (int nt = 0; nt < 4; nt++)
            #pragma unroll
            for (int i = 0; i < 4; i++) acc[mt][nt][i] = 0.f;

    const int KT = K >> 6;

    // prefetch chunks 0,1 -> stages 0,1
    #pragma unroll
    for (int ps = 0; ps < 2; ps++) {
        const int k0 = ps << 6;
        const uint32_t ao = smem_base + ps * H3_STAGE;
        const uint32_t bo = ao + 128 * 144;
        #pragma unroll
        for (int i = 0; i < 4; i++) {
            int idx = tid + i * 256;
            int r = idx >> 3, c16 = idx & 7;
            cp_async16s(ao + r * 144 + c16 * 16, A + (long long)(m0 + r) * K + k0 + c16 * 8);
            int gn = n0 + r; if (gn >= N) gn = N - 1;
            cp_async16s(bo + r * 144 + c16 * 16, Bw + (long long)gn * K + k0 + c16 * 8);
        }
        asm volatile("cp.async.commit_group;");
    }

    int st = 0, sl = 2;
    for (int kt = 0; kt < KT; kt++) {
        if (kt + 2 < KT) {
            const int k0 = (kt + 2) << 6;
            const uint32_t ao = smem_base + sl * H3_STAGE;
            const uint32_t bo = ao + 128 * 144;
            #pragma unroll
            for (int i = 0; i < 4; i++) {
                int idx = tid + i * 256;
                int r = idx >> 3, c16 = idx & 7;
                cp_async16s(ao + r * 144 + c16 * 16, A + (long long)(m0 + r) * K + k0 + c16 * 8);
                int gn = n0 + r; if (gn >= N) gn = N - 1;
                cp_async16s(bo + r * 144 + c16 * 16, Bw + (long long)gn * K + k0 + c16 * 8);
            }
            asm volatile("cp.async.commit_group;");
            asm volatile("cp.async.wait_group 2;");
        } else if (kt + 1 < KT) {
            asm volatile("cp.async.wait_group 1;");
        } else {
            asm volatile("cp.async.wait_group 0;");
        }
        __syncthreads();

        const uint32_t ab = smem_base + st * H3_STAGE;
        const uint32_t bb = ab + 128 * 144;
        #pragma unroll
        for (int kw = 0; kw < 32; kw += 8) {
            uint32_t af[4][4], bf[4][2];
            #pragma unroll
            for (int mt = 0; mt < 4; mt++)
                ldsm4(af[mt][0], af[mt][1], af[mt][2], af[mt][3],
                      ab + (wm + mt * 16) * 144 + kw * 4 + a_lane);
            #pragma unroll
            for (int ntp = 0; ntp < 2; ntp++)
                ldsm4(bf[2*ntp][0], bf[2*ntp][1], bf[2*ntp+1][0], bf[2*ntp+1][1],
                      bb + (wn + ntp * 16) * 144 + kw * 4 + b_lane);
            #pragma unroll
            for (int mt = 0; mt < 4; mt++)
                #pragma unroll
                for (int nt = 0; nt < 4; nt++)
                    mma_f16(acc[mt][nt], af[mt], bf[nt]);
        }
        __syncthreads();
        st = (st + 1 == 3) ? 0 : st + 1;
        sl = (sl + 1 == 3) ? 0 : sl + 1;
    }

    #pragma unroll
    for (int mt = 0; mt < 4; mt++) {
        #pragma unroll
        for (int nt = 0; nt < 4; nt++) {
            int mmb = m0 + wm + mt * 16 + lr;
            int nn = n0 + wn + nt * 8 + lc * 2;
            #pragma unroll
            for (int half_ = 0; half_ < 2; half_++) {
                int mrow = mmb + half_ * 8;
                #pragma unroll
                for (int q = 0; q < 2; q++) {
                    int nc = nn + q;
                    if (nc >= N) continue;
                    float v = acc[mt][nt][half_ * 2 + q];
                    long long off = (long long)mrow * N + nc;
                    if (MODE == 1) C[off] = (CT)(v + R[off]);
                    else           C[off] = (CT)v;
                }
            }
        }
    }
}

// ---- fused MLP dual GEMM: act = half(tf32(silu(y@Wg^T) * (y@Wu^T))) ----
// 64x128 tile, 2-stage, 2 CTAs/SM. 8 warps as 2x4 (32 m-rows x 32 n-cols each).
#define DG_ASTAGE (64*144)                  // 9216
#define DG_BSTAGE (128*144)                 // 18432
#define DG_STAGE  (DG_ASTAGE + 2*DG_BSTAGE) // 46080
#define DGEMM_SMEM (2*DG_STAGE)             // 92160
__global__ void __launch_bounds__(256, 2) gemm_dual(
    const __half* __restrict__ A, const __half* __restrict__ Bg, const __half* __restrict__ Bu,
    __half* __restrict__ C, int M, int N, int K)
{
    extern __shared__ char smem[];
    const uint32_t smem_base = smem_to_u32(smem);

    const int m0 = blockIdx.y * 64, n0 = blockIdx.x * 128;
    const int tid = threadIdx.x;
    const int warp = tid >> 5, lane = tid & 31;
    const int wm = (warp >> 2) * 32;
    const int wn = (warp & 3) * 32;
    const int lr = lane >> 2;
    const int lc = lane & 3;
    const uint32_t lq = lane >> 3, l8 = lane & 7;
    const uint32_t a_lane = ((lq & 1) * 8 + l8) * 144 + (lq >> 1) * 16;
    const uint32_t b_lane = ((lq >> 1) * 8 + l8) * 144 + (lq & 1) * 16;

    float accg[2][4][4], accu[2][4][4];
    #pragma unroll
    for (int mt = 0; mt < 2; mt++)
        #pragma unroll
        for (int nt = 0; nt < 4; nt++)
            #pragma unroll
            for (int i = 0; i < 4; i++) { accg[mt][nt][i] = 0.f; accu[mt][nt][i] = 0.f; }

    const int KT = K >> 6;

    // prefetch chunk 0
    {
        const uint32_t ao = smem_base;
        const uint32_t bgo = ao + DG_ASTAGE;
        const uint32_t buo = bgo + DG_BSTAGE;
        #pragma unroll
        for (int i = 0; i < 2; i++) {
            int idx = tid + i * 256;
            int r = idx >> 3, c16 = idx & 7;
            cp_async16s(ao + r * 144 + c16 * 16, A + (long long)(m0 + r) * K + c16 * 8);
        }
        #pragma unroll
        for (int i = 0; i < 4; i++) {
            int idx = tid + i * 256;
            int r = idx >> 3, c16 = idx & 7;
            int gn = n0 + r; if (gn >= N) gn = N - 1;
            cp_async16s(bgo + r * 144 + c16 * 16, Bg + (long long)gn * K + c16 * 8);
            cp_async16s(buo + r * 144 + c16 * 16, Bu + (long long)gn * K + c16 * 8);
        }
        asm volatile("cp.async.commit_group;");
    }

    for (int kt = 0; kt < KT; kt++) {
        const int st = kt & 1;
        if (kt + 1 < KT) {
            const int k0 = (kt + 1) << 6;
            const uint32_t ao = smem_base + (st ^ 1) * DG_STAGE;
            const uint32_t bgo = ao + DG_ASTAGE;
            const uint32_t buo = bgo + DG_BSTAGE;
            #pragma unroll
            for (int i = 0; i < 2; i++) {
                int idx = tid + i * 256;
                int r = idx >> 3, c16 = idx & 7;
                cp_async16s(ao + r * 144 + c16 * 16, A + (long long)(m0 + r) * K + k0 + c16 * 8);
            }
            #pragma unroll
            for (int i = 0; i < 4; i++) {
                int idx = tid + i * 256;
                int r = idx >> 3, c16 = idx & 7;
                int gn = n0 + r; if (gn >= N) gn = N - 1;
                cp_async16s(bgo + r * 144 + c16 * 16, Bg + (long long)gn * K + k0 + c16 * 8);
                cp_async16s(buo + r * 144 + c16 * 16, Bu + (long long)gn * K + k0 + c16 * 8);
            }
            asm volatile("cp.async.commit_group;");
            asm volatile("cp.async.wait_group 1;");
        } else {
            asm volatile("cp.async.wait_group 0;");
        }
        __syncthreads();

        const uint32_t ab = smem_base + st * DG_STAGE;
        const uint32_t bgb = ab + DG_ASTAGE;
        const uint32_t bub = bgb + DG_BSTAGE;
        #pragma unroll
        for (int kw = 0; kw < 32; kw += 8) {
            uint32_t af[2][4], bfg[4][2], bfu[4][2];
            #pragma unroll
            for (int mt = 0; mt < 2; mt++)
                ldsm4(af[mt][0], af[mt][1], af[mt][2], af[mt][3],
                      ab + (wm + mt * 16) * 144 + kw * 4 + a_lane);
            #pragma unroll
            for (int ntp = 0; ntp < 2; ntp++) {
                ldsm4(bfg[2*ntp][0], bfg[2*ntp][1], bfg[2*ntp+1][0], bfg[2*ntp+1][1],
                      bgb + (wn + ntp * 16) * 144 + kw * 4 + b_lane);
                ldsm4(bfu[2*ntp][0], bfu[2*ntp][1], bfu[2*ntp+1][0], bfu[2*ntp+1][1],
                      bub + (wn + ntp * 16) * 144 + kw * 4 + b_lane);
            }
            #pragma unroll
            for (int mt = 0; mt < 2; mt++)
                #pragma unroll
                for (int nt = 0; nt < 4; nt++) {
                    mma_f16(accg[mt][nt], af[mt], bfg[nt]);
                    mma_f16(accu[mt][nt], af[mt], bfu[nt]);
                }
        }
        __syncthreads();
    }

    #pragma unroll
    for (int mt = 0; mt < 2; mt++) {
        #pragma unroll
        for (int nt = 0; nt < 4; nt++) {
            int mmb = m0 + wm + mt * 16 + lr;
            int nn = n0 + wn + nt * 8 + lc * 2;
            #pragma unroll
            for (int half_ = 0; half_ < 2; half_++) {
                int mrow = mmb + half_ * 8;
                #pragma unroll
                for (int q = 0; q < 2; q++) {
                    int nc = nn + q;
                    if (nc >= N) continue;
                    float gg = accg[mt][nt][half_ * 2 + q];
                    float uu = accu[mt][nt][half_ * 2 + q];
                    float sig = 1.f / (1.f + expf(-gg));
                    C[(long long)mrow * N + nc] = __float2half(tf32r(gg * sig * uu));
                }
            }
        }
    }
}

// ---- RoPE in place ----
__global__ void rope_q_kernel(const int* __restrict__ pos_ids) {
    int idx = blockIdx.x * 256 + threadIdx.x;
    if (idx >= TOK_ * H_) return;
    int tok = idx / H_;
    float* x = g_q + (long long)idx * DQ_ + DNOPE_;
    float pos = (float)pos_ids[tok];
    float xv[64];
    #pragma unroll
    for (int i = 0; i < 64; i++) xv[i] = x[i];
    #pragma unroll
    for (int j = 0; j < 32; j++) {
        float th = pos * g_invfreq[j];
        float c = cosf(th), sn = sinf(th);
        float x1 = xv[2*j], x2 = xv[2*j+1];
        x[j]      = x1 * c - x2 * sn;
        x[j + 32] = x2 * c + x1 * sn;
    }
}

__global__ void rope_k_kernel(const int* __restrict__ pos_ids) {
    int tok = blockIdx.x * 256 + threadIdx.x;
    if (tok >= TOK_) return;
    float* x = g_ckv + (long long)tok * (RANK_ + DROPE_) + RANK_;
    float pos = (float)pos_ids[tok];
    float xv[64];
    #pragma unroll
    for (int i = 0; i < 64; i++) xv[i] = x[i];
    #pragma unroll
    for (int j = 0; j < 32; j++) {
        float th = pos * g_invfreq[j];
        float c = cosf(th), sn = sinf(th);
        float x1 = xv[2*j], x2 = xv[2*j+1];
        x[j]      = x1 * c - x2 * sn;
        x[j + 32] = x2 * c + x1 * sn;
    }
}

// ---- pack Q/K to half [z][s][192] ----
__global__ void pack_q_h_kernel() {
    long long idx = (long long)blockIdx.x * 256 + threadIdx.x;
    const long long total = (long long)TOK_ * H_ * 48;
    if (idx >= total) return;
    int d4 = (int)(idx % 48);
    long long t2 = idx / 48;
    int h = (int)(t2 % H_);
    long long tok = t2 / H_;
    int b = (int)(tok / S_), s = (int)(tok % S_);
    float4 v = *(const float4*)(g_q + (tok * H_ + h) * DQ_ + d4 * 4);
    __half2 h0 = __floats2half2_rn(v.x, v.y);
    __half2 h1 = __floats2half2_rn(v.z, v.w);
    uint2 o; o.x = *(uint32_t*)&h0; o.y = *(uint32_t*)&h1;
    *(uint2*)(g_Qh + (((long long)(b * H_ + h)) * S_ + s) * DQ_ + d4 * 4) = o;
}

__global__ void pack_k_h_kernel() {
    long long idx = (long long)blockIdx.x * 256 + threadIdx.x;
    const long long total = (long long)TOK_ * H_ * 48;
    if (idx >= total) return;
    int d4 = (int)(idx % 48);
    long long t2 = idx / 48;
    int h = (int)(t2 % H_);
    long long tok = t2 / H_;
    int b = (int)(tok / S_), s = (int)(tok % S_);
    float4 v;
    if (d4 < 32) v = *(const float4*)(g_kv + (tok * H_ + h) * (DNOPE_ + DV_) + d4 * 4);
    else         v = *(const float4*)(g_ckv + tok * (RANK_ + DROPE_) + RANK_ + (d4 - 32) * 4);
    __half2 h0 = __floats2half2_rn(v.x, v.y);
    __half2 h1 = __floats2half2_rn(v.z, v.w);
    uint2 o; o.x = *(uint32_t*)&h0; o.y = *(uint32_t*)&h1;
    *(uint2*)(g_Kh + (((long long)(b * H_ + h)) * S_ + s) * DQ_ + d4 * 4) = o;
}

// ---- V transpose ----
__global__ void transpose_v_kernel() {
    __shared__ float t[32][33];
    int z = blockIdx.z;
    int d0 = blockIdx.y * 32, s0 = blockIdx.x * 32;
    int b = z >> 4, h = z & 15;
    int tx = threadIdx.x, ty0 = threadIdx.y;
    #pragma unroll
    for (int dy = 0; dy < 32; dy += 8) {
        int ty = ty0 + dy;
        t[ty][tx] = g_kv[(((long long)b * S_ + s0 + ty) * H_ + h) * (DNOPE_ + DV_) + DNOPE_ + d0 + tx];
    }
    __syncthreads();
    #pragma unroll
    for (int dy = 0; dy < 32; dy += 8) {
        int ty = ty0 + dy;
        g_Vt[((long long)z * DV_ + d0 + ty) * S_ + s0 + tx] = __float2half(t[tx][ty]);
    }
}

// ---- fp16 flash attention, half inputs via cp.async ----
#define FQS_OFF 0
#define FKS_OFF 25600
#define FVS_OFF 51200
#define FSS_OFF 69632
#define FPH_OFF 87040
#define FML_OFF 96256
#define FLASH_SMEM (FML_OFF + 768)

__global__ void __launch_bounds__(256) flash_h_kernel(__half* __restrict__ outfl)
{
    extern __shared__ char smem[];
    uint32_t* qw = (uint32_t*)(smem + FQS_OFF);
    uint32_t* kw = (uint32_t*)(smem + FKS_OFF);
    uint32_t* vw = (uint32_t*)(smem + FVS_OFF);
    float*    Ss = (float*)(smem + FSS_OFF);
    __half*   Ph = (__half*)(smem + FPH_OFF);
    uint32_t* pw = (uint32_t*)(smem + FPH_OFF);
    float*    m_s = (float*)(smem + FML_OFF);
    float*    l_s = m_s + 64;
    float*    a_s = l_s + 64;
    const uint32_t smem_base = smem_to_u32(smem);

    const int z = blockIdx.y;
    const int b = z >> 4, h = z & 15;
    const int qt = gridDim.x - 1 - blockIdx.x;
    const int q0 = qt * 64;
    const int tid = threadIdx.x;
    const int warp = tid >> 5, lane = tid & 31;
    const int lr = lane >> 2, lc = lane & 3;
    const int wm = (warp & 3) * 16;
    const int wn_qk = (warp >> 2) * 32;
    const int wn_pv = (warp >> 2) * 64;
    const float scale = 0.07216878364870323f;
    const __half* Qg = g_Qh + ((long long)z * S_ + q0) * DQ_;
    const __half* Kg = g_Kh + (long long)z * S_ * DQ_;
    const __half* Vg = g_Vt + (long long)z * DV_ * S_;

    for (int i = tid; i < 64 * 24; i += 256) {
        int r = i / 24, c = i % 24;
        cp_async16s(smem_base + FQS_OFF + r * 400 + c * 16,
                    Qg + (long long)r * DQ_ + c * 8);
    }
    asm volatile("cp.async.commit_group;");
    if (tid < 64) { m_s[tid] = -1e30f; l_s[tid] = 0.f; }

    float oacc[8][4];
    #pragma unroll
    for (int nt = 0; nt < 8; nt++)
        #pragma unroll
        for (int i = 0; i < 4; i++) oacc[nt][i] = 0.f;

    for (int t = 0; t <= qt; t++) {
        const int k0 = t * 64;
        __syncthreads();
        for (int i = tid; i < 64 * 24; i += 256) {
            int r = i / 24, c = i % 24;
            cp_async16s(smem_base + FKS_OFF + r * 400 + c * 16,
                        Kg + (long long)(k0 + r) * DQ_ + c * 8);
        }
        for (int i = tid; i < 128 * 8; i += 256) {
            int r = i >> 3, c16 = i & 7;
            cp_async16s(smem_base + FVS_OFF + r * 144 + c16 * 16,
                        Vg + (long long)r * S_ + k0 + c16 * 8);
        }
        asm volatile("cp.async.commit_group; cp.async.wait_group 0;" ::: "memory");
        __syncthreads();

        float sc[4][4];
        #pragma unroll
        for (int nt = 0; nt < 4; nt++)
            #pragma unroll
            for (int i = 0; i < 4; i++) sc[nt][i] = 0.f;
        #pragma unroll
        for (int kk = 0; kk < 96; kk += 8) {
            uint32_t af[4], bf[4][2];
            af[0] = qw[(wm + lr    ) * 100 + kk + lc];
            af[1] = qw[(wm + lr + 8) * 100 + kk + lc];
            af[2] = qw[(wm + lr    ) * 100 + kk + 4 + lc];
            af[3] = qw[(wm + lr + 8) * 100 + kk + 4 + lc];
            #pragma unroll
            for (int nt = 0; nt < 4; nt++) {
                int col = wn_qk + nt * 8 + lr;
                bf[nt][0] = kw[col * 100 + kk + lc];
                bf[nt][1] = kw[col * 100 + kk + 4 + lc];
            }
            #pragma unroll
            for (int nt = 0; nt < 4; nt++)
                mma_f16(sc[nt], af, bf[nt]);
        }
        #pragma unroll
        for (int nt = 0; nt < 4; nt++) {
            int c = wn_qk + nt * 8 + lc * 2;
            int r0 = wm + lr, r1 = wm + lr + 8;
            float v00 = sc[nt][0] * scale, v01 = sc[nt][1] * scale;
            float v10 = sc[nt][2] * scale, v11 = sc[nt][3] * scale;
            if (k0 + c     > q0 + r0) v00 = -1e30f;
            if (k0 + c + 1 > q0 + r0) v01 = -1e30f;
            if (k0 + c     > q0 + r1) v10 = -1e30f;
            if (k0 + c + 1 > q0 + r1) v11 = -1e30f;
            *(float2*)(Ss + r0 * 68 + c) = make_float2(v00, v01);
            *(float2*)(Ss + r1 * 68 + c) = make_float2(v10, v11);
        }
        __syncthreads();

        {
            int r = tid >> 2, p4 = tid & 3;
            int cb = p4 * 16;
            float mx = -1e30f;
            #pragma unroll
            for (int j = 0; j < 16; j++) mx = fmaxf(mx, Ss[r * 68 + cb + j]);
            mx = fmaxf(mx, __shfl_xor_sync(0xffffffffu, mx, 1));
            mx = fmaxf(mx, __shfl_xor_sync(0xffffffffu, mx, 2));
            float m_old = m_s[r];
            float m_new = fmaxf(m_old, mx);
            float alpha = __expf(m_old - m_new);
            float es = 0.f;
            #pragma unroll
            for (int j = 0; j < 16; j++) {
                float e = __expf(Ss[r * 68 + cb + j] - m_new);
                Ph[r * 72 + cb + j] = __float2half(e);
                es += e;
            }
            es += __shfl_xor_sync(0xffffffffu, es, 1);
            es += __shfl_xor_sync(0xffffffffu, es, 2);
            if (p4 == 0) {
                l_s[r] = l_s[r] * alpha + es;
                m_s[r] = m_new;
                a_s[r] = alpha;
            }
        }
        __syncthreads();

        {
            float a0 = a_s[wm + lr], a1 = a_s[wm + lr + 8];
            #pragma unroll
            for (int nt = 0; nt < 8; nt++) {
                oacc[nt][0] *= a0; oacc[nt][1] *= a0;
                oacc[nt][2] *= a1; oacc[nt][3] *= a1;
            }
            #pragma unroll
            for (int kk = 0; kk < 32; kk += 8) {
                uint32_t af[4], bf[8][2];
                af[0] = pw[(wm + lr    ) * 36 + kk + lc];
                af[1] = pw[(wm + lr + 8) * 36 + kk + lc];
                af[2] = pw[(wm + lr    ) * 36 + kk + 4 + lc];
                af[3] = pw[(wm + lr + 8) * 36 + kk + 4 + lc];
                #pragma unroll
                for (int nt = 0; nt < 8; nt++) {
                    int col = wn_pv + nt * 8 + lr;
                    bf[nt][0] = vw[col * 36 + kk + lc];
                    bf[nt][1] = vw[col * 36 + kk + 4 + lc];
                }
                #pragma unroll
                for (int nt = 0; nt < 8; nt++)
                    mma_f16(oacc[nt], af, bf[nt]);
            }
        }
    }
    __syncthreads();

    {
        float il0 = 1.f / l_s[wm + lr];
        float il1 = 1.f / l_s[wm + lr + 8];
        long long tok0 = (long long)b * S_ + q0 + wm + lr;
        long long tok1 = tok0 + 8;
        #pragma unroll
        for (int nt = 0; nt < 8; nt++) {
            int c = wn_pv + nt * 8 + lc * 2;
            __half2 o0 = __floats2half2_rn(tf32r(oacc[nt][0] * il0), tf32r(oacc[nt][1] * il0));
            __half2 o1 = __floats2half2_rn(tf32r(oacc[nt][2] * il1), tf32r(oacc[nt][3] * il1));
            *(__half2*)(outfl + tok0 * (H_*DV_) + h * DV_ + c) = o0;
            *(__half2*)(outfl + tok1 * (H_*DV_) + h * DV_ + c) = o1;
        }
    }
}

static inline dim3 g128(int M, int N) { return dim3((N + 127) / 128, M / 128, 1); }

extern "C" void kernel_launch(void* const* d_in, const int* in_sizes, int n_in,
                              void* d_out, int out_size)
{
    const float* hidden = (const float*)d_in[0];
    const int*   pos    = (const int*)  d_in[1];
    const float* Wq     = (const float*)d_in[2];
    const float* Wkva   = (const float*)d_in[3];
    const float* w_kvln = (const float*)d_in[4];
    const float* Wkvb   = (const float*)d_in[5];
    const float* Wo     = (const float*)d_in[6];
    const float* Wg     = (const float*)d_in[7];
    const float* Wu     = (const float*)d_in[8];
    const float* Wd     = (const float*)d_in[9];
    const float* w_ln1  = (const float*)d_in[10];
    const float* w_ln2  = (const float*)d_in[11];
    float* out = (float*)d_out;

    float *p_q, *p_ckv, *p_kv, *p_x2;
    __half *p_xln, *p_cln, *p_afl, *p_y, *p_a;
    __half *t_wq, *t_wkva, *t_wkvb, *t_wo, *t_wg, *t_wu, *t_wd;
    cudaGetSymbolAddress((void**)&p_xln, g_xln);
    cudaGetSymbolAddress((void**)&p_q,   g_q);
    cudaGetSymbolAddress((void**)&p_ckv, g_ckv);
    cudaGetSymbolAddress((void**)&p_cln, g_cln);
    cudaGetSymbolAddress((void**)&p_kv,  g_kv);
    cudaGetSymbolAddress((void**)&p_afl, g_attnfl);
    cudaGetSymbolAddress((void**)&p_x2,  g_x2);
    cudaGetSymbolAddress((void**)&p_y,   g_y);
    cudaGetSymbolAddress((void**)&p_a,   g_act);
    cudaGetSymbolAddress((void**)&t_wq,   g_tWq);
    cudaGetSymbolAddress((void**)&t_wkva, g_tWkva);
    cudaGetSymbolAddress((void**)&t_wkvb, g_tWkvb);
    cudaGetSymbolAddress((void**)&t_wo,   g_tWo);
    cudaGetSymbolAddress((void**)&t_wg,   g_tWg);
    cudaGetSymbolAddress((void**)&t_wu,   g_tWu);
    cudaGetSymbolAddress((void**)&t_wd,   g_tWd);

    cudaFuncSetAttribute(gemm_h3<0,float>,  cudaFuncAttributeMaxDynamicSharedMemorySize, H3GEMM_SMEM);
    cudaFuncSetAttribute(gemm_h3<1,float>,  cudaFuncAttributeMaxDynamicSharedMemorySize, H3GEMM_SMEM);
    cudaFuncSetAttribute(gemm_dual,         cudaFuncAttributeMaxDynamicSharedMemorySize, DGEMM_SMEM);
    cudaFuncSetAttribute(flash_h_kernel,    cudaFuncAttributeMaxDynamicSharedMemorySize, FLASH_SMEM);

    init_invfreq2_kernel<<<1, 32>>>();
    trunc_kernel<<<1184, 256>>>(Wq,   t_wq,   (long long)H_*DQ_*HID_/4);
    trunc_kernel<<<1184, 256>>>(Wkva, t_wkva, (long long)(RANK_+DROPE_)*HID_/4);
    trunc_kernel<<<1184, 256>>>(Wkvb, t_wkvb, (long long)H_*(DNOPE_+DV_)*RANK_/4);
    rmsnorm_h_kernel<<<TOK_, 256>>>(hidden, w_ln1, p_xln, HID_, HID_);
    gemm_h3<0,float><<<g128(TOK_, H_*DQ_), 256, H3GEMM_SMEM>>>(p_xln, t_wq, p_q, nullptr,
        TOK_, H_*DQ_, HID_);
    gemm_h3<0,float><<<g128(TOK_, RANK_+DROPE_), 256, H3GEMM_SMEM>>>(p_xln, t_wkva, p_ckv, nullptr,
        TOK_, RANK_+DROPE_, HID_);

    rmsnorm_h_kernel<<<TOK_, 256>>>(p_ckv, w_kvln, p_cln, RANK_, RANK_+DROPE_);

    gemm_h3<0,float><<<g128(TOK_, H_*(DNOPE_+DV_)), 256, H3GEMM_SMEM>>>(p_cln, t_wkvb, p_kv, nullptr,
        TOK_, H_*(DNOPE_+DV_), RANK_);

    rope_q_kernel<<<(TOK_*H_ + 255)/256, 256>>>(pos);
    rope_k_kernel<<<(TOK_ + 255)/256, 256>>>(pos);
    {
        long long tp = (long long)TOK_ * H_ * 48;
        pack_q_h_kernel<<<(unsigned)((tp + 255)/256), 256>>>();
        pack_k_h_kernel<<<(unsigned)((tp + 255)/256), 256>>>();
    }
    transpose_v_kernel<<<dim3(S_/32, DV_/32, B_*H_), dim3(32, 8)>>>();

    flash_h_kernel<<<dim3(S_/64, B_*H_), 256, FLASH_SMEM>>>(p_afl);

    trunc_kernel<<<1184, 256>>>(Wo, t_wo, (long long)HID_*H_*DV_/4);
    gemm_h3<1,float><<<g128(TOK_, HID_), 256, H3GEMM_SMEM>>>(p_afl, t_wo, p_x2, hidden, TOK_, HID_, H_*DV_);

    rmsnorm_h_kernel<<<TOK_, 256>>>(p_x2, w_ln2, p_y, HID_, HID_);

    trunc_kernel<<<1184, 256>>>(Wg, t_wg, (long long)INTER_*HID_/4);
    trunc_kernel<<<1184, 256>>>(Wu, t_wu, (long long)INTER_*HID_/4);
    gemm_dual<<<dim3((INTER_ + 127)/128, TOK_/64), 256, DGEMM_SMEM>>>(p_y, t_wg, t_wu, p_a,
        TOK_, INTER_, HID_);

    trunc_kernel<<<1184, 256>>>(Wd, t_wd, (long long)HID_*INTER_/4);
    gemm_h3<1,float><<<g128(TOK_, HID_), 256, H3GEMM_SMEM>>>(p_a, t_wd, out, p_x2, TOK_, HID_, INTER_);
}